// round 9
// baseline (speedup 1.0000x reference)
#include <cuda_runtime.h>
#include <cuda_bf16.h>
#include <mma.h>
#include <cstdint>

using namespace nvcuda;
typedef __nv_bfloat16  bf16;
typedef __nv_bfloat162 bf162;

// Problem constants
#define Bsz 16384
#define Dd  1024
#define Lc  6
#define NMC 64
#define Hh  16
#define M1  (1024 * 1024)
#define BD  ((size_t)Bsz * Dd)

// Tiling: block 128x128 (generic) / 128x64 (fused), 8 warps, occ 2, 2-stage
#define BK   32
#define LDK  40
#define MATB (128 * LDK * 2)
#define GSTGB (4 * MATB)                        // 40960 B/stage
#define FSTGB (2 * MATB + 4 * (64 * LDK * 2))   // 40960 B/stage
#define GDSM (2 * GSTGB)
#define FDSM (2 * FSTGB)
#define NKT  (Dd / BK)

// ---------------------------------------------------------------------------
// Persistent buffers
// ---------------------------------------------------------------------------
__device__ bf16 g_wc_h [6 * M1], g_wc_l [6 * M1];   // combo weights, [n][k]
__device__ bf16 g_wv_h [6 * M1], g_wv_l [6 * M1];
__device__ bf16 g_wo_h [6 * M1], g_wo_l [6 * M1];
__device__ bf16 g_fb_h [5 * M1], g_fb_l [5 * M1];
__device__ bf16 g_we_h [6 * M1], g_we_l [6 * M1];   // gathered [n=m*16+h][k=d]
__device__ bf16 g_wi_h [6 * M1], g_wi_l [6 * M1];
__device__ bf16 g_s1h[6 * M1], g_s1l[6 * M1];
__device__ bf16 g_s2h[6 * M1], g_s2l[6 * M1];
__device__ float g_t2[6 * M1];
__device__ float g_bc1[6 * Dd], g_bc2[6 * Dd];
__device__ float g_zero[Dd];
__device__ bf16 g_a0h[BD], g_a0l[BD], g_a1h[BD], g_a1l[BD];

__device__ __forceinline__ void split1(float v, bf16* h, bf16* l) {
    bf16 hh = __float2bfloat16(v);
    *h = hh;
    *l = __float2bfloat16(v - __bfloat162float(hh));
}

__device__ __forceinline__ void cp16(void* smem, const void* g) {
    uint32_t s = (uint32_t)__cvta_generic_to_shared(smem);
    asm volatile("cp.async.cg.shared.global [%0], [%1], 16;" :: "r"(s), "l"(g));
}
__device__ __forceinline__ void cp_commit() { asm volatile("cp.async.commit_group;"); }
template <int N>
__device__ __forceinline__ void cp_wait() {
    asm volatile("cp.async.wait_group %0;" :: "n"(N));
}

// ---------------------------------------------------------------------------
// Conversion kernels (merged to minimize launch count before first GEMM)
// ---------------------------------------------------------------------------
__device__ __forceinline__ void convT_body(const float* S, bf16* H, bf16* L,
                                           int k0, int n0, int tid) {
    __shared__ float t[32][33];
    const int r = tid >> 5, c = tid & 31;
    #pragma unroll
    for (int i = 0; i < 4; i++)
        t[r + i * 8][c] = S[(size_t)(k0 + r + i * 8) * Dd + n0 + c];
    __syncthreads();
    #pragma unroll
    for (int i = 0; i < 4; i++) {
        bf16 hb, lb; split1(t[c][r + i * 8], &hb, &lb);
        size_t o = (size_t)(n0 + r + i * 8) * Dd + k0 + c;
        H[o] = hb; L[o] = lb;
    }
}

// All three [k][n]->[n][k] weight families in one launch (z: 0-5 Wv, 6-11 Wo, 12-16 fbW)
__global__ void convT_all(const float* __restrict__ Wv, const float* __restrict__ Wo,
                          const float* __restrict__ fbW,
                          bf16* __restrict__ wvh, bf16* __restrict__ wvl,
                          bf16* __restrict__ woh, bf16* __restrict__ wol,
                          bf16* __restrict__ fbh, bf16* __restrict__ fbl) {
    const int z = blockIdx.z;
    const float* S; bf16 *H, *L;
    if (z < 6)       { S = Wv  + (size_t)z * M1;        H = wvh + (size_t)z * M1;        L = wvl + (size_t)z * M1; }
    else if (z < 12) { S = Wo  + (size_t)(z - 6) * M1;  H = woh + (size_t)(z - 6) * M1;  L = wol + (size_t)(z - 6) * M1; }
    else             { S = fbW + (size_t)(z - 12) * M1; H = fbh + (size_t)(z - 12) * M1; L = fbl + (size_t)(z - 12) * M1; }
    convT_body(S, H, L, blockIdx.y * 32, blockIdx.x * 32, threadIdx.x);
}

// Plain conv_T (used for the combo weight t2 only)
__global__ void conv_T(const float* __restrict__ src, bf16* __restrict__ hi,
                       bf16* __restrict__ lo) {
    const int l = blockIdx.z;
    convT_body(src + (size_t)l * M1, hi + (size_t)l * M1, lo + (size_t)l * M1,
               blockIdx.y * 32, blockIdx.x * 32, threadIdx.x);
}

// Gather+transpose We/Wi in one launch (z: 0-5 We, 6-11 Wi)
__global__ void convgT_all(const float* __restrict__ We, const float* __restrict__ Wi,
                           bf16* __restrict__ weh, bf16* __restrict__ wel,
                           bf16* __restrict__ wih, bf16* __restrict__ wil) {
    __shared__ float t[64][17];
    const int z = blockIdx.z;
    const int l = (z < 6) ? z : z - 6;
    const float* src = (z < 6) ? We : Wi;
    bf16* hi = (z < 6) ? weh : wih;
    bf16* lo = (z < 6) ? wel : wil;
    const int d0 = blockIdx.x * 64, m = blockIdx.y;
    const int tid = threadIdx.x;
    {
        int dd = tid >> 2, h4 = (tid & 3) * 4;
        float4 v = *reinterpret_cast<const float4*>(
            &src[((size_t)(l * NMC + m) * Dd + d0 + dd) * Hh + h4]);
        t[dd][h4] = v.x; t[dd][h4 + 1] = v.y; t[dd][h4 + 2] = v.z; t[dd][h4 + 3] = v.w;
    }
    __syncthreads();
    int h = tid >> 4, cq = tid & 15;
    size_t rowo = (size_t)l * M1 + (size_t)(m * 16 + h) * Dd + d0 + cq * 4;
    #pragma unroll
    for (int j = 0; j < 4; j++) {
        bf16 hb, lb; split1(t[cq * 4 + j][h], &hb, &lb);
        hi[rowo + j] = hb; lo[rowo + j] = lb;
    }
}

// Wlat (row-major split) + x (activations) in one launch
__global__ void convact_all(const float* __restrict__ Wlat, const float* __restrict__ x,
                            bf16* __restrict__ s1h, bf16* __restrict__ s1l,
                            bf16* __restrict__ a1h, bf16* __restrict__ a1l) {
    size_t idx = (size_t)blockIdx.x * blockDim.x + threadIdx.x;   // float4 index
    const size_t n1 = (size_t)6 * M1 / 4;
    const float* src; bf16 *hi, *lo; size_t i;
    if (idx < n1) { src = Wlat; hi = s1h; lo = s1l; i = idx * 4; }
    else          { src = x;    hi = a1h; lo = a1l; i = (idx - n1) * 4; }
    float4 v = *reinterpret_cast<const float4*>(src + i);
    bf16 hs[4], ls[4];
    split1(v.x, &hs[0], &ls[0]); split1(v.y, &hs[1], &ls[1]);
    split1(v.z, &hs[2], &ls[2]); split1(v.w, &hs[3], &ls[3]);
    *reinterpret_cast<float2*>(hi + i) = *reinterpret_cast<float2*>(hs);
    *reinterpret_cast<float2*>(lo + i) = *reinterpret_cast<float2*>(ls);
}

// bc[l][j] = sum_i bin[l][i] * W[l][i][j] + badd[l][j]
__global__ void bias_combo(const float* __restrict__ bin, const float* __restrict__ W,
                           const float* __restrict__ badd, float* __restrict__ bc) {
    const int l = blockIdx.y;
    const int j = blockIdx.x * 256 + threadIdx.x;
    const float* Wl = W + (size_t)l * M1;
    const float* bi = bin + (size_t)l * Dd;
    float s = badd[(size_t)l * Dd + j];
    for (int i = 0; i < Dd; i++) s += bi[i] * Wl[(size_t)i * Dd + j];
    bc[(size_t)l * Dd + j] = s;
}

// ---------------------------------------------------------------------------
// GEMM: C = (ACC ? Cf : 0) + A @ W + bias. Block 128x128, 8 warps, warp 32x64,
// occ 2 (16 warps/SM). Single-barrier double-buffered cp.async mainloop.
// ---------------------------------------------------------------------------
template <bool ACC, bool WF32, bool WSPLIT>
__global__ __launch_bounds__(256, 2)
void gemm_w(const bf16* __restrict__ Ahi_, const bf16* __restrict__ Alo_,
            const bf16* __restrict__ Whi_, const bf16* __restrict__ Wlo_,
            const float* __restrict__ bias_, float* __restrict__ Cf_,
            bf16* __restrict__ Chi_, bf16* __restrict__ Clo_,
            size_t sA, size_t sW, size_t sB, size_t sC) {
    extern __shared__ char smraw[];
    const int z = blockIdx.z;
    const bf16* Ahi = Ahi_ + (size_t)z * sA;
    const bf16* Alo = Alo_ + (size_t)z * sA;
    const bf16* Whi = Whi_ + (size_t)z * sW;
    const bf16* Wlo = Wlo_ + (size_t)z * sW;
    const float* bias = bias_ + (size_t)z * sB;
    float* Cf = WF32 ? Cf_ + (size_t)z * sC : nullptr;
    bf16* Chi = WSPLIT ? Chi_ + (size_t)z * sC : nullptr;
    bf16* Clo = WSPLIT ? Clo_ + (size_t)z * sC : nullptr;

    const int tid = threadIdx.x, wid = tid >> 5, lane = tid & 31;
    const int wm = wid >> 1;    // 0..3 : 32-row band
    const int wn = wid & 1;     // 0..1 : 64-col band
    const int m0 = blockIdx.y * 128, n0 = blockIdx.x * 128;

    wmma::fragment<wmma::accumulator, 16, 16, 16, float> acc[2][4];
    #pragma unroll
    for (int i = 0; i < 2; i++)
        #pragma unroll
        for (int j = 0; j < 4; j++)
            wmma::fill_fragment(acc[i][j], 0.0f);

    auto load_stage = [&](int st, int kt) {
        bf16* Ah = reinterpret_cast<bf16*>(smraw + st * GSTGB);
        bf16* Al = Ah + 128 * LDK;
        bf16* Bh = Al + 128 * LDK;
        bf16* Bl = Bh + 128 * LDK;
        const int k0 = kt * BK;
        #pragma unroll
        for (int t = 0; t < 2; t++) {
            int item = tid + t * 256;
            int r = item >> 2, c = (item & 3) * 8;
            size_t ga = (size_t)(m0 + r) * Dd + k0 + c;
            size_t gb = (size_t)(n0 + r) * Dd + k0 + c;
            cp16(Ah + r * LDK + c, Ahi + ga);
            cp16(Al + r * LDK + c, Alo + ga);
            cp16(Bh + r * LDK + c, Whi + gb);
            cp16(Bl + r * LDK + c, Wlo + gb);
        }
        cp_commit();
    };

    load_stage(0, 0);
    for (int kt = 0; kt < NKT; kt++) {
        const int st = kt & 1;
        cp_wait<0>();
        __syncthreads();
        if (kt + 1 < NKT) load_stage(st ^ 1, kt + 1);

        bf16* Ah = reinterpret_cast<bf16*>(smraw + st * GSTGB);
        bf16* Al = Ah + 128 * LDK;
        bf16* Bh = Al + 128 * LDK;
        bf16* Bl = Bh + 128 * LDK;
        #pragma unroll
        for (int ks = 0; ks < BK; ks += 16) {
            wmma::fragment<wmma::matrix_b, 16, 16, 16, bf16, wmma::col_major> bh[4], bl[4];
            #pragma unroll
            for (int j = 0; j < 4; j++) {
                wmma::load_matrix_sync(bh[j], &Bh[(wn * 64 + j * 16) * LDK + ks], LDK);
                wmma::load_matrix_sync(bl[j], &Bl[(wn * 64 + j * 16) * LDK + ks], LDK);
            }
            #pragma unroll
            for (int i = 0; i < 2; i++) {
                wmma::fragment<wmma::matrix_a, 16, 16, 16, bf16, wmma::row_major> ah, al;
                wmma::load_matrix_sync(ah, &Ah[(wm * 32 + i * 16) * LDK + ks], LDK);
                wmma::load_matrix_sync(al, &Al[(wm * 32 + i * 16) * LDK + ks], LDK);
                #pragma unroll
                for (int j = 0; j < 4; j++) {
                    wmma::mma_sync(acc[i][j], ah, bh[j], acc[i][j]);
                    wmma::mma_sync(acc[i][j], ah, bl[j], acc[i][j]);
                    wmma::mma_sync(acc[i][j], al, bh[j], acc[i][j]);
                }
            }
        }
    }

    __syncthreads();
    float* patch = reinterpret_cast<float*>(smraw) + wid * 16 * 20;
    const int er = lane >> 1, eh = (lane & 1) * 8;
    #pragma unroll
    for (int i = 0; i < 2; i++) {
        #pragma unroll
        for (int j = 0; j < 4; j++) {
            wmma::store_matrix_sync(patch, acc[i][j], 20, wmma::mem_row_major);
            __syncwarp();
            int gr = m0 + wm * 32 + i * 16 + er;
            int gc = n0 + wn * 64 + j * 16 + eh;
            size_t go = (size_t)gr * Dd + gc;
            float4 b0 = *reinterpret_cast<const float4*>(&bias[gc]);
            float4 b1 = *reinterpret_cast<const float4*>(&bias[gc + 4]);
            float v[8];
            #pragma unroll
            for (int e = 0; e < 8; e++) v[e] = patch[er * 20 + eh + e];
            v[0] += b0.x; v[1] += b0.y; v[2] += b0.z; v[3] += b0.w;
            v[4] += b1.x; v[5] += b1.y; v[6] += b1.z; v[7] += b1.w;
            if (ACC) {
                float4 o0 = *reinterpret_cast<const float4*>(&Cf[go]);
                float4 o1 = *reinterpret_cast<const float4*>(&Cf[go + 4]);
                v[0] += o0.x; v[1] += o0.y; v[2] += o0.z; v[3] += o0.w;
                v[4] += o1.x; v[5] += o1.y; v[6] += o1.z; v[7] += o1.w;
            }
            if (WF32) {
                *reinterpret_cast<float4*>(&Cf[go])     = *reinterpret_cast<float4*>(&v[0]);
                *reinterpret_cast<float4*>(&Cf[go + 4]) = *reinterpret_cast<float4*>(&v[4]);
            }
            if (WSPLIT) {
                bf16 hs[8], ls[8];
                #pragma unroll
                for (int e = 0; e < 8; e++) split1(v[e], &hs[e], &ls[e]);
                *reinterpret_cast<float4*>(&Chi[go]) = *reinterpret_cast<float4*>(hs);
                *reinterpret_cast<float4*>(&Clo[go]) = *reinterpret_cast<float4*>(ls);
            }
            __syncwarp();
        }
    }
}

// ---------------------------------------------------------------------------
// Fused minicolumn kernel: block 128x64, 8 warps, warp 32x32 (e and i), occ 2.
// ---------------------------------------------------------------------------
__global__ __launch_bounds__(256, 2)
void fused_w(const bf16* __restrict__ Ahi, const bf16* __restrict__ Alo,
             const bf16* __restrict__ Weh, const bf16* __restrict__ Wel,
             const bf16* __restrict__ Wih, const bf16* __restrict__ Wil,
             const float* __restrict__ be_l, const float* __restrict__ bi_l,
             const float* __restrict__ Wl_l, const float* __restrict__ bl_l,
             bf16* __restrict__ Mhi, bf16* __restrict__ Mlo) {
    extern __shared__ char smraw[];
    __shared__ float swl[1024];
    __shared__ float sbe[64], sbi[64], sbl[64];

    const int tid = threadIdx.x, wid = tid >> 5, lane = tid & 31;
    const int wm = wid >> 1;    // 0..3 : 32-row band
    const int wn = wid & 1;     // 0..1 : 32-col band
    const int m0 = blockIdx.y * 128, n0 = blockIdx.x * 64;

    if (tid < 256)
        *reinterpret_cast<float4*>(&swl[tid * 4]) =
            *reinterpret_cast<const float4*>(&Wl_l[(size_t)n0 * Hh + tid * 4]);
    if (tid < 64) {
        sbe[tid] = be_l[n0 + tid];
        sbi[tid] = bi_l[n0 + tid];
        sbl[tid] = bl_l[n0 + tid];
    }

    wmma::fragment<wmma::accumulator, 16, 16, 16, float> ae[2][2], ai[2][2];
    #pragma unroll
    for (int i = 0; i < 2; i++)
        #pragma unroll
        for (int j = 0; j < 2; j++) {
            wmma::fill_fragment(ae[i][j], 0.0f);
            wmma::fill_fragment(ai[i][j], 0.0f);
        }

    auto load_stage = [&](int st, int kt) {
        bf16* Ah = reinterpret_cast<bf16*>(smraw + st * FSTGB);
        bf16* Al = Ah + 128 * LDK;
        bf16* Eh = Al + 128 * LDK;
        bf16* El = Eh + 64 * LDK;
        bf16* Ih = El + 64 * LDK;
        bf16* Il = Ih + 64 * LDK;
        const int k0 = kt * BK;
        #pragma unroll
        for (int t = 0; t < 2; t++) {
            int item = tid + t * 256;
            int r = item >> 2, c = (item & 3) * 8;
            size_t ga = (size_t)(m0 + r) * Dd + k0 + c;
            cp16(Ah + r * LDK + c, Ahi + ga);
            cp16(Al + r * LDK + c, Alo + ga);
        }
        {
            int r = tid >> 2, c = (tid & 3) * 8;
            if (r < 64) {
                size_t gb = (size_t)(n0 + r) * Dd + k0 + c;
                cp16(Eh + r * LDK + c, Weh + gb);
                cp16(El + r * LDK + c, Wel + gb);
                cp16(Ih + r * LDK + c, Wih + gb);
                cp16(Il + r * LDK + c, Wil + gb);
            }
        }
        cp_commit();
    };

    load_stage(0, 0);
    for (int kt = 0; kt < NKT; kt++) {
        const int st = kt & 1;
        cp_wait<0>();
        __syncthreads();
        if (kt + 1 < NKT) load_stage(st ^ 1, kt + 1);

        bf16* Ah = reinterpret_cast<bf16*>(smraw + st * FSTGB);
        bf16* Al = Ah + 128 * LDK;
        bf16* Eh = Al + 128 * LDK;
        bf16* El = Eh + 64 * LDK;
        bf16* Ih = El + 64 * LDK;
        bf16* Il = Ih + 64 * LDK;
        #pragma unroll
        for (int ks = 0; ks < BK; ks += 16) {
            wmma::fragment<wmma::matrix_b, 16, 16, 16, bf16, wmma::col_major>
                eh[2], el[2], ih[2], il[2];
            #pragma unroll
            for (int j = 0; j < 2; j++) {
                int nb = (wn * 32 + j * 16) * LDK + ks;
                wmma::load_matrix_sync(eh[j], &Eh[nb], LDK);
                wmma::load_matrix_sync(el[j], &El[nb], LDK);
                wmma::load_matrix_sync(ih[j], &Ih[nb], LDK);
                wmma::load_matrix_sync(il[j], &Il[nb], LDK);
            }
            #pragma unroll
            for (int i = 0; i < 2; i++) {
                wmma::fragment<wmma::matrix_a, 16, 16, 16, bf16, wmma::row_major> ah, al;
                wmma::load_matrix_sync(ah, &Ah[(wm * 32 + i * 16) * LDK + ks], LDK);
                wmma::load_matrix_sync(al, &Al[(wm * 32 + i * 16) * LDK + ks], LDK);
                #pragma unroll
                for (int j = 0; j < 2; j++) {
                    wmma::mma_sync(ae[i][j], ah, eh[j], ae[i][j]);
                    wmma::mma_sync(ae[i][j], ah, el[j], ae[i][j]);
                    wmma::mma_sync(ae[i][j], al, eh[j], ae[i][j]);
                    wmma::mma_sync(ai[i][j], ah, ih[j], ai[i][j]);
                    wmma::mma_sync(ai[i][j], ah, il[j], ai[i][j]);
                    wmma::mma_sync(ai[i][j], al, ih[j], ai[i][j]);
                }
            }
        }
    }

    __syncthreads();
    float* pe = reinterpret_cast<float*>(smraw) + wid * 2 * 16 * 20;
    float* pi = pe + 16 * 20;
    const int er = lane >> 1, eh8 = (lane & 1) * 8;
    #pragma unroll
    for (int i = 0; i < 2; i++) {
        #pragma unroll
        for (int j = 0; j < 2; j++) {
            wmma::store_matrix_sync(pe, ae[i][j], 20, wmma::mem_row_major);
            wmma::store_matrix_sync(pi, ai[i][j], 20, wmma::mem_row_major);
            __syncwarp();
            int ml = wn * 2 + j;
            int gr = m0 + wm * 32 + i * 16 + er;
            float ihv[16];
            #pragma unroll
            for (int h = 0; h < 16; h++)
                ihv[h] = fmaxf(pi[er * 20 + h] + sbi[ml * 16 + h], 0.0f);
            bf16 hs[8], ls[8];
            #pragma unroll
            for (int e = 0; e < 8; e++) {
                int k = eh8 + e;
                float lat = sbl[ml * 16 + k];
                #pragma unroll
                for (int h = 0; h < 16; h++)
                    lat += ihv[h] * swl[ml * 256 + h * 16 + k];
                float ex = fmaxf(pe[er * 20 + k] + sbe[ml * 16 + k], 0.0f);
                split1(fmaxf(ex - lat, 0.0f), &hs[e], &ls[e]);
            }
            size_t go = (size_t)gr * Dd + n0 + ml * 16 + eh8;
            *reinterpret_cast<float4*>(&Mhi[go]) = *reinterpret_cast<float4*>(hs);
            *reinterpret_cast<float4*>(&Mlo[go]) = *reinterpret_cast<float4*>(ls);
            __syncwarp();
        }
    }
}

// ---------------------------------------------------------------------------
// Host orchestration
// ---------------------------------------------------------------------------
extern "C" void kernel_launch(void* const* d_in, const int* in_sizes, int n_in,
                              void* d_out, int out_size) {
    const float* x    = (const float*)d_in[0];
    const float* We   = (const float*)d_in[1];
    const float* be   = (const float*)d_in[2];
    const float* Wi   = (const float*)d_in[3];
    const float* bi   = (const float*)d_in[4];
    const float* Wl   = (const float*)d_in[5];
    const float* bl   = (const float*)d_in[6];
    const float* Wlat = (const float*)d_in[7];
    const float* blat = (const float*)d_in[8];
    const float* Wv   = (const float*)d_in[9];
    const float* bv   = (const float*)d_in[10];
    const float* Wo   = (const float*)d_in[11];
    const float* bo   = (const float*)d_in[12];
    const float* fbW  = (const float*)d_in[13];
    const float* fbb  = (const float*)d_in[14];
    float* out = (float*)d_out;

    bf16 *wc_h, *wc_l, *wv_h, *wv_l, *wo_h, *wo_l, *fb_h, *fb_l;
    bf16 *we_h, *we_l, *wi_h, *wi_l, *a0h, *a0l, *a1h, *a1l;
    bf16 *s1h, *s1l, *s2h, *s2l;
    float *t2, *bc1, *bc2, *zero;
    cudaGetSymbolAddress((void**)&wc_h, g_wc_h);
    cudaGetSymbolAddress((void**)&wc_l, g_wc_l);
    cudaGetSymbolAddress((void**)&wv_h, g_wv_h);
    cudaGetSymbolAddress((void**)&wv_l, g_wv_l);
    cudaGetSymbolAddress((void**)&wo_h, g_wo_h);
    cudaGetSymbolAddress((void**)&wo_l, g_wo_l);
    cudaGetSymbolAddress((void**)&fb_h, g_fb_h);
    cudaGetSymbolAddress((void**)&fb_l, g_fb_l);
    cudaGetSymbolAddress((void**)&we_h, g_we_h);
    cudaGetSymbolAddress((void**)&we_l, g_we_l);
    cudaGetSymbolAddress((void**)&wi_h, g_wi_h);
    cudaGetSymbolAddress((void**)&wi_l, g_wi_l);
    cudaGetSymbolAddress((void**)&a0h,  g_a0h);
    cudaGetSymbolAddress((void**)&a0l,  g_a0l);
    cudaGetSymbolAddress((void**)&a1h,  g_a1h);
    cudaGetSymbolAddress((void**)&a1l,  g_a1l);
    cudaGetSymbolAddress((void**)&s1h,  g_s1h);
    cudaGetSymbolAddress((void**)&s1l,  g_s1l);
    cudaGetSymbolAddress((void**)&s2h,  g_s2h);
    cudaGetSymbolAddress((void**)&s2l,  g_s2l);
    cudaGetSymbolAddress((void**)&t2,   g_t2);
    cudaGetSymbolAddress((void**)&bc1,  g_bc1);
    cudaGetSymbolAddress((void**)&bc2,  g_bc2);
    cudaGetSymbolAddress((void**)&zero, g_zero);

    cudaFuncSetAttribute(gemm_w<false, false, true>, cudaFuncAttributeMaxDynamicSharedMemorySize, GDSM);
    cudaFuncSetAttribute(gemm_w<false, true, false>, cudaFuncAttributeMaxDynamicSharedMemorySize, GDSM);
    cudaFuncSetAttribute(gemm_w<false, true, true>,  cudaFuncAttributeMaxDynamicSharedMemorySize, GDSM);
    cudaFuncSetAttribute(gemm_w<true, true, true>,   cudaFuncAttributeMaxDynamicSharedMemorySize, GDSM);
    cudaFuncSetAttribute(fused_w,                    cudaFuncAttributeMaxDynamicSharedMemorySize, FDSM);

    // --- One-time conversions (3 launches) ---
    convT_all<<<dim3(32, 32, 17), 256>>>(Wv, Wo, fbW, wv_h, wv_l, wo_h, wo_l, fb_h, fb_l);
    convgT_all<<<dim3(16, 64, 12), 256>>>(We, Wi, we_h, we_l, wi_h, wi_l);
    convact_all<<<(int)(6 * M1 / 4 / 256 + BD / 4 / 256), 256>>>(Wlat, x, s1h, s1l, a1h, a1l);

    // --- Combined biases (independent of combo GEMMs; launched early so that
    //     ncu -s 5 captures a gemm_w mainloop launch) ---
    bias_combo<<<dim3(4, 6), 256>>>(blat, Wv, bv, bc1);
    bias_combo<<<dim3(4, 6), 256>>>(bc1, Wo, bo, bc2);

    // --- Combo precompute: W_combo = Wlat @ Wv @ Wo ---
    dim3 gridC(8, 8, 6);
    gemm_w<false, false, true><<<gridC, 256, GDSM>>>(s1h, s1l, wv_h, wv_l,
        zero, nullptr, s2h, s2l, M1, M1, 0, M1);               // launch #5 (ncu)
    gemm_w<false, true, false><<<gridC, 256, GDSM>>>(s2h, s2l, wo_h, wo_l,
        zero, t2, nullptr, nullptr, M1, M1, 0, M1);
    conv_T<<<dim3(32, 32, 6), 256>>>(t2, wc_h, wc_l);

    const size_t WL_STRIDE = (size_t)NMC * Hh * Hh;
    dim3 gridG(Dd / 128, Bsz / 128, 1);   // 8 x 128
    dim3 gridF(Dd / 64,  Bsz / 128);      // 16 x 128

    for (int l = 0; l < Lc; l++) {
        fused_w<<<gridF, 256, FDSM>>>(a1h, a1l,
            we_h + (size_t)l * M1, we_l + (size_t)l * M1,
            wi_h + (size_t)l * M1, wi_l + (size_t)l * M1,
            be + l * Dd, bi + l * Dd, Wl + l * WL_STRIDE, bl + l * Dd,
            a0h, a0l);
        gemm_w<false, true, true><<<gridG, 256, GDSM>>>(a0h, a0l,
            wc_h + (size_t)l * M1, wc_l + (size_t)l * M1,
            bc2 + (size_t)l * Dd, out + (size_t)l * BD, a1h, a1l,
            0, 0, 0, 0);
    }

    int p = 1;
    for (int i = 0; i < Lc - 1; i++) {
        int idx = Lc - 2 - i;
        bf16* sh = p ? a1h : a0h;
        bf16* sl = p ? a1l : a0l;
        bf16* dh = p ? a0h : a1h;
        bf16* dl = p ? a0l : a1l;
        gemm_w<true, true, true><<<gridG, 256, GDSM>>>(sh, sl,
            fb_h + (size_t)i * M1, fb_l + (size_t)i * M1,
            fbb + i * Dd, out + (size_t)idx * BD, dh, dl,
            0, 0, 0, 0);
        p ^= 1;
    }
}

// round 10
// speedup vs baseline: 1.0891x; 1.0891x over previous
#include <cuda_runtime.h>
#include <cuda_bf16.h>
#include <mma.h>
#include <cstdint>

using namespace nvcuda;
typedef __nv_bfloat16  bf16;
typedef __nv_bfloat162 bf162;

// Problem constants
#define Bsz 16384
#define Dd  1024
#define Lc  6
#define NMC 64
#define Hh  16
#define M1  (1024 * 1024)
#define BD  ((size_t)Bsz * Dd)

// Tiling: block 128x128 (generic) / 128x64 (fused), 4 warps, warp 64x64/64x32, occ 2
#define BK   32
#define LDK  40
#define MATB (128 * LDK * 2)
#define GSTGB (4 * MATB)                        // 40960 B/stage
#define FSTGB (2 * MATB + 4 * (64 * LDK * 2))   // 40960 B/stage
#define GDSM (2 * GSTGB)
#define FDSM (2 * FSTGB)
#define NKT  (Dd / BK)

// ---------------------------------------------------------------------------
// Persistent buffers
// ---------------------------------------------------------------------------
__device__ bf16 g_wc_h [6 * M1], g_wc_l [6 * M1];   // combo weights, [n][k]
__device__ bf16 g_wv_h [6 * M1], g_wv_l [6 * M1];
__device__ bf16 g_wo_h [6 * M1], g_wo_l [6 * M1];
__device__ bf16 g_fb_h [5 * M1], g_fb_l [5 * M1];
__device__ bf16 g_we_h [6 * M1], g_we_l [6 * M1];   // gathered [n=m*16+h][k=d]
__device__ bf16 g_wi_h [6 * M1], g_wi_l [6 * M1];
__device__ bf16 g_s1h[6 * M1], g_s1l[6 * M1];
__device__ bf16 g_s2h[6 * M1], g_s2l[6 * M1];
__device__ float g_t2[6 * M1];
__device__ float g_bc1[6 * Dd], g_bc2[6 * Dd];
__device__ float g_bcp[6 * 8 * Dd];                 // bias partials
__device__ float g_zero[Dd];
__device__ bf16 g_a0h[BD], g_a0l[BD], g_a1h[BD], g_a1l[BD];

__device__ __forceinline__ void split1(float v, bf16* h, bf16* l) {
    bf16 hh = __float2bfloat16(v);
    *h = hh;
    *l = __float2bfloat16(v - __bfloat162float(hh));
}

__device__ __forceinline__ void cp16(void* smem, const void* g) {
    uint32_t s = (uint32_t)__cvta_generic_to_shared(smem);
    asm volatile("cp.async.cg.shared.global [%0], [%1], 16;" :: "r"(s), "l"(g));
}
__device__ __forceinline__ void cp_commit() { asm volatile("cp.async.commit_group;"); }
template <int N>
__device__ __forceinline__ void cp_wait() {
    asm volatile("cp.async.wait_group %0;" :: "n"(N));
}

// ---------------------------------------------------------------------------
// Conversion kernels (merged; minimal launch count before first GEMM)
// ---------------------------------------------------------------------------
__device__ __forceinline__ void convT_body(const float* S, bf16* H, bf16* L,
                                           int k0, int n0, int tid) {
    __shared__ float t[32][33];
    const int r = tid >> 5, c = tid & 31;
    #pragma unroll
    for (int i = 0; i < 4; i++)
        t[r + i * 8][c] = S[(size_t)(k0 + r + i * 8) * Dd + n0 + c];
    __syncthreads();
    #pragma unroll
    for (int i = 0; i < 4; i++) {
        bf16 hb, lb; split1(t[c][r + i * 8], &hb, &lb);
        size_t o = (size_t)(n0 + r + i * 8) * Dd + k0 + c;
        H[o] = hb; L[o] = lb;
    }
}

__global__ void convT_all(const float* __restrict__ Wv, const float* __restrict__ Wo,
                          const float* __restrict__ fbW,
                          bf16* __restrict__ wvh, bf16* __restrict__ wvl,
                          bf16* __restrict__ woh, bf16* __restrict__ wol,
                          bf16* __restrict__ fbh, bf16* __restrict__ fbl) {
    const int z = blockIdx.z;
    const float* S; bf16 *H, *L;
    if (z < 6)       { S = Wv  + (size_t)z * M1;        H = wvh + (size_t)z * M1;        L = wvl + (size_t)z * M1; }
    else if (z < 12) { S = Wo  + (size_t)(z - 6) * M1;  H = woh + (size_t)(z - 6) * M1;  L = wol + (size_t)(z - 6) * M1; }
    else             { S = fbW + (size_t)(z - 12) * M1; H = fbh + (size_t)(z - 12) * M1; L = fbl + (size_t)(z - 12) * M1; }
    convT_body(S, H, L, blockIdx.y * 32, blockIdx.x * 32, threadIdx.x);
}

__global__ void conv_T(const float* __restrict__ src, bf16* __restrict__ hi,
                       bf16* __restrict__ lo) {
    const int l = blockIdx.z;
    convT_body(src + (size_t)l * M1, hi + (size_t)l * M1, lo + (size_t)l * M1,
               blockIdx.y * 32, blockIdx.x * 32, threadIdx.x);
}

__global__ void convgT_all(const float* __restrict__ We, const float* __restrict__ Wi,
                           bf16* __restrict__ weh, bf16* __restrict__ wel,
                           bf16* __restrict__ wih, bf16* __restrict__ wil) {
    __shared__ float t[64][17];
    const int z = blockIdx.z;
    const int l = (z < 6) ? z : z - 6;
    const float* src = (z < 6) ? We : Wi;
    bf16* hi = (z < 6) ? weh : wih;
    bf16* lo = (z < 6) ? wel : wil;
    const int d0 = blockIdx.x * 64, m = blockIdx.y;
    const int tid = threadIdx.x;
    {
        int dd = tid >> 2, h4 = (tid & 3) * 4;
        float4 v = *reinterpret_cast<const float4*>(
            &src[((size_t)(l * NMC + m) * Dd + d0 + dd) * Hh + h4]);
        t[dd][h4] = v.x; t[dd][h4 + 1] = v.y; t[dd][h4 + 2] = v.z; t[dd][h4 + 3] = v.w;
    }
    __syncthreads();
    int h = tid >> 4, cq = tid & 15;
    size_t rowo = (size_t)l * M1 + (size_t)(m * 16 + h) * Dd + d0 + cq * 4;
    #pragma unroll
    for (int j = 0; j < 4; j++) {
        bf16 hb, lb; split1(t[cq * 4 + j][h], &hb, &lb);
        hi[rowo + j] = hb; lo[rowo + j] = lb;
    }
}

__global__ void convact_all(const float* __restrict__ Wlat, const float* __restrict__ x,
                            bf16* __restrict__ s1h, bf16* __restrict__ s1l,
                            bf16* __restrict__ a1h, bf16* __restrict__ a1l) {
    size_t idx = (size_t)blockIdx.x * blockDim.x + threadIdx.x;   // float4 index
    const size_t n1 = (size_t)6 * M1 / 4;
    const float* src; bf16 *hi, *lo; size_t i;
    if (idx < n1) { src = Wlat; hi = s1h; lo = s1l; i = idx * 4; }
    else          { src = x;    hi = a1h; lo = a1l; i = (idx - n1) * 4; }
    float4 v = *reinterpret_cast<const float4*>(src + i);
    bf16 hs[4], ls[4];
    split1(v.x, &hs[0], &ls[0]); split1(v.y, &hs[1], &ls[1]);
    split1(v.z, &hs[2], &ls[2]); split1(v.w, &hs[3], &ls[3]);
    *reinterpret_cast<float2*>(hi + i) = *reinterpret_cast<float2*>(hs);
    *reinterpret_cast<float2*>(lo + i) = *reinterpret_cast<float2*>(ls);
}

// Bias combo, deterministic 2-phase: partials over 8 i-chunks, then reduce.
__global__ void bias_part(const float* __restrict__ bin, const float* __restrict__ W,
                          float* __restrict__ bcp) {
    const int l = blockIdx.z;
    const int i0 = blockIdx.y * 128;
    const int j = blockIdx.x * 256 + threadIdx.x;
    const float* Wl = W + (size_t)l * M1;
    const float* bi = bin + (size_t)l * Dd;
    float s = 0.0f;
    #pragma unroll 4
    for (int i = i0; i < i0 + 128; i++) s += bi[i] * Wl[(size_t)i * Dd + j];
    bcp[((size_t)l * 8 + blockIdx.y) * Dd + j] = s;
}
__global__ void bias_reduce(const float* __restrict__ bcp, const float* __restrict__ badd,
                            float* __restrict__ bc) {
    const int l = blockIdx.y;
    const int j = blockIdx.x * 256 + threadIdx.x;
    float s = badd[(size_t)l * Dd + j];
    #pragma unroll
    for (int c = 0; c < 8; c++) s += bcp[((size_t)l * 8 + c) * Dd + j];
    bc[(size_t)l * Dd + j] = s;
}

// ---------------------------------------------------------------------------
// GEMM: C = (ACC ? Cf : 0) + A @ W + bias. Block 128x128, 4 warps, warp 64x64,
// occ 2, 2-stage cp.async. Inner MMAs pass-reordered for ILP.
// ---------------------------------------------------------------------------
template <bool ACC, bool WF32, bool WSPLIT>
__global__ __launch_bounds__(128, 2)
void gemm_w(const bf16* __restrict__ Ahi_, const bf16* __restrict__ Alo_,
            const bf16* __restrict__ Whi_, const bf16* __restrict__ Wlo_,
            const float* __restrict__ bias_, float* __restrict__ Cf_,
            bf16* __restrict__ Chi_, bf16* __restrict__ Clo_,
            size_t sA, size_t sW, size_t sB, size_t sC) {
    extern __shared__ char smraw[];
    const int z = blockIdx.z;
    const bf16* Ahi = Ahi_ + (size_t)z * sA;
    const bf16* Alo = Alo_ + (size_t)z * sA;
    const bf16* Whi = Whi_ + (size_t)z * sW;
    const bf16* Wlo = Wlo_ + (size_t)z * sW;
    const float* bias = bias_ + (size_t)z * sB;
    float* Cf = WF32 ? Cf_ + (size_t)z * sC : nullptr;
    bf16* Chi = WSPLIT ? Chi_ + (size_t)z * sC : nullptr;
    bf16* Clo = WSPLIT ? Clo_ + (size_t)z * sC : nullptr;

    const int tid = threadIdx.x, wid = tid >> 5, lane = tid & 31;
    const int wm = wid >> 1, wn = wid & 1;
    const int m0 = blockIdx.y * 128, n0 = blockIdx.x * 128;

    wmma::fragment<wmma::accumulator, 16, 16, 16, float> acc[4][4];
    #pragma unroll
    for (int i = 0; i < 4; i++)
        #pragma unroll
        for (int j = 0; j < 4; j++)
            wmma::fill_fragment(acc[i][j], 0.0f);

    auto load_stage = [&](int st, int kt) {
        bf16* Ah = reinterpret_cast<bf16*>(smraw + st * GSTGB);
        bf16* Al = Ah + 128 * LDK;
        bf16* Bh = Al + 128 * LDK;
        bf16* Bl = Bh + 128 * LDK;
        const int k0 = kt * BK;
        #pragma unroll
        for (int t = 0; t < 4; t++) {
            int item = tid + t * 128;
            int r = item >> 2, c = (item & 3) * 8;
            size_t ga = (size_t)(m0 + r) * Dd + k0 + c;
            size_t gb = (size_t)(n0 + r) * Dd + k0 + c;
            cp16(Ah + r * LDK + c, Ahi + ga);
            cp16(Al + r * LDK + c, Alo + ga);
            cp16(Bh + r * LDK + c, Whi + gb);
            cp16(Bl + r * LDK + c, Wlo + gb);
        }
        cp_commit();
    };

    load_stage(0, 0);
    for (int kt = 0; kt < NKT; kt++) {
        int st = kt & 1;
        if (kt + 1 < NKT) { load_stage(st ^ 1, kt + 1); cp_wait<1>(); }
        else              { cp_wait<0>(); }
        __syncthreads();

        bf16* Ah = reinterpret_cast<bf16*>(smraw + st * GSTGB);
        bf16* Al = Ah + 128 * LDK;
        bf16* Bh = Al + 128 * LDK;
        bf16* Bl = Bh + 128 * LDK;
        #pragma unroll
        for (int ks = 0; ks < BK; ks += 16) {
            wmma::fragment<wmma::matrix_b, 16, 16, 16, bf16, wmma::col_major> bh[4], bl[4];
            #pragma unroll
            for (int j = 0; j < 4; j++) {
                wmma::load_matrix_sync(bh[j], &Bh[(wn * 64 + j * 16) * LDK + ks], LDK);
                wmma::load_matrix_sync(bl[j], &Bl[(wn * 64 + j * 16) * LDK + ks], LDK);
            }
            #pragma unroll
            for (int i = 0; i < 4; i++) {
                wmma::fragment<wmma::matrix_a, 16, 16, 16, bf16, wmma::row_major> ah, al;
                wmma::load_matrix_sync(ah, &Ah[(wm * 64 + i * 16) * LDK + ks], LDK);
                wmma::load_matrix_sync(al, &Al[(wm * 64 + i * 16) * LDK + ks], LDK);
                // pass-reordered: dependent MMAs on acc[i][j] are 4 apart
                #pragma unroll
                for (int j = 0; j < 4; j++) wmma::mma_sync(acc[i][j], ah, bh[j], acc[i][j]);
                #pragma unroll
                for (int j = 0; j < 4; j++) wmma::mma_sync(acc[i][j], ah, bl[j], acc[i][j]);
                #pragma unroll
                for (int j = 0; j < 4; j++) wmma::mma_sync(acc[i][j], al, bh[j], acc[i][j]);
            }
        }
        __syncthreads();
    }

    __syncthreads();
    float* patch = reinterpret_cast<float*>(smraw) + wid * 16 * 20;
    const int er = lane >> 1, eh = (lane & 1) * 8;
    #pragma unroll
    for (int i = 0; i < 4; i++) {
        #pragma unroll
        for (int j = 0; j < 4; j++) {
            wmma::store_matrix_sync(patch, acc[i][j], 20, wmma::mem_row_major);
            __syncwarp();
            int gr = m0 + wm * 64 + i * 16 + er;
            int gc = n0 + wn * 64 + j * 16 + eh;
            size_t go = (size_t)gr * Dd + gc;
            float4 b0 = *reinterpret_cast<const float4*>(&bias[gc]);
            float4 b1 = *reinterpret_cast<const float4*>(&bias[gc + 4]);
            float v[8];
            #pragma unroll
            for (int e = 0; e < 8; e++) v[e] = patch[er * 20 + eh + e];
            v[0] += b0.x; v[1] += b0.y; v[2] += b0.z; v[3] += b0.w;
            v[4] += b1.x; v[5] += b1.y; v[6] += b1.z; v[7] += b1.w;
            if (ACC) {
                float4 o0 = *reinterpret_cast<const float4*>(&Cf[go]);
                float4 o1 = *reinterpret_cast<const float4*>(&Cf[go + 4]);
                v[0] += o0.x; v[1] += o0.y; v[2] += o0.z; v[3] += o0.w;
                v[4] += o1.x; v[5] += o1.y; v[6] += o1.z; v[7] += o1.w;
            }
            if (WF32) {
                *reinterpret_cast<float4*>(&Cf[go])     = *reinterpret_cast<float4*>(&v[0]);
                *reinterpret_cast<float4*>(&Cf[go + 4]) = *reinterpret_cast<float4*>(&v[4]);
            }
            if (WSPLIT) {
                bf16 hs[8], ls[8];
                #pragma unroll
                for (int e = 0; e < 8; e++) split1(v[e], &hs[e], &ls[e]);
                *reinterpret_cast<float4*>(&Chi[go]) = *reinterpret_cast<float4*>(hs);
                *reinterpret_cast<float4*>(&Clo[go]) = *reinterpret_cast<float4*>(ls);
            }
            __syncwarp();
        }
    }
}

// ---------------------------------------------------------------------------
// Fused minicolumn kernel: block 128x64, 4 warps, warp 64x32 (e and i), occ 2.
// Inner MMAs pass-reordered for ILP.
// ---------------------------------------------------------------------------
__global__ __launch_bounds__(128, 2)
void fused_w(const bf16* __restrict__ Ahi, const bf16* __restrict__ Alo,
             const bf16* __restrict__ Weh, const bf16* __restrict__ Wel,
             const bf16* __restrict__ Wih, const bf16* __restrict__ Wil,
             const float* __restrict__ be_l, const float* __restrict__ bi_l,
             const float* __restrict__ Wl_l, const float* __restrict__ bl_l,
             bf16* __restrict__ Mhi, bf16* __restrict__ Mlo) {
    extern __shared__ char smraw[];
    __shared__ float swl[1024];
    __shared__ float sbe[64], sbi[64], sbl[64];

    const int tid = threadIdx.x, wid = tid >> 5, lane = tid & 31;
    const int wm = wid >> 1, wn = wid & 1;
    const int m0 = blockIdx.y * 128, n0 = blockIdx.x * 64;

    for (int i = tid; i < 256; i += 128)
        *reinterpret_cast<float4*>(&swl[i * 4]) =
            *reinterpret_cast<const float4*>(&Wl_l[(size_t)n0 * Hh + i * 4]);
    if (tid < 64) {
        sbe[tid] = be_l[n0 + tid];
        sbi[tid] = bi_l[n0 + tid];
        sbl[tid] = bl_l[n0 + tid];
    }

    wmma::fragment<wmma::accumulator, 16, 16, 16, float> ae[4][2], ai[4][2];
    #pragma unroll
    for (int i = 0; i < 4; i++)
        #pragma unroll
        for (int j = 0; j < 2; j++) {
            wmma::fill_fragment(ae[i][j], 0.0f);
            wmma::fill_fragment(ai[i][j], 0.0f);
        }

    auto load_stage = [&](int st, int kt) {
        bf16* Ah = reinterpret_cast<bf16*>(smraw + st * FSTGB);
        bf16* Al = Ah + 128 * LDK;
        bf16* Eh = Al + 128 * LDK;
        bf16* El = Eh + 64 * LDK;
        bf16* Ih = El + 64 * LDK;
        bf16* Il = Ih + 64 * LDK;
        const int k0 = kt * BK;
        #pragma unroll
        for (int t = 0; t < 4; t++) {
            int item = tid + t * 128;
            int r = item >> 2, c = (item & 3) * 8;
            size_t ga = (size_t)(m0 + r) * Dd + k0 + c;
            cp16(Ah + r * LDK + c, Ahi + ga);
            cp16(Al + r * LDK + c, Alo + ga);
        }
        #pragma unroll
        for (int t = 0; t < 2; t++) {
            int item = tid + t * 128;
            int r = item >> 2, c = (item & 3) * 8;
            size_t gb = (size_t)(n0 + r) * Dd + k0 + c;
            cp16(Eh + r * LDK + c, Weh + gb);
            cp16(El + r * LDK + c, Wel + gb);
            cp16(Ih + r * LDK + c, Wih + gb);
            cp16(Il + r * LDK + c, Wil + gb);
        }
        cp_commit();
    };

    load_stage(0, 0);
    for (int kt = 0; kt < NKT; kt++) {
        int st = kt & 1;
        if (kt + 1 < NKT) { load_stage(st ^ 1, kt + 1); cp_wait<1>(); }
        else              { cp_wait<0>(); }
        __syncthreads();

        bf16* Ah = reinterpret_cast<bf16*>(smraw + st * FSTGB);
        bf16* Al = Ah + 128 * LDK;
        bf16* Eh = Al + 128 * LDK;
        bf16* El = Eh + 64 * LDK;
        bf16* Ih = El + 64 * LDK;
        bf16* Il = Ih + 64 * LDK;
        #pragma unroll
        for (int ks = 0; ks < BK; ks += 16) {
            wmma::fragment<wmma::matrix_b, 16, 16, 16, bf16, wmma::col_major>
                eh[2], el[2], ih[2], il[2];
            #pragma unroll
            for (int j = 0; j < 2; j++) {
                int nb = (wn * 32 + j * 16) * LDK + ks;
                wmma::load_matrix_sync(eh[j], &Eh[nb], LDK);
                wmma::load_matrix_sync(el[j], &El[nb], LDK);
                wmma::load_matrix_sync(ih[j], &Ih[nb], LDK);
                wmma::load_matrix_sync(il[j], &Il[nb], LDK);
            }
            #pragma unroll
            for (int i = 0; i < 4; i++) {
                wmma::fragment<wmma::matrix_a, 16, 16, 16, bf16, wmma::row_major> ah, al;
                wmma::load_matrix_sync(ah, &Ah[(wm * 64 + i * 16) * LDK + ks], LDK);
                wmma::load_matrix_sync(al, &Al[(wm * 64 + i * 16) * LDK + ks], LDK);
                // pass-reordered: dependent MMAs on same accumulator are 4 apart
                #pragma unroll
                for (int j = 0; j < 2; j++) wmma::mma_sync(ae[i][j], ah, eh[j], ae[i][j]);
                #pragma unroll
                for (int j = 0; j < 2; j++) wmma::mma_sync(ai[i][j], ah, ih[j], ai[i][j]);
                #pragma unroll
                for (int j = 0; j < 2; j++) wmma::mma_sync(ae[i][j], ah, el[j], ae[i][j]);
                #pragma unroll
                for (int j = 0; j < 2; j++) wmma::mma_sync(ai[i][j], ah, il[j], ai[i][j]);
                #pragma unroll
                for (int j = 0; j < 2; j++) wmma::mma_sync(ae[i][j], al, eh[j], ae[i][j]);
                #pragma unroll
                for (int j = 0; j < 2; j++) wmma::mma_sync(ai[i][j], al, ih[j], ai[i][j]);
            }
        }
        __syncthreads();
    }

    __syncthreads();
    float* pe = reinterpret_cast<float*>(smraw) + wid * 2 * 16 * 20;
    float* pi = pe + 16 * 20;
    const int er = lane >> 1, eh8 = (lane & 1) * 8;
    #pragma unroll
    for (int i = 0; i < 4; i++) {
        #pragma unroll
        for (int j = 0; j < 2; j++) {
            wmma::store_matrix_sync(pe, ae[i][j], 20, wmma::mem_row_major);
            wmma::store_matrix_sync(pi, ai[i][j], 20, wmma::mem_row_major);
            __syncwarp();
            int ml = wn * 2 + j;
            int gr = m0 + wm * 64 + i * 16 + er;
            float ihv[16];
            #pragma unroll
            for (int h = 0; h < 16; h++)
                ihv[h] = fmaxf(pi[er * 20 + h] + sbi[ml * 16 + h], 0.0f);
            bf16 hs[8], ls[8];
            #pragma unroll
            for (int e = 0; e < 8; e++) {
                int k = eh8 + e;
                float lat = sbl[ml * 16 + k];
                #pragma unroll
                for (int h = 0; h < 16; h++)
                    lat += ihv[h] * swl[ml * 256 + h * 16 + k];
                float ex = fmaxf(pe[er * 20 + k] + sbe[ml * 16 + k], 0.0f);
                split1(fmaxf(ex - lat, 0.0f), &hs[e], &ls[e]);
            }
            size_t go = (size_t)gr * Dd + n0 + ml * 16 + eh8;
            *reinterpret_cast<float4*>(&Mhi[go]) = *reinterpret_cast<float4*>(hs);
            *reinterpret_cast<float4*>(&Mlo[go]) = *reinterpret_cast<float4*>(ls);
            __syncwarp();
        }
    }
}

// ---------------------------------------------------------------------------
// Host orchestration
// ---------------------------------------------------------------------------
extern "C" void kernel_launch(void* const* d_in, const int* in_sizes, int n_in,
                              void* d_out, int out_size) {
    const float* x    = (const float*)d_in[0];
    const float* We   = (const float*)d_in[1];
    const float* be   = (const float*)d_in[2];
    const float* Wi   = (const float*)d_in[3];
    const float* bi   = (const float*)d_in[4];
    const float* Wl   = (const float*)d_in[5];
    const float* bl   = (const float*)d_in[6];
    const float* Wlat = (const float*)d_in[7];
    const float* blat = (const float*)d_in[8];
    const float* Wv   = (const float*)d_in[9];
    const float* bv   = (const float*)d_in[10];
    const float* Wo   = (const float*)d_in[11];
    const float* bo   = (const float*)d_in[12];
    const float* fbW  = (const float*)d_in[13];
    const float* fbb  = (const float*)d_in[14];
    float* out = (float*)d_out;

    bf16 *wc_h, *wc_l, *wv_h, *wv_l, *wo_h, *wo_l, *fb_h, *fb_l;
    bf16 *we_h, *we_l, *wi_h, *wi_l, *a0h, *a0l, *a1h, *a1l;
    bf16 *s1h, *s1l, *s2h, *s2l;
    float *t2, *bc1, *bc2, *bcp, *zero;
    cudaGetSymbolAddress((void**)&wc_h, g_wc_h);
    cudaGetSymbolAddress((void**)&wc_l, g_wc_l);
    cudaGetSymbolAddress((void**)&wv_h, g_wv_h);
    cudaGetSymbolAddress((void**)&wv_l, g_wv_l);
    cudaGetSymbolAddress((void**)&wo_h, g_wo_h);
    cudaGetSymbolAddress((void**)&wo_l, g_wo_l);
    cudaGetSymbolAddress((void**)&fb_h, g_fb_h);
    cudaGetSymbolAddress((void**)&fb_l, g_fb_l);
    cudaGetSymbolAddress((void**)&we_h, g_we_h);
    cudaGetSymbolAddress((void**)&we_l, g_we_l);
    cudaGetSymbolAddress((void**)&wi_h, g_wi_h);
    cudaGetSymbolAddress((void**)&wi_l, g_wi_l);
    cudaGetSymbolAddress((void**)&a0h,  g_a0h);
    cudaGetSymbolAddress((void**)&a0l,  g_a0l);
    cudaGetSymbolAddress((void**)&a1h,  g_a1h);
    cudaGetSymbolAddress((void**)&a1l,  g_a1l);
    cudaGetSymbolAddress((void**)&s1h,  g_s1h);
    cudaGetSymbolAddress((void**)&s1l,  g_s1l);
    cudaGetSymbolAddress((void**)&s2h,  g_s2h);
    cudaGetSymbolAddress((void**)&s2l,  g_s2l);
    cudaGetSymbolAddress((void**)&t2,   g_t2);
    cudaGetSymbolAddress((void**)&bc1,  g_bc1);
    cudaGetSymbolAddress((void**)&bc2,  g_bc2);
    cudaGetSymbolAddress((void**)&bcp,  g_bcp);
    cudaGetSymbolAddress((void**)&zero, g_zero);

    cudaFuncSetAttribute(gemm_w<false, false, true>, cudaFuncAttributeMaxDynamicSharedMemorySize, GDSM);
    cudaFuncSetAttribute(gemm_w<false, true, false>, cudaFuncAttributeMaxDynamicSharedMemorySize, GDSM);
    cudaFuncSetAttribute(gemm_w<false, true, true>,  cudaFuncAttributeMaxDynamicSharedMemorySize, GDSM);
    cudaFuncSetAttribute(gemm_w<true, true, true>,   cudaFuncAttributeMaxDynamicSharedMemorySize, GDSM);
    cudaFuncSetAttribute(fused_w,                    cudaFuncAttributeMaxDynamicSharedMemorySize, FDSM);

    // --- One-time conversions (launches 0-2) ---
    convT_all<<<dim3(32, 32, 17), 256>>>(Wv, Wo, fbW, wv_h, wv_l, wo_h, wo_l, fb_h, fb_l);
    convgT_all<<<dim3(16, 64, 12), 256>>>(We, Wi, we_h, we_l, wi_h, wi_l);
    convact_all<<<(int)(6 * M1 / 4 / 256 + BD / 4 / 256), 256>>>(Wlat, x, s1h, s1l, a1h, a1l);

    // --- Combo weight precompute (launches 3-4) ---
    dim3 gridC(8, 8, 6);
    gemm_w<false, false, true><<<gridC, 128, GDSM>>>(s1h, s1l, wv_h, wv_l,
        zero, nullptr, s2h, s2l, M1, M1, 0, M1);
    gemm_w<false, true, false><<<gridC, 128, GDSM>>>(s2h, s2l, wo_h, wo_l,
        zero, t2, nullptr, nullptr, M1, M1, 0, M1);

    const size_t WL_STRIDE = (size_t)NMC * Hh * Hh;
    dim3 gridG(Dd / 128, Bsz / 128, 1);   // 8 x 128
    dim3 gridF(Dd / 64,  Bsz / 128);      // 16 x 128

    // Launch 5 = fused_w l0 (ncu -s 5 target: the dominant mainloop)
    fused_w<<<gridF, 128, FDSM>>>(a1h, a1l,
        we_h, we_l, wi_h, wi_l,
        be, bi, Wl, bl, a0h, a0l);

    // Combo weight conversion + combined biases (needed before combo-apply l0)
    conv_T<<<dim3(32, 32, 6), 256>>>(t2, wc_h, wc_l);
    bias_part<<<dim3(4, 8, 6), 256>>>(blat, Wv, bcp);
    bias_reduce<<<dim3(4, 6), 256>>>(bcp, bv, bc1);
    bias_part<<<dim3(4, 8, 6), 256>>>(bc1, Wo, bcp);
    bias_reduce<<<dim3(4, 6), 256>>>(bcp, bo, bc2);

    for (int l = 0; l < Lc; l++) {
        if (l > 0) {
            fused_w<<<gridF, 128, FDSM>>>(a1h, a1l,
                we_h + (size_t)l * M1, we_l + (size_t)l * M1,
                wi_h + (size_t)l * M1, wi_l + (size_t)l * M1,
                be + l * Dd, bi + l * Dd, Wl + l * WL_STRIDE, bl + l * Dd,
                a0h, a0l);
        }
        gemm_w<false, true, true><<<gridG, 128, GDSM>>>(a0h, a0l,
            wc_h + (size_t)l * M1, wc_l + (size_t)l * M1,
            bc2 + (size_t)l * Dd, out + (size_t)l * BD, a1h, a1l,
            0, 0, 0, 0);
    }

    int p = 1;
    for (int i = 0; i < Lc - 1; i++) {
        int idx = Lc - 2 - i;
        bf16* sh = p ? a1h : a0h;
        bf16* sl = p ? a1l : a0l;
        bf16* dh = p ? a0h : a1h;
        bf16* dl = p ? a0l : a1l;
        gemm_w<true, true, true><<<gridG, 128, GDSM>>>(sh, sl,
            fb_h + (size_t)i * M1, fb_l + (size_t)i * M1,
            fbb + i * Dd, out + (size_t)idx * BD, dh, dl,
            0, 0, 0, 0);
        p ^= 1;
    }
}

// round 11
// speedup vs baseline: 1.1269x; 1.0348x over previous
#include <cuda_runtime.h>
#include <cuda_bf16.h>
#include <mma.h>
#include <cstdint>

using namespace nvcuda;
typedef __nv_bfloat16  bf16;
typedef __nv_bfloat162 bf162;

// Problem constants
#define Bsz 16384
#define Dd  1024
#define Lc  6
#define NMC 64
#define Hh  16
#define M1  (1024 * 1024)
#define BD  ((size_t)Bsz * Dd)

// Tiling: block 128x128 (generic) / 128x64 (fused), 4 warps, warp 64x64/64x32, occ 2
#define BK   32
#define LDK  40
#define MATB (128 * LDK * 2)
#define GSTGB (4 * MATB)                        // 40960 B/stage
#define FSTGB (2 * MATB + 4 * (64 * LDK * 2))   // 40960 B/stage
#define GDSM (2 * GSTGB)
#define FDSM (2 * FSTGB)
#define NKT  (Dd / BK)

// ---------------------------------------------------------------------------
// Persistent buffers
// ---------------------------------------------------------------------------
__device__ bf16 g_wc_h [6 * M1], g_wc_l [6 * M1];   // combo weights, [n][k]
__device__ bf16 g_wv_h [6 * M1], g_wv_l [6 * M1];
__device__ bf16 g_wo_h [6 * M1], g_wo_l [6 * M1];
__device__ bf16 g_fb_h [5 * M1], g_fb_l [5 * M1];
__device__ bf16 g_we_h [6 * M1], g_we_l [6 * M1];   // gathered [n=m*16+h][k=d]
__device__ bf16 g_wi_h [6 * M1], g_wi_l [6 * M1];
__device__ bf16 g_s1h[6 * M1], g_s1l[6 * M1];
__device__ bf16 g_s2h[6 * M1], g_s2l[6 * M1];
__device__ float g_t2[6 * M1];
__device__ float g_bc1[6 * Dd], g_bc2[6 * Dd];
__device__ float g_bcp[6 * 8 * Dd];                 // bias partials
__device__ float g_zero[Dd];
__device__ bf16 g_a0h[BD], g_a0l[BD], g_a1h[BD], g_a1l[BD];

__device__ __forceinline__ void split1(float v, bf16* h, bf16* l) {
    bf16 hh = __float2bfloat16(v);
    *h = hh;
    *l = __float2bfloat16(v - __bfloat162float(hh));
}

__device__ __forceinline__ void cp16(void* smem, const void* g) {
    uint32_t s = (uint32_t)__cvta_generic_to_shared(smem);
    asm volatile("cp.async.cg.shared.global [%0], [%1], 16;" :: "r"(s), "l"(g));
}
__device__ __forceinline__ void cp_commit() { asm volatile("cp.async.commit_group;"); }
template <int N>
__device__ __forceinline__ void cp_wait() {
    asm volatile("cp.async.wait_group %0;" :: "n"(N));
}

// ---------------------------------------------------------------------------
// Conversion kernels
// ---------------------------------------------------------------------------
__device__ __forceinline__ void convT_body(const float* S, bf16* H, bf16* L,
                                           int k0, int n0, int tid) {
    __shared__ float t[32][33];
    const int r = tid >> 5, c = tid & 31;
    #pragma unroll
    for (int i = 0; i < 4; i++)
        t[r + i * 8][c] = S[(size_t)(k0 + r + i * 8) * Dd + n0 + c];
    __syncthreads();
    #pragma unroll
    for (int i = 0; i < 4; i++) {
        bf16 hb, lb; split1(t[c][r + i * 8], &hb, &lb);
        size_t o = (size_t)(n0 + r + i * 8) * Dd + k0 + c;
        H[o] = hb; L[o] = lb;
    }
}

__global__ void convT_all(const float* __restrict__ Wv, const float* __restrict__ Wo,
                          const float* __restrict__ fbW,
                          bf16* __restrict__ wvh, bf16* __restrict__ wvl,
                          bf16* __restrict__ woh, bf16* __restrict__ wol,
                          bf16* __restrict__ fbh, bf16* __restrict__ fbl) {
    const int z = blockIdx.z;
    const float* S; bf16 *H, *L;
    if (z < 6)       { S = Wv  + (size_t)z * M1;        H = wvh + (size_t)z * M1;        L = wvl + (size_t)z * M1; }
    else if (z < 12) { S = Wo  + (size_t)(z - 6) * M1;  H = woh + (size_t)(z - 6) * M1;  L = wol + (size_t)(z - 6) * M1; }
    else             { S = fbW + (size_t)(z - 12) * M1; H = fbh + (size_t)(z - 12) * M1; L = fbl + (size_t)(z - 12) * M1; }
    convT_body(S, H, L, blockIdx.y * 32, blockIdx.x * 32, threadIdx.x);
}

__global__ void conv_T(const float* __restrict__ src, bf16* __restrict__ hi,
                       bf16* __restrict__ lo) {
    const int l = blockIdx.z;
    convT_body(src + (size_t)l * M1, hi + (size_t)l * M1, lo + (size_t)l * M1,
               blockIdx.y * 32, blockIdx.x * 32, threadIdx.x);
}

__global__ void convgT_all(const float* __restrict__ We, const float* __restrict__ Wi,
                           bf16* __restrict__ weh, bf16* __restrict__ wel,
                           bf16* __restrict__ wih, bf16* __restrict__ wil) {
    __shared__ float t[64][17];
    const int z = blockIdx.z;
    const int l = (z < 6) ? z : z - 6;
    const float* src = (z < 6) ? We : Wi;
    bf16* hi = (z < 6) ? weh : wih;
    bf16* lo = (z < 6) ? wel : wil;
    const int d0 = blockIdx.x * 64, m = blockIdx.y;
    const int tid = threadIdx.x;
    {
        int dd = tid >> 2, h4 = (tid & 3) * 4;
        float4 v = *reinterpret_cast<const float4*>(
            &src[((size_t)(l * NMC + m) * Dd + d0 + dd) * Hh + h4]);
        t[dd][h4] = v.x; t[dd][h4 + 1] = v.y; t[dd][h4 + 2] = v.z; t[dd][h4 + 3] = v.w;
    }
    __syncthreads();
    int h = tid >> 4, cq = tid & 15;
    size_t rowo = (size_t)l * M1 + (size_t)(m * 16 + h) * Dd + d0 + cq * 4;
    #pragma unroll
    for (int j = 0; j < 4; j++) {
        bf16 hb, lb; split1(t[cq * 4 + j][h], &hb, &lb);
        hi[rowo + j] = hb; lo[rowo + j] = lb;
    }
}

__global__ void convact_all(const float* __restrict__ Wlat, const float* __restrict__ x,
                            bf16* __restrict__ s1h, bf16* __restrict__ s1l,
                            bf16* __restrict__ a1h, bf16* __restrict__ a1l) {
    size_t idx = (size_t)blockIdx.x * blockDim.x + threadIdx.x;   // float4 index
    const size_t n1 = (size_t)6 * M1 / 4;
    const float* src; bf16 *hi, *lo; size_t i;
    if (idx < n1) { src = Wlat; hi = s1h; lo = s1l; i = idx * 4; }
    else          { src = x;    hi = a1h; lo = a1l; i = (idx - n1) * 4; }
    float4 v = *reinterpret_cast<const float4*>(src + i);
    bf16 hs[4], ls[4];
    split1(v.x, &hs[0], &ls[0]); split1(v.y, &hs[1], &ls[1]);
    split1(v.z, &hs[2], &ls[2]); split1(v.w, &hs[3], &ls[3]);
    *reinterpret_cast<float2*>(hi + i) = *reinterpret_cast<float2*>(hs);
    *reinterpret_cast<float2*>(lo + i) = *reinterpret_cast<float2*>(ls);
}

// Bias combo, deterministic 2-phase
__global__ void bias_part(const float* __restrict__ bin, const float* __restrict__ W,
                          float* __restrict__ bcp) {
    const int l = blockIdx.z;
    const int i0 = blockIdx.y * 128;
    const int j = blockIdx.x * 256 + threadIdx.x;
    const float* Wl = W + (size_t)l * M1;
    const float* bi = bin + (size_t)l * Dd;
    float s = 0.0f;
    #pragma unroll 4
    for (int i = i0; i < i0 + 128; i++) s += bi[i] * Wl[(size_t)i * Dd + j];
    bcp[((size_t)l * 8 + blockIdx.y) * Dd + j] = s;
}
__global__ void bias_reduce(const float* __restrict__ bcp, const float* __restrict__ badd,
                            float* __restrict__ bc) {
    const int l = blockIdx.y;
    const int j = blockIdx.x * 256 + threadIdx.x;
    float s = badd[(size_t)l * Dd + j];
    #pragma unroll
    for (int c = 0; c < 8; c++) s += bcp[((size_t)l * 8 + c) * Dd + j];
    bc[(size_t)l * Dd + j] = s;
}

// ---------------------------------------------------------------------------
// GEMM: C = (ACC ? Cf : 0) + A @ W + bias. Block 128x128, 4 warps, warp 64x64,
// occ 2. B band processed in two 32-wide halves per k-step to cap register
// liveness (~206 regs, no spills).
// ---------------------------------------------------------------------------
template <bool ACC, bool WF32, bool WSPLIT>
__global__ __launch_bounds__(128, 2)
void gemm_w(const bf16* __restrict__ Ahi_, const bf16* __restrict__ Alo_,
            const bf16* __restrict__ Whi_, const bf16* __restrict__ Wlo_,
            const float* __restrict__ bias_, float* __restrict__ Cf_,
            bf16* __restrict__ Chi_, bf16* __restrict__ Clo_,
            size_t sA, size_t sW, size_t sB, size_t sC) {
    extern __shared__ char smraw[];
    const int z = blockIdx.z;
    const bf16* Ahi = Ahi_ + (size_t)z * sA;
    const bf16* Alo = Alo_ + (size_t)z * sA;
    const bf16* Whi = Whi_ + (size_t)z * sW;
    const bf16* Wlo = Wlo_ + (size_t)z * sW;
    const float* bias = bias_ + (size_t)z * sB;
    float* Cf = WF32 ? Cf_ + (size_t)z * sC : nullptr;
    bf16* Chi = WSPLIT ? Chi_ + (size_t)z * sC : nullptr;
    bf16* Clo = WSPLIT ? Clo_ + (size_t)z * sC : nullptr;

    const int tid = threadIdx.x, wid = tid >> 5, lane = tid & 31;
    const int wm = wid >> 1, wn = wid & 1;
    const int m0 = blockIdx.y * 128, n0 = blockIdx.x * 128;

    wmma::fragment<wmma::accumulator, 16, 16, 16, float> acc[4][4];
    #pragma unroll
    for (int i = 0; i < 4; i++)
        #pragma unroll
        for (int j = 0; j < 4; j++)
            wmma::fill_fragment(acc[i][j], 0.0f);

    auto load_stage = [&](int st, int kt) {
        bf16* Ah = reinterpret_cast<bf16*>(smraw + st * GSTGB);
        bf16* Al = Ah + 128 * LDK;
        bf16* Bh = Al + 128 * LDK;
        bf16* Bl = Bh + 128 * LDK;
        const int k0 = kt * BK;
        #pragma unroll
        for (int t = 0; t < 4; t++) {
            int item = tid + t * 128;
            int r = item >> 2, c = (item & 3) * 8;
            size_t ga = (size_t)(m0 + r) * Dd + k0 + c;
            size_t gb = (size_t)(n0 + r) * Dd + k0 + c;
            cp16(Ah + r * LDK + c, Ahi + ga);
            cp16(Al + r * LDK + c, Alo + ga);
            cp16(Bh + r * LDK + c, Whi + gb);
            cp16(Bl + r * LDK + c, Wlo + gb);
        }
        cp_commit();
    };

    load_stage(0, 0);
    for (int kt = 0; kt < NKT; kt++) {
        int st = kt & 1;
        if (kt + 1 < NKT) { load_stage(st ^ 1, kt + 1); cp_wait<1>(); }
        else              { cp_wait<0>(); }
        __syncthreads();

        bf16* Ah = reinterpret_cast<bf16*>(smraw + st * GSTGB);
        bf16* Al = Ah + 128 * LDK;
        bf16* Bh = Al + 128 * LDK;
        bf16* Bl = Bh + 128 * LDK;
        #pragma unroll
        for (int ks = 0; ks < BK; ks += 16) {
            // Two 32-wide B halves: only 4 B fragments live at a time.
            #pragma unroll
            for (int jh = 0; jh < 2; jh++) {
                wmma::fragment<wmma::matrix_b, 16, 16, 16, bf16, wmma::col_major> bh[2], bl[2];
                #pragma unroll
                for (int j = 0; j < 2; j++) {
                    int nb = (wn * 64 + (jh * 2 + j) * 16) * LDK + ks;
                    wmma::load_matrix_sync(bh[j], &Bh[nb], LDK);
                    wmma::load_matrix_sync(bl[j], &Bl[nb], LDK);
                }
                #pragma unroll
                for (int i = 0; i < 4; i++) {
                    wmma::fragment<wmma::matrix_a, 16, 16, 16, bf16, wmma::row_major> ah, al;
                    wmma::load_matrix_sync(ah, &Ah[(wm * 64 + i * 16) * LDK + ks], LDK);
                    wmma::load_matrix_sync(al, &Al[(wm * 64 + i * 16) * LDK + ks], LDK);
                    #pragma unroll
                    for (int j = 0; j < 2; j++)
                        wmma::mma_sync(acc[i][jh * 2 + j], ah, bh[j], acc[i][jh * 2 + j]);
                    #pragma unroll
                    for (int j = 0; j < 2; j++)
                        wmma::mma_sync(acc[i][jh * 2 + j], ah, bl[j], acc[i][jh * 2 + j]);
                    #pragma unroll
                    for (int j = 0; j < 2; j++)
                        wmma::mma_sync(acc[i][jh * 2 + j], al, bh[j], acc[i][jh * 2 + j]);
                }
            }
        }
        __syncthreads();
    }

    __syncthreads();
    float* patch = reinterpret_cast<float*>(smraw) + wid * 16 * 20;
    const int er = lane >> 1, eh = (lane & 1) * 8;
    #pragma unroll
    for (int i = 0; i < 4; i++) {
        #pragma unroll
        for (int j = 0; j < 4; j++) {
            wmma::store_matrix_sync(patch, acc[i][j], 20, wmma::mem_row_major);
            __syncwarp();
            int gr = m0 + wm * 64 + i * 16 + er;
            int gc = n0 + wn * 64 + j * 16 + eh;
            size_t go = (size_t)gr * Dd + gc;
            float4 b0 = *reinterpret_cast<const float4*>(&bias[gc]);
            float4 b1 = *reinterpret_cast<const float4*>(&bias[gc + 4]);
            float v[8];
            #pragma unroll
            for (int e = 0; e < 8; e++) v[e] = patch[er * 20 + eh + e];
            v[0] += b0.x; v[1] += b0.y; v[2] += b0.z; v[3] += b0.w;
            v[4] += b1.x; v[5] += b1.y; v[6] += b1.z; v[7] += b1.w;
            if (ACC) {
                float4 o0 = *reinterpret_cast<const float4*>(&Cf[go]);
                float4 o1 = *reinterpret_cast<const float4*>(&Cf[go + 4]);
                v[0] += o0.x; v[1] += o0.y; v[2] += o0.z; v[3] += o0.w;
                v[4] += o1.x; v[5] += o1.y; v[6] += o1.z; v[7] += o1.w;
            }
            if (WF32) {
                *reinterpret_cast<float4*>(&Cf[go])     = *reinterpret_cast<float4*>(&v[0]);
                *reinterpret_cast<float4*>(&Cf[go + 4]) = *reinterpret_cast<float4*>(&v[4]);
            }
            if (WSPLIT) {
                bf16 hs[8], ls[8];
                #pragma unroll
                for (int e = 0; e < 8; e++) split1(v[e], &hs[e], &ls[e]);
                *reinterpret_cast<float4*>(&Chi[go]) = *reinterpret_cast<float4*>(hs);
                *reinterpret_cast<float4*>(&Clo[go]) = *reinterpret_cast<float4*>(ls);
            }
            __syncwarp();
        }
    }
}

// ---------------------------------------------------------------------------
// Fused minicolumn kernel: block 128x64, 4 warps, warp 64x32 (e and i), occ 2.
// e-half and i-half processed sequentially per k-step to cap register liveness.
// ---------------------------------------------------------------------------
__global__ __launch_bounds__(128, 2)
void fused_w(const bf16* __restrict__ Ahi, const bf16* __restrict__ Alo,
             const bf16* __restrict__ Weh, const bf16* __restrict__ Wel,
             const bf16* __restrict__ Wih, const bf16* __restrict__ Wil,
             const float* __restrict__ be_l, const float* __restrict__ bi_l,
             const float* __restrict__ Wl_l, const float* __restrict__ bl_l,
             bf16* __restrict__ Mhi, bf16* __restrict__ Mlo) {
    extern __shared__ char smraw[];
    __shared__ float swl[1024];
    __shared__ float sbe[64], sbi[64], sbl[64];

    const int tid = threadIdx.x, wid = tid >> 5, lane = tid & 31;
    const int wm = wid >> 1, wn = wid & 1;
    const int m0 = blockIdx.y * 128, n0 = blockIdx.x * 64;

    for (int i = tid; i < 256; i += 128)
        *reinterpret_cast<float4*>(&swl[i * 4]) =
            *reinterpret_cast<const float4*>(&Wl_l[(size_t)n0 * Hh + i * 4]);
    if (tid < 64) {
        sbe[tid] = be_l[n0 + tid];
        sbi[tid] = bi_l[n0 + tid];
        sbl[tid] = bl_l[n0 + tid];
    }

    wmma::fragment<wmma::accumulator, 16, 16, 16, float> ae[4][2], ai[4][2];
    #pragma unroll
    for (int i = 0; i < 4; i++)
        #pragma unroll
        for (int j = 0; j < 2; j++) {
            wmma::fill_fragment(ae[i][j], 0.0f);
            wmma::fill_fragment(ai[i][j], 0.0f);
        }

    auto load_stage = [&](int st, int kt) {
        bf16* Ah = reinterpret_cast<bf16*>(smraw + st * FSTGB);
        bf16* Al = Ah + 128 * LDK;
        bf16* Eh = Al + 128 * LDK;
        bf16* El = Eh + 64 * LDK;
        bf16* Ih = El + 64 * LDK;
        bf16* Il = Ih + 64 * LDK;
        const int k0 = kt * BK;
        #pragma unroll
        for (int t = 0; t < 4; t++) {
            int item = tid + t * 128;
            int r = item >> 2, c = (item & 3) * 8;
            size_t ga = (size_t)(m0 + r) * Dd + k0 + c;
            cp16(Ah + r * LDK + c, Ahi + ga);
            cp16(Al + r * LDK + c, Alo + ga);
        }
        #pragma unroll
        for (int t = 0; t < 2; t++) {
            int item = tid + t * 128;
            int r = item >> 2, c = (item & 3) * 8;
            size_t gb = (size_t)(n0 + r) * Dd + k0 + c;
            cp16(Eh + r * LDK + c, Weh + gb);
            cp16(El + r * LDK + c, Wel + gb);
            cp16(Ih + r * LDK + c, Wih + gb);
            cp16(Il + r * LDK + c, Wil + gb);
        }
        cp_commit();
    };

    load_stage(0, 0);
    for (int kt = 0; kt < NKT; kt++) {
        int st = kt & 1;
        if (kt + 1 < NKT) { load_stage(st ^ 1, kt + 1); cp_wait<1>(); }
        else              { cp_wait<0>(); }
        __syncthreads();

        bf16* Ah = reinterpret_cast<bf16*>(smraw + st * FSTGB);
        bf16* Al = Ah + 128 * LDK;
        bf16* Eh = Al + 128 * LDK;
        bf16* El = Eh + 64 * LDK;
        bf16* Ih = El + 64 * LDK;
        bf16* Il = Ih + 64 * LDK;
        #pragma unroll
        for (int ks = 0; ks < BK; ks += 16) {
            // e-half then i-half: only 4 B fragments live at a time
            #pragma unroll
            for (int half = 0; half < 2; half++) {
                const bf16* Xh = half ? Ih : Eh;
                const bf16* Xl = half ? Il : El;
                wmma::fragment<wmma::matrix_b, 16, 16, 16, bf16, wmma::col_major> xh[2], xl[2];
                #pragma unroll
                for (int j = 0; j < 2; j++) {
                    int nb = (wn * 32 + j * 16) * LDK + ks;
                    wmma::load_matrix_sync(xh[j], &Xh[nb], LDK);
                    wmma::load_matrix_sync(xl[j], &Xl[nb], LDK);
                }
                #pragma unroll
                for (int i = 0; i < 4; i++) {
                    wmma::fragment<wmma::matrix_a, 16, 16, 16, bf16, wmma::row_major> ah, al;
                    wmma::load_matrix_sync(ah, &Ah[(wm * 64 + i * 16) * LDK + ks], LDK);
                    wmma::load_matrix_sync(al, &Al[(wm * 64 + i * 16) * LDK + ks], LDK);
                    wmma::fragment<wmma::accumulator, 16, 16, 16, float>* ax =
                        half ? ai[i] : ae[i];
                    #pragma unroll
                    for (int j = 0; j < 2; j++) wmma::mma_sync(ax[j], ah, xh[j], ax[j]);
                    #pragma unroll
                    for (int j = 0; j < 2; j++) wmma::mma_sync(ax[j], ah, xl[j], ax[j]);
                    #pragma unroll
                    for (int j = 0; j < 2; j++) wmma::mma_sync(ax[j], al, xh[j], ax[j]);
                }
            }
        }
        __syncthreads();
    }

    __syncthreads();
    float* pe = reinterpret_cast<float*>(smraw) + wid * 2 * 16 * 20;
    float* pi = pe + 16 * 20;
    const int er = lane >> 1, eh8 = (lane & 1) * 8;
    #pragma unroll
    for (int i = 0; i < 4; i++) {
        #pragma unroll
        for (int j = 0; j < 2; j++) {
            wmma::store_matrix_sync(pe, ae[i][j], 20, wmma::mem_row_major);
            wmma::store_matrix_sync(pi, ai[i][j], 20, wmma::mem_row_major);
            __syncwarp();
            int ml = wn * 2 + j;
            int gr = m0 + wm * 64 + i * 16 + er;
            float ihv[16];
            #pragma unroll
            for (int h = 0; h < 16; h++)
                ihv[h] = fmaxf(pi[er * 20 + h] + sbi[ml * 16 + h], 0.0f);
            bf16 hs[8], ls[8];
            #pragma unroll
            for (int e = 0; e < 8; e++) {
                int k = eh8 + e;
                float lat = sbl[ml * 16 + k];
                #pragma unroll
                for (int h = 0; h < 16; h++)
                    lat += ihv[h] * swl[ml * 256 + h * 16 + k];
                float ex = fmaxf(pe[er * 20 + k] + sbe[ml * 16 + k], 0.0f);
                split1(fmaxf(ex - lat, 0.0f), &hs[e], &ls[e]);
            }
            size_t go = (size_t)gr * Dd + n0 + ml * 16 + eh8;
            *reinterpret_cast<float4*>(&Mhi[go]) = *reinterpret_cast<float4*>(hs);
            *reinterpret_cast<float4*>(&Mlo[go]) = *reinterpret_cast<float4*>(ls);
            __syncwarp();
        }
    }
}

// ---------------------------------------------------------------------------
// Host orchestration
// ---------------------------------------------------------------------------
extern "C" void kernel_launch(void* const* d_in, const int* in_sizes, int n_in,
                              void* d_out, int out_size) {
    const float* x    = (const float*)d_in[0];
    const float* We   = (const float*)d_in[1];
    const float* be   = (const float*)d_in[2];
    const float* Wi   = (const float*)d_in[3];
    const float* bi   = (const float*)d_in[4];
    const float* Wl   = (const float*)d_in[5];
    const float* bl   = (const float*)d_in[6];
    const float* Wlat = (const float*)d_in[7];
    const float* blat = (const float*)d_in[8];
    const float* Wv   = (const float*)d_in[9];
    const float* bv   = (const float*)d_in[10];
    const float* Wo   = (const float*)d_in[11];
    const float* bo   = (const float*)d_in[12];
    const float* fbW  = (const float*)d_in[13];
    const float* fbb  = (const float*)d_in[14];
    float* out = (float*)d_out;

    bf16 *wc_h, *wc_l, *wv_h, *wv_l, *wo_h, *wo_l, *fb_h, *fb_l;
    bf16 *we_h, *we_l, *wi_h, *wi_l, *a0h, *a0l, *a1h, *a1l;
    bf16 *s1h, *s1l, *s2h, *s2l;
    float *t2, *bc1, *bc2, *bcp, *zero;
    cudaGetSymbolAddress((void**)&wc_h, g_wc_h);
    cudaGetSymbolAddress((void**)&wc_l, g_wc_l);
    cudaGetSymbolAddress((void**)&wv_h, g_wv_h);
    cudaGetSymbolAddress((void**)&wv_l, g_wv_l);
    cudaGetSymbolAddress((void**)&wo_h, g_wo_h);
    cudaGetSymbolAddress((void**)&wo_l, g_wo_l);
    cudaGetSymbolAddress((void**)&fb_h, g_fb_h);
    cudaGetSymbolAddress((void**)&fb_l, g_fb_l);
    cudaGetSymbolAddress((void**)&we_h, g_we_h);
    cudaGetSymbolAddress((void**)&we_l, g_we_l);
    cudaGetSymbolAddress((void**)&wi_h, g_wi_h);
    cudaGetSymbolAddress((void**)&wi_l, g_wi_l);
    cudaGetSymbolAddress((void**)&a0h,  g_a0h);
    cudaGetSymbolAddress((void**)&a0l,  g_a0l);
    cudaGetSymbolAddress((void**)&a1h,  g_a1h);
    cudaGetSymbolAddress((void**)&a1l,  g_a1l);
    cudaGetSymbolAddress((void**)&s1h,  g_s1h);
    cudaGetSymbolAddress((void**)&s1l,  g_s1l);
    cudaGetSymbolAddress((void**)&s2h,  g_s2h);
    cudaGetSymbolAddress((void**)&s2l,  g_s2l);
    cudaGetSymbolAddress((void**)&t2,   g_t2);
    cudaGetSymbolAddress((void**)&bc1,  g_bc1);
    cudaGetSymbolAddress((void**)&bc2,  g_bc2);
    cudaGetSymbolAddress((void**)&bcp,  g_bcp);
    cudaGetSymbolAddress((void**)&zero, g_zero);

    cudaFuncSetAttribute(gemm_w<false, false, true>, cudaFuncAttributeMaxDynamicSharedMemorySize, GDSM);
    cudaFuncSetAttribute(gemm_w<false, true, false>, cudaFuncAttributeMaxDynamicSharedMemorySize, GDSM);
    cudaFuncSetAttribute(gemm_w<false, true, true>,  cudaFuncAttributeMaxDynamicSharedMemorySize, GDSM);
    cudaFuncSetAttribute(gemm_w<true, true, true>,   cudaFuncAttributeMaxDynamicSharedMemorySize, GDSM);
    cudaFuncSetAttribute(fused_w,                    cudaFuncAttributeMaxDynamicSharedMemorySize, FDSM);

    // --- One-time conversions (launches 0-2) ---
    convT_all<<<dim3(32, 32, 17), 256>>>(Wv, Wo, fbW, wv_h, wv_l, wo_h, wo_l, fb_h, fb_l);
    convgT_all<<<dim3(16, 64, 12), 256>>>(We, Wi, we_h, we_l, wi_h, wi_l);
    convact_all<<<(int)(6 * M1 / 4 / 256 + BD / 4 / 256), 256>>>(Wlat, x, s1h, s1l, a1h, a1l);

    // --- Combo weight precompute (launches 3-4) ---
    dim3 gridC(8, 8, 6);
    gemm_w<false, false, true><<<gridC, 128, GDSM>>>(s1h, s1l, wv_h, wv_l,
        zero, nullptr, s2h, s2l, M1, M1, 0, M1);
    gemm_w<false, true, false><<<gridC, 128, GDSM>>>(s2h, s2l, wo_h, wo_l,
        zero, t2, nullptr, nullptr, M1, M1, 0, M1);

    const size_t WL_STRIDE = (size_t)NMC * Hh * Hh;
    dim3 gridG(Dd / 128, Bsz / 128, 1);   // 8 x 128
    dim3 gridF(Dd / 64,  Bsz / 128);      // 16 x 128

    // Launch 5 = fused_w l0 (ncu -s 5 target)
    fused_w<<<gridF, 128, FDSM>>>(a1h, a1l,
        we_h, we_l, wi_h, wi_l,
        be, bi, Wl, bl, a0h, a0l);

    conv_T<<<dim3(32, 32, 6), 256>>>(t2, wc_h, wc_l);
    bias_part<<<dim3(4, 8, 6), 256>>>(blat, Wv, bcp);
    bias_reduce<<<dim3(4, 6), 256>>>(bcp, bv, bc1);
    bias_part<<<dim3(4, 8, 6), 256>>>(bc1, Wo, bcp);
    bias_reduce<<<dim3(4, 6), 256>>>(bcp, bo, bc2);

    for (int l = 0; l < Lc; l++) {
        if (l > 0) {
            fused_w<<<gridF, 128, FDSM>>>(a1h, a1l,
                we_h + (size_t)l * M1, we_l + (size_t)l * M1,
                wi_h + (size_t)l * M1, wi_l + (size_t)l * M1,
                be + l * Dd, bi + l * Dd, Wl + l * WL_STRIDE, bl + l * Dd,
                a0h, a0l);
        }
        gemm_w<false, true, true><<<gridG, 128, GDSM>>>(a0h, a0l,
            wc_h + (size_t)l * M1, wc_l + (size_t)l * M1,
            bc2 + (size_t)l * Dd, out + (size_t)l * BD, a1h, a1l,
            0, 0, 0, 0);
    }

    int p = 1;
    for (int i = 0; i < Lc - 1; i++) {
        int idx = Lc - 2 - i;
        bf16* sh = p ? a1h : a0h;
        bf16* sl = p ? a1l : a0l;
        bf16* dh = p ? a0h : a1h;
        bf16* dl = p ? a0l : a1l;
        gemm_w<true, true, true><<<gridG, 128, GDSM>>>(sh, sl,
            fb_h + (size_t)i * M1, fb_l + (size_t)i * M1,
            fbb + i * Dd, out + (size_t)idx * BD, dh, dl,
            0, 0, 0, 0);
        p ^= 1;
    }
}

// round 12
// speedup vs baseline: 1.2454x; 1.1051x over previous
#include <cuda_runtime.h>
#include <cuda_bf16.h>
#include <mma.h>
#include <cstdint>

using namespace nvcuda;
typedef __nv_bfloat16  bf16;
typedef __nv_bfloat162 bf162;

// Problem constants
#define Bsz 16384
#define Dd  1024
#define Lc  6
#define NMC 64
#define Hh  16
#define M1  (1024 * 1024)
#define BD  ((size_t)Bsz * Dd)

// Tiling: block 128x128 (generic) / 128x64 (fused), 4 warps, occ 2
#define BK   32
#define LDK  40
#define MATB (128 * LDK * 2)
#define GSTGB (4 * MATB)                        // 40960 B/stage
#define FSTGB (2 * MATB + 3 * (64 * LDK * 2))   // 35840 B/stage (Eh,El,Ih only)
#define GDSM (2 * GSTGB)
#define FDSM (2 * FSTGB)
#define NKT  (Dd / BK)

// ---------------------------------------------------------------------------
// Persistent buffers
// ---------------------------------------------------------------------------
__device__ bf16 g_wc_h [6 * M1], g_wc_l [6 * M1];   // combo weights, [n][k]
__device__ bf16 g_wv_h [6 * M1], g_wv_l [6 * M1];
__device__ bf16 g_wo_h [6 * M1], g_wo_l [6 * M1];
__device__ bf16 g_fb_h [5 * M1], g_fb_l [5 * M1];
__device__ bf16 g_we_h [6 * M1], g_we_l [6 * M1];   // gathered [n=m*16+h][k=d]
__device__ bf16 g_wi_h [6 * M1], g_wi_l [6 * M1];   // (wi_l unused by fused now)
__device__ bf16 g_s1h[6 * M1], g_s1l[6 * M1];
__device__ bf16 g_s2h[6 * M1], g_s2l[6 * M1];
__device__ float g_t2[6 * M1];
__device__ float g_bc1[6 * Dd], g_bc2[6 * Dd];
__device__ float g_bcp[6 * 8 * Dd];                 // bias partials
__device__ float g_zero[Dd];
__device__ bf16 g_a0h[BD], g_a0l[BD], g_a1h[BD], g_a1l[BD];

__device__ __forceinline__ void split1(float v, bf16* h, bf16* l) {
    bf16 hh = __float2bfloat16(v);
    *h = hh;
    *l = __float2bfloat16(v - __bfloat162float(hh));
}

__device__ __forceinline__ void cp16(void* smem, const void* g) {
    uint32_t s = (uint32_t)__cvta_generic_to_shared(smem);
    asm volatile("cp.async.cg.shared.global [%0], [%1], 16;" :: "r"(s), "l"(g));
}
__device__ __forceinline__ void cp_commit() { asm volatile("cp.async.commit_group;"); }
template <int N>
__device__ __forceinline__ void cp_wait() {
    asm volatile("cp.async.wait_group %0;" :: "n"(N));
}

// ---------------------------------------------------------------------------
// Conversion kernels
// ---------------------------------------------------------------------------
__device__ __forceinline__ void convT_body(const float* S, bf16* H, bf16* L,
                                           int k0, int n0, int tid) {
    __shared__ float t[32][33];
    const int r = tid >> 5, c = tid & 31;
    #pragma unroll
    for (int i = 0; i < 4; i++)
        t[r + i * 8][c] = S[(size_t)(k0 + r + i * 8) * Dd + n0 + c];
    __syncthreads();
    #pragma unroll
    for (int i = 0; i < 4; i++) {
        bf16 hb, lb; split1(t[c][r + i * 8], &hb, &lb);
        size_t o = (size_t)(n0 + r + i * 8) * Dd + k0 + c;
        H[o] = hb; L[o] = lb;
    }
}

__global__ void convT_all(const float* __restrict__ Wv, const float* __restrict__ Wo,
                          const float* __restrict__ fbW,
                          bf16* __restrict__ wvh, bf16* __restrict__ wvl,
                          bf16* __restrict__ woh, bf16* __restrict__ wol,
                          bf16* __restrict__ fbh, bf16* __restrict__ fbl) {
    const int z = blockIdx.z;
    const float* S; bf16 *H, *L;
    if (z < 6)       { S = Wv  + (size_t)z * M1;        H = wvh + (size_t)z * M1;        L = wvl + (size_t)z * M1; }
    else if (z < 12) { S = Wo  + (size_t)(z - 6) * M1;  H = woh + (size_t)(z - 6) * M1;  L = wol + (size_t)(z - 6) * M1; }
    else             { S = fbW + (size_t)(z - 12) * M1; H = fbh + (size_t)(z - 12) * M1; L = fbl + (size_t)(z - 12) * M1; }
    convT_body(S, H, L, blockIdx.y * 32, blockIdx.x * 32, threadIdx.x);
}

__global__ void conv_T(const float* __restrict__ src, bf16* __restrict__ hi,
                       bf16* __restrict__ lo) {
    const int l = blockIdx.z;
    convT_body(src + (size_t)l * M1, hi + (size_t)l * M1, lo + (size_t)l * M1,
               blockIdx.y * 32, blockIdx.x * 32, threadIdx.x);
}

__global__ void convgT_all(const float* __restrict__ We, const float* __restrict__ Wi,
                           bf16* __restrict__ weh, bf16* __restrict__ wel,
                           bf16* __restrict__ wih, bf16* __restrict__ wil) {
    __shared__ float t[64][17];
    const int z = blockIdx.z;
    const int l = (z < 6) ? z : z - 6;
    const float* src = (z < 6) ? We : Wi;
    bf16* hi = (z < 6) ? weh : wih;
    bf16* lo = (z < 6) ? wel : wil;
    const int d0 = blockIdx.x * 64, m = blockIdx.y;
    const int tid = threadIdx.x;
    {
        int dd = tid >> 2, h4 = (tid & 3) * 4;
        float4 v = *reinterpret_cast<const float4*>(
            &src[((size_t)(l * NMC + m) * Dd + d0 + dd) * Hh + h4]);
        t[dd][h4] = v.x; t[dd][h4 + 1] = v.y; t[dd][h4 + 2] = v.z; t[dd][h4 + 3] = v.w;
    }
    __syncthreads();
    int h = tid >> 4, cq = tid & 15;
    size_t rowo = (size_t)l * M1 + (size_t)(m * 16 + h) * Dd + d0 + cq * 4;
    #pragma unroll
    for (int j = 0; j < 4; j++) {
        bf16 hb, lb; split1(t[cq * 4 + j][h], &hb, &lb);
        hi[rowo + j] = hb; lo[rowo + j] = lb;
    }
}

__global__ void convact_all(const float* __restrict__ Wlat, const float* __restrict__ x,
                            bf16* __restrict__ s1h, bf16* __restrict__ s1l,
                            bf16* __restrict__ a1h, bf16* __restrict__ a1l) {
    size_t idx = (size_t)blockIdx.x * blockDim.x + threadIdx.x;   // float4 index
    const size_t n1 = (size_t)6 * M1 / 4;
    const float* src; bf16 *hi, *lo; size_t i;
    if (idx < n1) { src = Wlat; hi = s1h; lo = s1l; i = idx * 4; }
    else          { src = x;    hi = a1h; lo = a1l; i = (idx - n1) * 4; }
    float4 v = *reinterpret_cast<const float4*>(src + i);
    bf16 hs[4], ls[4];
    split1(v.x, &hs[0], &ls[0]); split1(v.y, &hs[1], &ls[1]);
    split1(v.z, &hs[2], &ls[2]); split1(v.w, &hs[3], &ls[3]);
    *reinterpret_cast<float2*>(hi + i) = *reinterpret_cast<float2*>(hs);
    *reinterpret_cast<float2*>(lo + i) = *reinterpret_cast<float2*>(ls);
}

// Bias combo, deterministic 2-phase
__global__ void bias_part(const float* __restrict__ bin, const float* __restrict__ W,
                          float* __restrict__ bcp) {
    const int l = blockIdx.z;
    const int i0 = blockIdx.y * 128;
    const int j = blockIdx.x * 256 + threadIdx.x;
    const float* Wl = W + (size_t)l * M1;
    const float* bi = bin + (size_t)l * Dd;
    float s = 0.0f;
    #pragma unroll 4
    for (int i = i0; i < i0 + 128; i++) s += bi[i] * Wl[(size_t)i * Dd + j];
    bcp[((size_t)l * 8 + blockIdx.y) * Dd + j] = s;
}
__global__ void bias_reduce(const float* __restrict__ bcp, const float* __restrict__ badd,
                            float* __restrict__ bc) {
    const int l = blockIdx.y;
    const int j = blockIdx.x * 256 + threadIdx.x;
    float s = badd[(size_t)l * Dd + j];
    #pragma unroll
    for (int c = 0; c < 8; c++) s += bcp[((size_t)l * 8 + c) * Dd + j];
    bc[(size_t)l * Dd + j] = s;
}

// ---------------------------------------------------------------------------
// GEMM: C = (ACC ? Cf : 0) + A @ W + bias. Block 128x128, 4 warps, warp 64x64,
// occ 2. B band processed in two 32-wide halves per k-step.
// ---------------------------------------------------------------------------
template <bool ACC, bool WF32, bool WSPLIT>
__global__ __launch_bounds__(128, 2)
void gemm_w(const bf16* __restrict__ Ahi_, const bf16* __restrict__ Alo_,
            const bf16* __restrict__ Whi_, const bf16* __restrict__ Wlo_,
            const float* __restrict__ bias_, float* __restrict__ Cf_,
            bf16* __restrict__ Chi_, bf16* __restrict__ Clo_,
            size_t sA, size_t sW, size_t sB, size_t sC) {
    extern __shared__ char smraw[];
    const int z = blockIdx.z;
    const bf16* Ahi = Ahi_ + (size_t)z * sA;
    const bf16* Alo = Alo_ + (size_t)z * sA;
    const bf16* Whi = Whi_ + (size_t)z * sW;
    const bf16* Wlo = Wlo_ + (size_t)z * sW;
    const float* bias = bias_ + (size_t)z * sB;
    float* Cf = WF32 ? Cf_ + (size_t)z * sC : nullptr;
    bf16* Chi = WSPLIT ? Chi_ + (size_t)z * sC : nullptr;
    bf16* Clo = WSPLIT ? Clo_ + (size_t)z * sC : nullptr;

    const int tid = threadIdx.x, wid = tid >> 5, lane = tid & 31;
    const int wm = wid >> 1, wn = wid & 1;
    const int m0 = blockIdx.y * 128, n0 = blockIdx.x * 128;

    wmma::fragment<wmma::accumulator, 16, 16, 16, float> acc[4][4];
    #pragma unroll
    for (int i = 0; i < 4; i++)
        #pragma unroll
        for (int j = 0; j < 4; j++)
            wmma::fill_fragment(acc[i][j], 0.0f);

    auto load_stage = [&](int st, int kt) {
        bf16* Ah = reinterpret_cast<bf16*>(smraw + st * GSTGB);
        bf16* Al = Ah + 128 * LDK;
        bf16* Bh = Al + 128 * LDK;
        bf16* Bl = Bh + 128 * LDK;
        const int k0 = kt * BK;
        #pragma unroll
        for (int t = 0; t < 4; t++) {
            int item = tid + t * 128;
            int r = item >> 2, c = (item & 3) * 8;
            size_t ga = (size_t)(m0 + r) * Dd + k0 + c;
            size_t gb = (size_t)(n0 + r) * Dd + k0 + c;
            cp16(Ah + r * LDK + c, Ahi + ga);
            cp16(Al + r * LDK + c, Alo + ga);
            cp16(Bh + r * LDK + c, Whi + gb);
            cp16(Bl + r * LDK + c, Wlo + gb);
        }
        cp_commit();
    };

    load_stage(0, 0);
    for (int kt = 0; kt < NKT; kt++) {
        int st = kt & 1;
        if (kt + 1 < NKT) { load_stage(st ^ 1, kt + 1); cp_wait<1>(); }
        else              { cp_wait<0>(); }
        __syncthreads();

        bf16* Ah = reinterpret_cast<bf16*>(smraw + st * GSTGB);
        bf16* Al = Ah + 128 * LDK;
        bf16* Bh = Al + 128 * LDK;
        bf16* Bl = Bh + 128 * LDK;
        #pragma unroll
        for (int ks = 0; ks < BK; ks += 16) {
            #pragma unroll
            for (int jh = 0; jh < 2; jh++) {
                wmma::fragment<wmma::matrix_b, 16, 16, 16, bf16, wmma::col_major> bh[2], bl[2];
                #pragma unroll
                for (int j = 0; j < 2; j++) {
                    int nb = (wn * 64 + (jh * 2 + j) * 16) * LDK + ks;
                    wmma::load_matrix_sync(bh[j], &Bh[nb], LDK);
                    wmma::load_matrix_sync(bl[j], &Bl[nb], LDK);
                }
                #pragma unroll
                for (int i = 0; i < 4; i++) {
                    wmma::fragment<wmma::matrix_a, 16, 16, 16, bf16, wmma::row_major> ah, al;
                    wmma::load_matrix_sync(ah, &Ah[(wm * 64 + i * 16) * LDK + ks], LDK);
                    wmma::load_matrix_sync(al, &Al[(wm * 64 + i * 16) * LDK + ks], LDK);
                    #pragma unroll
                    for (int j = 0; j < 2; j++)
                        wmma::mma_sync(acc[i][jh * 2 + j], ah, bh[j], acc[i][jh * 2 + j]);
                    #pragma unroll
                    for (int j = 0; j < 2; j++)
                        wmma::mma_sync(acc[i][jh * 2 + j], ah, bl[j], acc[i][jh * 2 + j]);
                    #pragma unroll
                    for (int j = 0; j < 2; j++)
                        wmma::mma_sync(acc[i][jh * 2 + j], al, bh[j], acc[i][jh * 2 + j]);
                }
            }
        }
        __syncthreads();
    }

    __syncthreads();
    float* patch = reinterpret_cast<float*>(smraw) + wid * 16 * 20;
    const int er = lane >> 1, eh = (lane & 1) * 8;
    #pragma unroll
    for (int i = 0; i < 4; i++) {
        #pragma unroll
        for (int j = 0; j < 4; j++) {
            wmma::store_matrix_sync(patch, acc[i][j], 20, wmma::mem_row_major);
            __syncwarp();
            int gr = m0 + wm * 64 + i * 16 + er;
            int gc = n0 + wn * 64 + j * 16 + eh;
            size_t go = (size_t)gr * Dd + gc;
            float4 b0 = *reinterpret_cast<const float4*>(&bias[gc]);
            float4 b1 = *reinterpret_cast<const float4*>(&bias[gc + 4]);
            float v[8];
            #pragma unroll
            for (int e = 0; e < 8; e++) v[e] = patch[er * 20 + eh + e];
            v[0] += b0.x; v[1] += b0.y; v[2] += b0.z; v[3] += b0.w;
            v[4] += b1.x; v[5] += b1.y; v[6] += b1.z; v[7] += b1.w;
            if (ACC) {
                float4 o0 = *reinterpret_cast<const float4*>(&Cf[go]);
                float4 o1 = *reinterpret_cast<const float4*>(&Cf[go + 4]);
                v[0] += o0.x; v[1] += o0.y; v[2] += o0.z; v[3] += o0.w;
                v[4] += o1.x; v[5] += o1.y; v[6] += o1.z; v[7] += o1.w;
            }
            if (WF32) {
                *reinterpret_cast<float4*>(&Cf[go])     = *reinterpret_cast<float4*>(&v[0]);
                *reinterpret_cast<float4*>(&Cf[go + 4]) = *reinterpret_cast<float4*>(&v[4]);
            }
            if (WSPLIT) {
                bf16 hs[8], ls[8];
                #pragma unroll
                for (int e = 0; e < 8; e++) split1(v[e], &hs[e], &ls[e]);
                *reinterpret_cast<float4*>(&Chi[go]) = *reinterpret_cast<float4*>(hs);
                *reinterpret_cast<float4*>(&Clo[go]) = *reinterpret_cast<float4*>(ls);
            }
            __syncwarp();
        }
    }
}

// ---------------------------------------------------------------------------
// Fused minicolumn kernel: block 128x64, 4 warps, warp 64x32, occ 2.
// exc: full 3-pass split; inh: SINGLE bf16 pass (precision-tolerant pathway:
// lat = relu(inh)@Wl is ~0.03sigma vs mc ~0.26sigma -> inh error attenuated ~9x).
// ---------------------------------------------------------------------------
__global__ __launch_bounds__(128, 2)
void fused_w(const bf16* __restrict__ Ahi, const bf16* __restrict__ Alo,
             const bf16* __restrict__ Weh, const bf16* __restrict__ Wel,
             const bf16* __restrict__ Wih,
             const float* __restrict__ be_l, const float* __restrict__ bi_l,
             const float* __restrict__ Wl_l, const float* __restrict__ bl_l,
             bf16* __restrict__ Mhi, bf16* __restrict__ Mlo) {
    extern __shared__ char smraw[];
    __shared__ float swl[1024];
    __shared__ float sbe[64], sbi[64], sbl[64];

    const int tid = threadIdx.x, wid = tid >> 5, lane = tid & 31;
    const int wm = wid >> 1, wn = wid & 1;
    const int m0 = blockIdx.y * 128, n0 = blockIdx.x * 64;

    for (int i = tid; i < 256; i += 128)
        *reinterpret_cast<float4*>(&swl[i * 4]) =
            *reinterpret_cast<const float4*>(&Wl_l[(size_t)n0 * Hh + i * 4]);
    if (tid < 64) {
        sbe[tid] = be_l[n0 + tid];
        sbi[tid] = bi_l[n0 + tid];
        sbl[tid] = bl_l[n0 + tid];
    }

    wmma::fragment<wmma::accumulator, 16, 16, 16, float> ae[4][2], ai[4][2];
    #pragma unroll
    for (int i = 0; i < 4; i++)
        #pragma unroll
        for (int j = 0; j < 2; j++) {
            wmma::fill_fragment(ae[i][j], 0.0f);
            wmma::fill_fragment(ai[i][j], 0.0f);
        }

    auto load_stage = [&](int st, int kt) {
        bf16* Ah = reinterpret_cast<bf16*>(smraw + st * FSTGB);
        bf16* Al = Ah + 128 * LDK;
        bf16* Eh = Al + 128 * LDK;
        bf16* El = Eh + 64 * LDK;
        bf16* Ih = El + 64 * LDK;
        const int k0 = kt * BK;
        #pragma unroll
        for (int t = 0; t < 4; t++) {
            int item = tid + t * 128;
            int r = item >> 2, c = (item & 3) * 8;
            size_t ga = (size_t)(m0 + r) * Dd + k0 + c;
            cp16(Ah + r * LDK + c, Ahi + ga);
            cp16(Al + r * LDK + c, Alo + ga);
        }
        #pragma unroll
        for (int t = 0; t < 2; t++) {
            int item = tid + t * 128;
            int r = item >> 2, c = (item & 3) * 8;
            size_t gb = (size_t)(n0 + r) * Dd + k0 + c;
            cp16(Eh + r * LDK + c, Weh + gb);
            cp16(El + r * LDK + c, Wel + gb);
            cp16(Ih + r * LDK + c, Wih + gb);
        }
        cp_commit();
    };

    load_stage(0, 0);
    for (int kt = 0; kt < NKT; kt++) {
        int st = kt & 1;
        if (kt + 1 < NKT) { load_stage(st ^ 1, kt + 1); cp_wait<1>(); }
        else              { cp_wait<0>(); }
        __syncthreads();

        bf16* Ah = reinterpret_cast<bf16*>(smraw + st * FSTGB);
        bf16* Al = Ah + 128 * LDK;
        bf16* Eh = Al + 128 * LDK;
        bf16* El = Eh + 64 * LDK;
        bf16* Ih = El + 64 * LDK;
        #pragma unroll
        for (int ks = 0; ks < BK; ks += 16) {
            // exc half: full 3-pass split
            {
                wmma::fragment<wmma::matrix_b, 16, 16, 16, bf16, wmma::col_major> xh[2], xl[2];
                #pragma unroll
                for (int j = 0; j < 2; j++) {
                    int nb = (wn * 32 + j * 16) * LDK + ks;
                    wmma::load_matrix_sync(xh[j], &Eh[nb], LDK);
                    wmma::load_matrix_sync(xl[j], &El[nb], LDK);
                }
                #pragma unroll
                for (int i = 0; i < 4; i++) {
                    wmma::fragment<wmma::matrix_a, 16, 16, 16, bf16, wmma::row_major> ah, al;
                    wmma::load_matrix_sync(ah, &Ah[(wm * 64 + i * 16) * LDK + ks], LDK);
                    wmma::load_matrix_sync(al, &Al[(wm * 64 + i * 16) * LDK + ks], LDK);
                    #pragma unroll
                    for (int j = 0; j < 2; j++) wmma::mma_sync(ae[i][j], ah, xh[j], ae[i][j]);
                    #pragma unroll
                    for (int j = 0; j < 2; j++) wmma::mma_sync(ae[i][j], ah, xl[j], ae[i][j]);
                    #pragma unroll
                    for (int j = 0; j < 2; j++) wmma::mma_sync(ae[i][j], al, xh[j], ae[i][j]);
                }
            }
            // inh half: single bf16 pass (hi x hi only)
            {
                wmma::fragment<wmma::matrix_b, 16, 16, 16, bf16, wmma::col_major> xh[2];
                #pragma unroll
                for (int j = 0; j < 2; j++) {
                    int nb = (wn * 32 + j * 16) * LDK + ks;
                    wmma::load_matrix_sync(xh[j], &Ih[nb], LDK);
                }
                #pragma unroll
                for (int i = 0; i < 4; i++) {
                    wmma::fragment<wmma::matrix_a, 16, 16, 16, bf16, wmma::row_major> ah;
                    wmma::load_matrix_sync(ah, &Ah[(wm * 64 + i * 16) * LDK + ks], LDK);
                    #pragma unroll
                    for (int j = 0; j < 2; j++) wmma::mma_sync(ai[i][j], ah, xh[j], ai[i][j]);
                }
            }
        }
        __syncthreads();
    }

    __syncthreads();
    float* pe = reinterpret_cast<float*>(smraw) + wid * 2 * 16 * 20;
    float* pi = pe + 16 * 20;
    const int er = lane >> 1, eh8 = (lane & 1) * 8;
    #pragma unroll
    for (int i = 0; i < 4; i++) {
        #pragma unroll
        for (int j = 0; j < 2; j++) {
            wmma::store_matrix_sync(pe, ae[i][j], 20, wmma::mem_row_major);
            wmma::store_matrix_sync(pi, ai[i][j], 20, wmma::mem_row_major);
            __syncwarp();
            int ml = wn * 2 + j;
            int gr = m0 + wm * 64 + i * 16 + er;
            float ihv[16];
            #pragma unroll
            for (int h = 0; h < 16; h++)
                ihv[h] = fmaxf(pi[er * 20 + h] + sbi[ml * 16 + h], 0.0f);
            bf16 hs[8], ls[8];
            #pragma unroll
            for (int e = 0; e < 8; e++) {
                int k = eh8 + e;
                float lat = sbl[ml * 16 + k];
                #pragma unroll
                for (int h = 0; h < 16; h++)
                    lat += ihv[h] * swl[ml * 256 + h * 16 + k];
                float ex = fmaxf(pe[er * 20 + k] + sbe[ml * 16 + k], 0.0f);
                split1(fmaxf(ex - lat, 0.0f), &hs[e], &ls[e]);
            }
            size_t go = (size_t)gr * Dd + n0 + ml * 16 + eh8;
            *reinterpret_cast<float4*>(&Mhi[go]) = *reinterpret_cast<float4*>(hs);
            *reinterpret_cast<float4*>(&Mlo[go]) = *reinterpret_cast<float4*>(ls);
            __syncwarp();
        }
    }
}

// ---------------------------------------------------------------------------
// Host orchestration
// ---------------------------------------------------------------------------
extern "C" void kernel_launch(void* const* d_in, const int* in_sizes, int n_in,
                              void* d_out, int out_size) {
    const float* x    = (const float*)d_in[0];
    const float* We   = (const float*)d_in[1];
    const float* be   = (const float*)d_in[2];
    const float* Wi   = (const float*)d_in[3];
    const float* bi   = (const float*)d_in[4];
    const float* Wl   = (const float*)d_in[5];
    const float* bl   = (const float*)d_in[6];
    const float* Wlat = (const float*)d_in[7];
    const float* blat = (const float*)d_in[8];
    const float* Wv   = (const float*)d_in[9];
    const float* bv   = (const float*)d_in[10];
    const float* Wo   = (const float*)d_in[11];
    const float* bo   = (const float*)d_in[12];
    const float* fbW  = (const float*)d_in[13];
    const float* fbb  = (const float*)d_in[14];
    float* out = (float*)d_out;

    bf16 *wc_h, *wc_l, *wv_h, *wv_l, *wo_h, *wo_l, *fb_h, *fb_l;
    bf16 *we_h, *we_l, *wi_h, *wi_l, *a0h, *a0l, *a1h, *a1l;
    bf16 *s1h, *s1l, *s2h, *s2l;
    float *t2, *bc1, *bc2, *bcp, *zero;
    cudaGetSymbolAddress((void**)&wc_h, g_wc_h);
    cudaGetSymbolAddress((void**)&wc_l, g_wc_l);
    cudaGetSymbolAddress((void**)&wv_h, g_wv_h);
    cudaGetSymbolAddress((void**)&wv_l, g_wv_l);
    cudaGetSymbolAddress((void**)&wo_h, g_wo_h);
    cudaGetSymbolAddress((void**)&wo_l, g_wo_l);
    cudaGetSymbolAddress((void**)&fb_h, g_fb_h);
    cudaGetSymbolAddress((void**)&fb_l, g_fb_l);
    cudaGetSymbolAddress((void**)&we_h, g_we_h);
    cudaGetSymbolAddress((void**)&we_l, g_we_l);
    cudaGetSymbolAddress((void**)&wi_h, g_wi_h);
    cudaGetSymbolAddress((void**)&wi_l, g_wi_l);
    cudaGetSymbolAddress((void**)&a0h,  g_a0h);
    cudaGetSymbolAddress((void**)&a0l,  g_a0l);
    cudaGetSymbolAddress((void**)&a1h,  g_a1h);
    cudaGetSymbolAddress((void**)&a1l,  g_a1l);
    cudaGetSymbolAddress((void**)&s1h,  g_s1h);
    cudaGetSymbolAddress((void**)&s1l,  g_s1l);
    cudaGetSymbolAddress((void**)&s2h,  g_s2h);
    cudaGetSymbolAddress((void**)&s2l,  g_s2l);
    cudaGetSymbolAddress((void**)&t2,   g_t2);
    cudaGetSymbolAddress((void**)&bc1,  g_bc1);
    cudaGetSymbolAddress((void**)&bc2,  g_bc2);
    cudaGetSymbolAddress((void**)&bcp,  g_bcp);
    cudaGetSymbolAddress((void**)&zero, g_zero);

    cudaFuncSetAttribute(gemm_w<false, false, true>, cudaFuncAttributeMaxDynamicSharedMemorySize, GDSM);
    cudaFuncSetAttribute(gemm_w<false, true, false>, cudaFuncAttributeMaxDynamicSharedMemorySize, GDSM);
    cudaFuncSetAttribute(gemm_w<false, true, true>,  cudaFuncAttributeMaxDynamicSharedMemorySize, GDSM);
    cudaFuncSetAttribute(gemm_w<true, true, true>,   cudaFuncAttributeMaxDynamicSharedMemorySize, GDSM);
    cudaFuncSetAttribute(fused_w,                    cudaFuncAttributeMaxDynamicSharedMemorySize, FDSM);

    // --- One-time conversions (launches 0-2) ---
    convT_all<<<dim3(32, 32, 17), 256>>>(Wv, Wo, fbW, wv_h, wv_l, wo_h, wo_l, fb_h, fb_l);
    convgT_all<<<dim3(16, 64, 12), 256>>>(We, Wi, we_h, we_l, wi_h, wi_l);
    convact_all<<<(int)(6 * M1 / 4 / 256 + BD / 4 / 256), 256>>>(Wlat, x, s1h, s1l, a1h, a1l);

    // --- Combo weight precompute (launches 3-4) ---
    dim3 gridC(8, 8, 6);
    gemm_w<false, false, true><<<gridC, 128, GDSM>>>(s1h, s1l, wv_h, wv_l,
        zero, nullptr, s2h, s2l, M1, M1, 0, M1);
    gemm_w<false, true, false><<<gridC, 128, GDSM>>>(s2h, s2l, wo_h, wo_l,
        zero, t2, nullptr, nullptr, M1, M1, 0, M1);

    const size_t WL_STRIDE = (size_t)NMC * Hh * Hh;
    dim3 gridG(Dd / 128, Bsz / 128, 1);   // 8 x 128
    dim3 gridF(Dd / 64,  Bsz / 128);      // 16 x 128

    // Launch 5 = fused_w l0 (ncu -s 5 target)
    fused_w<<<gridF, 128, FDSM>>>(a1h, a1l,
        we_h, we_l, wi_h,
        be, bi, Wl, bl, a0h, a0l);

    conv_T<<<dim3(32, 32, 6), 256>>>(t2, wc_h, wc_l);
    bias_part<<<dim3(4, 8, 6), 256>>>(blat, Wv, bcp);
    bias_reduce<<<dim3(4, 6), 256>>>(bcp, bv, bc1);
    bias_part<<<dim3(4, 8, 6), 256>>>(bc1, Wo, bcp);
    bias_reduce<<<dim3(4, 6), 256>>>(bcp, bo, bc2);

    for (int l = 0; l < Lc; l++) {
        if (l > 0) {
            fused_w<<<gridF, 128, FDSM>>>(a1h, a1l,
                we_h + (size_t)l * M1, we_l + (size_t)l * M1,
                wi_h + (size_t)l * M1,
                be + l * Dd, bi + l * Dd, Wl + l * WL_STRIDE, bl + l * Dd,
                a0h, a0l);
        }
        gemm_w<false, true, true><<<gridG, 128, GDSM>>>(a0h, a0l,
            wc_h + (size_t)l * M1, wc_l + (size_t)l * M1,
            bc2 + (size_t)l * Dd, out + (size_t)l * BD, a1h, a1l,
            0, 0, 0, 0);
    }

    int p = 1;
    for (int i = 0; i < Lc - 1; i++) {
        int idx = Lc - 2 - i;
        bf16* sh = p ? a1h : a0h;
        bf16* sl = p ? a1l : a0l;
        bf16* dh = p ? a0h : a1h;
        bf16* dl = p ? a0l : a1l;
        gemm_w<true, true, true><<<gridG, 128, GDSM>>>(sh, sl,
            fb_h + (size_t)i * M1, fb_l + (size_t)i * M1,
            fbb + i * Dd, out + (size_t)idx * BD, dh, dl,
            0, 0, 0, 0);
        p ^= 1;
    }
}

// round 13
// speedup vs baseline: 1.8574x; 1.4914x over previous
#include <cuda_runtime.h>
#include <cuda_fp16.h>
#include <mma.h>
#include <cstdint>

using namespace nvcuda;
typedef __half hlf;

// Problem constants
#define Bsz 16384
#define Dd  1024
#define Lc  6
#define NMC 64
#define Hh  16
#define M1  (1024 * 1024)
#define BD  ((size_t)Bsz * Dd)

// Tiling: block 128x128 (generic) / 128x64 (fused), 4 warps, occ 2, 2-stage
#define BK   32
#define LDK  40
#define NKT  (Dd / BK)
#define GPSTGB (4 * 128 * LDK * 2)        // pre (3-pass): A hi/lo + B hi/lo = 40960
#define GPDSM  (2 * GPSTGB)
#define G2STGB (3 * 128 * LDK * 2)        // 2-pass: A + Bh + Bl = 30720
#define G2DSM  (2 * G2STGB)
#define F2STGB ((128 + 3 * 64) * LDK * 2) // fused: A + Eh + El + Ih = 25600
#define F2DSM  (2 * F2STGB)

// ---------------------------------------------------------------------------
// Persistent buffers (weights split fp16 hi/lo; activations single fp16)
// ---------------------------------------------------------------------------
__device__ hlf g_wc_h [6 * M1], g_wc_l [6 * M1];   // combo weights, [n][k]
__device__ hlf g_wv_h [6 * M1], g_wv_l [6 * M1];
__device__ hlf g_wo_h [6 * M1], g_wo_l [6 * M1];
__device__ hlf g_fb_h [5 * M1], g_fb_l [5 * M1];
__device__ hlf g_we_h [6 * M1], g_we_l [6 * M1];   // gathered [n=m*16+h][k=d]
__device__ hlf g_wi_h [6 * M1], g_wi_l [6 * M1];   // wi_l written, unused
__device__ hlf g_s1h[6 * M1], g_s1l[6 * M1];
__device__ hlf g_s2h[6 * M1], g_s2l[6 * M1];
__device__ float g_t2[6 * M1];
__device__ float g_bc1[6 * Dd], g_bc2[6 * Dd];
__device__ float g_bcp[6 * 8 * Dd];
__device__ float g_zero[Dd];
__device__ hlf g_a0[BD], g_a1[BD];                 // single fp16 activations

__device__ __forceinline__ void split1(float v, hlf* h, hlf* l) {
    hlf hh = __float2half_rn(v);
    *h = hh;
    *l = __float2half_rn(v - __half2float(hh));
}

__device__ __forceinline__ void cp16(void* smem, const void* g) {
    uint32_t s = (uint32_t)__cvta_generic_to_shared(smem);
    asm volatile("cp.async.cg.shared.global [%0], [%1], 16;" :: "r"(s), "l"(g));
}
__device__ __forceinline__ void cp_commit() { asm volatile("cp.async.commit_group;"); }
template <int N>
__device__ __forceinline__ void cp_wait() {
    asm volatile("cp.async.wait_group %0;" :: "n"(N));
}

// ---------------------------------------------------------------------------
// Conversion kernels
// ---------------------------------------------------------------------------
__device__ __forceinline__ void convT_body(const float* S, hlf* H, hlf* L,
                                           int k0, int n0, int tid) {
    __shared__ float t[32][33];
    const int r = tid >> 5, c = tid & 31;
    #pragma unroll
    for (int i = 0; i < 4; i++)
        t[r + i * 8][c] = S[(size_t)(k0 + r + i * 8) * Dd + n0 + c];
    __syncthreads();
    #pragma unroll
    for (int i = 0; i < 4; i++) {
        hlf hb, lb; split1(t[c][r + i * 8], &hb, &lb);
        size_t o = (size_t)(n0 + r + i * 8) * Dd + k0 + c;
        H[o] = hb; L[o] = lb;
    }
}

__global__ void convT_all(const float* __restrict__ Wv, const float* __restrict__ Wo,
                          const float* __restrict__ fbW,
                          hlf* __restrict__ wvh, hlf* __restrict__ wvl,
                          hlf* __restrict__ woh, hlf* __restrict__ wol,
                          hlf* __restrict__ fbh, hlf* __restrict__ fbl) {
    const int z = blockIdx.z;
    const float* S; hlf *H, *L;
    if (z < 6)       { S = Wv  + (size_t)z * M1;        H = wvh + (size_t)z * M1;        L = wvl + (size_t)z * M1; }
    else if (z < 12) { S = Wo  + (size_t)(z - 6) * M1;  H = woh + (size_t)(z - 6) * M1;  L = wol + (size_t)(z - 6) * M1; }
    else             { S = fbW + (size_t)(z - 12) * M1; H = fbh + (size_t)(z - 12) * M1; L = fbl + (size_t)(z - 12) * M1; }
    convT_body(S, H, L, blockIdx.y * 32, blockIdx.x * 32, threadIdx.x);
}

__global__ void conv_T(const float* __restrict__ src, hlf* __restrict__ hi,
                       hlf* __restrict__ lo) {
    const int l = blockIdx.z;
    convT_body(src + (size_t)l * M1, hi + (size_t)l * M1, lo + (size_t)l * M1,
               blockIdx.y * 32, blockIdx.x * 32, threadIdx.x);
}

__global__ void convgT_all(const float* __restrict__ We, const float* __restrict__ Wi,
                           hlf* __restrict__ weh, hlf* __restrict__ wel,
                           hlf* __restrict__ wih, hlf* __restrict__ wil) {
    __shared__ float t[64][17];
    const int z = blockIdx.z;
    const int l = (z < 6) ? z : z - 6;
    const float* src = (z < 6) ? We : Wi;
    hlf* hi = (z < 6) ? weh : wih;
    hlf* lo = (z < 6) ? wel : wil;
    const int d0 = blockIdx.x * 64, m = blockIdx.y;
    const int tid = threadIdx.x;
    {
        int dd = tid >> 2, h4 = (tid & 3) * 4;
        float4 v = *reinterpret_cast<const float4*>(
            &src[((size_t)(l * NMC + m) * Dd + d0 + dd) * Hh + h4]);
        t[dd][h4] = v.x; t[dd][h4 + 1] = v.y; t[dd][h4 + 2] = v.z; t[dd][h4 + 3] = v.w;
    }
    __syncthreads();
    int h = tid >> 4, cq = tid & 15;
    size_t rowo = (size_t)l * M1 + (size_t)(m * 16 + h) * Dd + d0 + cq * 4;
    #pragma unroll
    for (int j = 0; j < 4; j++) {
        hlf hb, lb; split1(t[cq * 4 + j][h], &hb, &lb);
        hi[rowo + j] = hb; lo[rowo + j] = lb;
    }
}

// Wlat (split, for precompute) + x (single fp16 activation) in one launch
__global__ void convact_all(const float* __restrict__ Wlat, const float* __restrict__ x,
                            hlf* __restrict__ s1h, hlf* __restrict__ s1l,
                            hlf* __restrict__ a1) {
    size_t idx = (size_t)blockIdx.x * blockDim.x + threadIdx.x;   // float4 index
    const size_t n1 = (size_t)6 * M1 / 4;
    if (idx < n1) {
        size_t i = idx * 4;
        float4 v = *reinterpret_cast<const float4*>(Wlat + i);
        hlf hs[4], ls[4];
        split1(v.x, &hs[0], &ls[0]); split1(v.y, &hs[1], &ls[1]);
        split1(v.z, &hs[2], &ls[2]); split1(v.w, &hs[3], &ls[3]);
        *reinterpret_cast<float2*>(s1h + i) = *reinterpret_cast<float2*>(hs);
        *reinterpret_cast<float2*>(s1l + i) = *reinterpret_cast<float2*>(ls);
    } else {
        size_t i = (idx - n1) * 4;
        float4 v = *reinterpret_cast<const float4*>(x + i);
        hlf hs[4];
        hs[0] = __float2half_rn(v.x); hs[1] = __float2half_rn(v.y);
        hs[2] = __float2half_rn(v.z); hs[3] = __float2half_rn(v.w);
        *reinterpret_cast<float2*>(a1 + i) = *reinterpret_cast<float2*>(hs);
    }
}

// Bias combo, deterministic 2-phase
__global__ void bias_part(const float* __restrict__ bin, const float* __restrict__ W,
                          float* __restrict__ bcp) {
    const int l = blockIdx.z;
    const int i0 = blockIdx.y * 128;
    const int j = blockIdx.x * 256 + threadIdx.x;
    const float* Wl = W + (size_t)l * M1;
    const float* bi = bin + (size_t)l * Dd;
    float s = 0.0f;
    #pragma unroll 4
    for (int i = i0; i < i0 + 128; i++) s += bi[i] * Wl[(size_t)i * Dd + j];
    bcp[((size_t)l * 8 + blockIdx.y) * Dd + j] = s;
}
__global__ void bias_reduce(const float* __restrict__ bcp, const float* __restrict__ badd,
                            float* __restrict__ bc) {
    const int l = blockIdx.y;
    const int j = blockIdx.x * 256 + threadIdx.x;
    float s = badd[(size_t)l * Dd + j];
    #pragma unroll
    for (int c = 0; c < 8; c++) s += bcp[((size_t)l * 8 + c) * Dd + j];
    bc[(size_t)l * Dd + j] = s;
}

// ---------------------------------------------------------------------------
// gemm_pre: full 3-pass split GEMM (combo precompute only, 1/16 scale).
// ---------------------------------------------------------------------------
template <bool WF32, bool WSPLIT>
__global__ __launch_bounds__(128, 2)
void gemm_pre(const hlf* __restrict__ Ahi_, const hlf* __restrict__ Alo_,
              const hlf* __restrict__ Whi_, const hlf* __restrict__ Wlo_,
              const float* __restrict__ bias_, float* __restrict__ Cf_,
              hlf* __restrict__ Chi_, hlf* __restrict__ Clo_,
              size_t sA, size_t sW, size_t sB, size_t sC) {
    extern __shared__ char smraw[];
    const int z = blockIdx.z;
    const hlf* Ahi = Ahi_ + (size_t)z * sA;
    const hlf* Alo = Alo_ + (size_t)z * sA;
    const hlf* Whi = Whi_ + (size_t)z * sW;
    const hlf* Wlo = Wlo_ + (size_t)z * sW;
    const float* bias = bias_ + (size_t)z * sB;
    float* Cf = WF32 ? Cf_ + (size_t)z * sC : nullptr;
    hlf* Chi = WSPLIT ? Chi_ + (size_t)z * sC : nullptr;
    hlf* Clo = WSPLIT ? Clo_ + (size_t)z * sC : nullptr;

    const int tid = threadIdx.x, wid = tid >> 5, lane = tid & 31;
    const int wm = wid >> 1, wn = wid & 1;
    const int m0 = blockIdx.y * 128, n0 = blockIdx.x * 128;

    wmma::fragment<wmma::accumulator, 16, 16, 16, float> acc[4][4];
    #pragma unroll
    for (int i = 0; i < 4; i++)
        #pragma unroll
        for (int j = 0; j < 4; j++)
            wmma::fill_fragment(acc[i][j], 0.0f);

    auto load_stage = [&](int st, int kt) {
        hlf* Ah = reinterpret_cast<hlf*>(smraw + st * GPSTGB);
        hlf* Al = Ah + 128 * LDK;
        hlf* Bh = Al + 128 * LDK;
        hlf* Bl = Bh + 128 * LDK;
        const int k0 = kt * BK;
        #pragma unroll
        for (int t = 0; t < 4; t++) {
            int item = tid + t * 128;
            int r = item >> 2, c = (item & 3) * 8;
            size_t ga = (size_t)(m0 + r) * Dd + k0 + c;
            size_t gb = (size_t)(n0 + r) * Dd + k0 + c;
            cp16(Ah + r * LDK + c, Ahi + ga);
            cp16(Al + r * LDK + c, Alo + ga);
            cp16(Bh + r * LDK + c, Whi + gb);
            cp16(Bl + r * LDK + c, Wlo + gb);
        }
        cp_commit();
    };

    load_stage(0, 0);
    for (int kt = 0; kt < NKT; kt++) {
        int st = kt & 1;
        if (kt + 1 < NKT) { load_stage(st ^ 1, kt + 1); cp_wait<1>(); }
        else              { cp_wait<0>(); }
        __syncthreads();

        hlf* Ah = reinterpret_cast<hlf*>(smraw + st * GPSTGB);
        hlf* Al = Ah + 128 * LDK;
        hlf* Bh = Al + 128 * LDK;
        hlf* Bl = Bh + 128 * LDK;
        #pragma unroll
        for (int ks = 0; ks < BK; ks += 16) {
            #pragma unroll
            for (int jh = 0; jh < 2; jh++) {
                wmma::fragment<wmma::matrix_b, 16, 16, 16, hlf, wmma::col_major> bh[2], bl[2];
                #pragma unroll
                for (int j = 0; j < 2; j++) {
                    int nb = (wn * 64 + (jh * 2 + j) * 16) * LDK + ks;
                    wmma::load_matrix_sync(bh[j], &Bh[nb], LDK);
                    wmma::load_matrix_sync(bl[j], &Bl[nb], LDK);
                }
                #pragma unroll
                for (int i = 0; i < 4; i++) {
                    wmma::fragment<wmma::matrix_a, 16, 16, 16, hlf, wmma::row_major> ah, al;
                    wmma::load_matrix_sync(ah, &Ah[(wm * 64 + i * 16) * LDK + ks], LDK);
                    wmma::load_matrix_sync(al, &Al[(wm * 64 + i * 16) * LDK + ks], LDK);
                    #pragma unroll
                    for (int j = 0; j < 2; j++)
                        wmma::mma_sync(acc[i][jh * 2 + j], ah, bh[j], acc[i][jh * 2 + j]);
                    #pragma unroll
                    for (int j = 0; j < 2; j++)
                        wmma::mma_sync(acc[i][jh * 2 + j], ah, bl[j], acc[i][jh * 2 + j]);
                    #pragma unroll
                    for (int j = 0; j < 2; j++)
                        wmma::mma_sync(acc[i][jh * 2 + j], al, bh[j], acc[i][jh * 2 + j]);
                }
            }
        }
        __syncthreads();
    }

    __syncthreads();
    float* patch = reinterpret_cast<float*>(smraw) + wid * 16 * 20;
    const int er = lane >> 1, eh = (lane & 1) * 8;
    #pragma unroll
    for (int i = 0; i < 4; i++) {
        #pragma unroll
        for (int j = 0; j < 4; j++) {
            wmma::store_matrix_sync(patch, acc[i][j], 20, wmma::mem_row_major);
            __syncwarp();
            int gr = m0 + wm * 64 + i * 16 + er;
            int gc = n0 + wn * 64 + j * 16 + eh;
            size_t go = (size_t)gr * Dd + gc;
            float4 b0 = *reinterpret_cast<const float4*>(&bias[gc]);
            float4 b1 = *reinterpret_cast<const float4*>(&bias[gc + 4]);
            float v[8];
            #pragma unroll
            for (int e = 0; e < 8; e++) v[e] = patch[er * 20 + eh + e];
            v[0] += b0.x; v[1] += b0.y; v[2] += b0.z; v[3] += b0.w;
            v[4] += b1.x; v[5] += b1.y; v[6] += b1.z; v[7] += b1.w;
            if (WF32) {
                *reinterpret_cast<float4*>(&Cf[go])     = *reinterpret_cast<float4*>(&v[0]);
                *reinterpret_cast<float4*>(&Cf[go + 4]) = *reinterpret_cast<float4*>(&v[4]);
            }
            if (WSPLIT) {
                hlf hs[8], ls[8];
                #pragma unroll
                for (int e = 0; e < 8; e++) split1(v[e], &hs[e], &ls[e]);
                *reinterpret_cast<float4*>(&Chi[go]) = *reinterpret_cast<float4*>(hs);
                *reinterpret_cast<float4*>(&Clo[go]) = *reinterpret_cast<float4*>(ls);
            }
            __syncwarp();
        }
    }
}

// ---------------------------------------------------------------------------
// gemm2: 2-pass GEMM. C = (ACC ? Cf : 0) + A @ W + bias.
// A single fp16 [Bsz,Dd] rm; W split hi/lo [n][k] km. Writes fp16 Ch (+fp32 Cf).
// ---------------------------------------------------------------------------
template <bool ACC, bool WF32>
__global__ __launch_bounds__(128, 2)
void gemm2(const hlf* __restrict__ A, const hlf* __restrict__ Whi,
           const hlf* __restrict__ Wlo, const float* __restrict__ bias,
           float* __restrict__ Cf, hlf* __restrict__ Ch) {
    extern __shared__ char smraw[];
    const int tid = threadIdx.x, wid = tid >> 5, lane = tid & 31;
    const int wm = wid >> 1, wn = wid & 1;
    const int m0 = blockIdx.y * 128, n0 = blockIdx.x * 128;

    wmma::fragment<wmma::accumulator, 16, 16, 16, float> acc[4][4];
    #pragma unroll
    for (int i = 0; i < 4; i++)
        #pragma unroll
        for (int j = 0; j < 4; j++)
            wmma::fill_fragment(acc[i][j], 0.0f);

    auto load_stage = [&](int st, int kt) {
        hlf* Ad = reinterpret_cast<hlf*>(smraw + st * G2STGB);
        hlf* Bh = Ad + 128 * LDK;
        hlf* Bl = Bh + 128 * LDK;
        const int k0 = kt * BK;
        #pragma unroll
        for (int t = 0; t < 4; t++) {
            int item = tid + t * 128;
            int r = item >> 2, c = (item & 3) * 8;
            cp16(Ad + r * LDK + c, A + (size_t)(m0 + r) * Dd + k0 + c);
            size_t gb = (size_t)(n0 + r) * Dd + k0 + c;
            cp16(Bh + r * LDK + c, Whi + gb);
            cp16(Bl + r * LDK + c, Wlo + gb);
        }
        cp_commit();
    };

    load_stage(0, 0);
    for (int kt = 0; kt < NKT; kt++) {
        int st = kt & 1;
        if (kt + 1 < NKT) { load_stage(st ^ 1, kt + 1); cp_wait<1>(); }
        else              { cp_wait<0>(); }
        __syncthreads();

        hlf* Ad = reinterpret_cast<hlf*>(smraw + st * G2STGB);
        hlf* Bh = Ad + 128 * LDK;
        hlf* Bl = Bh + 128 * LDK;
        #pragma unroll
        for (int ks = 0; ks < BK; ks += 16) {
            #pragma unroll
            for (int jh = 0; jh < 2; jh++) {
                wmma::fragment<wmma::matrix_b, 16, 16, 16, hlf, wmma::col_major> bh[2], bl[2];
                #pragma unroll
                for (int j = 0; j < 2; j++) {
                    int nb = (wn * 64 + (jh * 2 + j) * 16) * LDK + ks;
                    wmma::load_matrix_sync(bh[j], &Bh[nb], LDK);
                    wmma::load_matrix_sync(bl[j], &Bl[nb], LDK);
                }
                #pragma unroll
                for (int i = 0; i < 4; i++) {
                    wmma::fragment<wmma::matrix_a, 16, 16, 16, hlf, wmma::row_major> ah;
                    wmma::load_matrix_sync(ah, &Ad[(wm * 64 + i * 16) * LDK + ks], LDK);
                    #pragma unroll
                    for (int j = 0; j < 2; j++)
                        wmma::mma_sync(acc[i][jh * 2 + j], ah, bh[j], acc[i][jh * 2 + j]);
                    #pragma unroll
                    for (int j = 0; j < 2; j++)
                        wmma::mma_sync(acc[i][jh * 2 + j], ah, bl[j], acc[i][jh * 2 + j]);
                }
            }
        }
        __syncthreads();
    }

    __syncthreads();
    float* patch = reinterpret_cast<float*>(smraw) + wid * 16 * 20;
    const int er = lane >> 1, eh = (lane & 1) * 8;
    #pragma unroll
    for (int i = 0; i < 4; i++) {
        #pragma unroll
        for (int j = 0; j < 4; j++) {
            wmma::store_matrix_sync(patch, acc[i][j], 20, wmma::mem_row_major);
            __syncwarp();
            int gr = m0 + wm * 64 + i * 16 + er;
            int gc = n0 + wn * 64 + j * 16 + eh;
            size_t go = (size_t)gr * Dd + gc;
            float4 b0 = *reinterpret_cast<const float4*>(&bias[gc]);
            float4 b1 = *reinterpret_cast<const float4*>(&bias[gc + 4]);
            float v[8];
            #pragma unroll
            for (int e = 0; e < 8; e++) v[e] = patch[er * 20 + eh + e];
            v[0] += b0.x; v[1] += b0.y; v[2] += b0.z; v[3] += b0.w;
            v[4] += b1.x; v[5] += b1.y; v[6] += b1.z; v[7] += b1.w;
            if (ACC) {
                float4 o0 = *reinterpret_cast<const float4*>(&Cf[go]);
                float4 o1 = *reinterpret_cast<const float4*>(&Cf[go + 4]);
                v[0] += o0.x; v[1] += o0.y; v[2] += o0.z; v[3] += o0.w;
                v[4] += o1.x; v[5] += o1.y; v[6] += o1.z; v[7] += o1.w;
            }
            if (WF32) {
                *reinterpret_cast<float4*>(&Cf[go])     = *reinterpret_cast<float4*>(&v[0]);
                *reinterpret_cast<float4*>(&Cf[go + 4]) = *reinterpret_cast<float4*>(&v[4]);
            }
            hlf hs[8];
            #pragma unroll
            for (int e = 0; e < 8; e++) hs[e] = __float2half_rn(v[e]);
            *reinterpret_cast<float4*>(&Ch[go]) = *reinterpret_cast<float4*>(hs);
            __syncwarp();
        }
    }
}

// ---------------------------------------------------------------------------
// fused2: block 128x64, 4 warps, warp 64x32. A single fp16.
// exc: 2-pass (We hi+lo); inh: 1-pass (Wi hi). Output single fp16 mc.
// ---------------------------------------------------------------------------
__global__ __launch_bounds__(128, 2)
void fused2(const hlf* __restrict__ A,
            const hlf* __restrict__ Weh, const hlf* __restrict__ Wel,
            const hlf* __restrict__ Wih,
            const float* __restrict__ be_l, const float* __restrict__ bi_l,
            const float* __restrict__ Wl_l, const float* __restrict__ bl_l,
            hlf* __restrict__ Mc) {
    extern __shared__ char smraw[];
    __shared__ float swl[1024];
    __shared__ float sbe[64], sbi[64], sbl[64];

    const int tid = threadIdx.x, wid = tid >> 5, lane = tid & 31;
    const int wm = wid >> 1, wn = wid & 1;
    const int m0 = blockIdx.y * 128, n0 = blockIdx.x * 64;

    for (int i = tid; i < 256; i += 128)
        *reinterpret_cast<float4*>(&swl[i * 4]) =
            *reinterpret_cast<const float4*>(&Wl_l[(size_t)n0 * Hh + i * 4]);
    if (tid < 64) {
        sbe[tid] = be_l[n0 + tid];
        sbi[tid] = bi_l[n0 + tid];
        sbl[tid] = bl_l[n0 + tid];
    }

    wmma::fragment<wmma::accumulator, 16, 16, 16, float> ae[4][2], ai[4][2];
    #pragma unroll
    for (int i = 0; i < 4; i++)
        #pragma unroll
        for (int j = 0; j < 2; j++) {
            wmma::fill_fragment(ae[i][j], 0.0f);
            wmma::fill_fragment(ai[i][j], 0.0f);
        }

    auto load_stage = [&](int st, int kt) {
        hlf* Ad = reinterpret_cast<hlf*>(smraw + st * F2STGB);
        hlf* Eh = Ad + 128 * LDK;
        hlf* El = Eh + 64 * LDK;
        hlf* Ih = El + 64 * LDK;
        const int k0 = kt * BK;
        #pragma unroll
        for (int t = 0; t < 4; t++) {
            int item = tid + t * 128;
            int r = item >> 2, c = (item & 3) * 8;
            cp16(Ad + r * LDK + c, A + (size_t)(m0 + r) * Dd + k0 + c);
        }
        #pragma unroll
        for (int t = 0; t < 2; t++) {
            int item = tid + t * 128;
            int r = item >> 2, c = (item & 3) * 8;
            size_t gb = (size_t)(n0 + r) * Dd + k0 + c;
            cp16(Eh + r * LDK + c, Weh + gb);
            cp16(El + r * LDK + c, Wel + gb);
            cp16(Ih + r * LDK + c, Wih + gb);
        }
        cp_commit();
    };

    load_stage(0, 0);
    for (int kt = 0; kt < NKT; kt++) {
        int st = kt & 1;
        if (kt + 1 < NKT) { load_stage(st ^ 1, kt + 1); cp_wait<1>(); }
        else              { cp_wait<0>(); }
        __syncthreads();

        hlf* Ad = reinterpret_cast<hlf*>(smraw + st * F2STGB);
        hlf* Eh = Ad + 128 * LDK;
        hlf* El = Eh + 64 * LDK;
        hlf* Ih = El + 64 * LDK;
        #pragma unroll
        for (int ks = 0; ks < BK; ks += 16) {
            wmma::fragment<wmma::matrix_b, 16, 16, 16, hlf, wmma::col_major>
                eh[2], el[2], ih[2];
            #pragma unroll
            for (int j = 0; j < 2; j++) {
                int nb = (wn * 32 + j * 16) * LDK + ks;
                wmma::load_matrix_sync(eh[j], &Eh[nb], LDK);
                wmma::load_matrix_sync(el[j], &El[nb], LDK);
                wmma::load_matrix_sync(ih[j], &Ih[nb], LDK);
            }
            #pragma unroll
            for (int i = 0; i < 4; i++) {
                wmma::fragment<wmma::matrix_a, 16, 16, 16, hlf, wmma::row_major> ah;
                wmma::load_matrix_sync(ah, &Ad[(wm * 64 + i * 16) * LDK + ks], LDK);
                #pragma unroll
                for (int j = 0; j < 2; j++) wmma::mma_sync(ae[i][j], ah, eh[j], ae[i][j]);
                #pragma unroll
                for (int j = 0; j < 2; j++) wmma::mma_sync(ai[i][j], ah, ih[j], ai[i][j]);
                #pragma unroll
                for (int j = 0; j < 2; j++) wmma::mma_sync(ae[i][j], ah, el[j], ae[i][j]);
            }
        }
        __syncthreads();
    }

    __syncthreads();
    float* pe = reinterpret_cast<float*>(smraw) + wid * 2 * 16 * 20;
    float* pi = pe + 16 * 20;
    const int er = lane >> 1, eh8 = (lane & 1) * 8;
    #pragma unroll
    for (int i = 0; i < 4; i++) {
        #pragma unroll
        for (int j = 0; j < 2; j++) {
            wmma::store_matrix_sync(pe, ae[i][j], 20, wmma::mem_row_major);
            wmma::store_matrix_sync(pi, ai[i][j], 20, wmma::mem_row_major);
            __syncwarp();
            int ml = wn * 2 + j;
            int gr = m0 + wm * 64 + i * 16 + er;
            float ihv[16];
            #pragma unroll
            for (int h = 0; h < 16; h++)
                ihv[h] = fmaxf(pi[er * 20 + h] + sbi[ml * 16 + h], 0.0f);
            hlf hs[8];
            #pragma unroll
            for (int e = 0; e < 8; e++) {
                int k = eh8 + e;
                float lat = sbl[ml * 16 + k];
                #pragma unroll
                for (int h = 0; h < 16; h++)
                    lat += ihv[h] * swl[ml * 256 + h * 16 + k];
                float ex = fmaxf(pe[er * 20 + k] + sbe[ml * 16 + k], 0.0f);
                hs[e] = __float2half_rn(fmaxf(ex - lat, 0.0f));
            }
            *reinterpret_cast<float4*>(&Mc[(size_t)gr * Dd + n0 + ml * 16 + eh8]) =
                *reinterpret_cast<float4*>(hs);
            __syncwarp();
        }
    }
}

// ---------------------------------------------------------------------------
// Host orchestration
// ---------------------------------------------------------------------------
extern "C" void kernel_launch(void* const* d_in, const int* in_sizes, int n_in,
                              void* d_out, int out_size) {
    const float* x    = (const float*)d_in[0];
    const float* We   = (const float*)d_in[1];
    const float* be   = (const float*)d_in[2];
    const float* Wi   = (const float*)d_in[3];
    const float* bi   = (const float*)d_in[4];
    const float* Wl   = (const float*)d_in[5];
    const float* bl   = (const float*)d_in[6];
    const float* Wlat = (const float*)d_in[7];
    const float* blat = (const float*)d_in[8];
    const float* Wv   = (const float*)d_in[9];
    const float* bv   = (const float*)d_in[10];
    const float* Wo   = (const float*)d_in[11];
    const float* bo   = (const float*)d_in[12];
    const float* fbW  = (const float*)d_in[13];
    const float* fbb  = (const float*)d_in[14];
    float* out = (float*)d_out;

    hlf *wc_h, *wc_l, *wv_h, *wv_l, *wo_h, *wo_l, *fb_h, *fb_l;
    hlf *we_h, *we_l, *wi_h, *wi_l, *a0, *a1;
    hlf *s1h, *s1l, *s2h, *s2l;
    float *t2, *bc1, *bc2, *bcp, *zero;
    cudaGetSymbolAddress((void**)&wc_h, g_wc_h);
    cudaGetSymbolAddress((void**)&wc_l, g_wc_l);
    cudaGetSymbolAddress((void**)&wv_h, g_wv_h);
    cudaGetSymbolAddress((void**)&wv_l, g_wv_l);
    cudaGetSymbolAddress((void**)&wo_h, g_wo_h);
    cudaGetSymbolAddress((void**)&wo_l, g_wo_l);
    cudaGetSymbolAddress((void**)&fb_h, g_fb_h);
    cudaGetSymbolAddress((void**)&fb_l, g_fb_l);
    cudaGetSymbolAddress((void**)&we_h, g_we_h);
    cudaGetSymbolAddress((void**)&we_l, g_we_l);
    cudaGetSymbolAddress((void**)&wi_h, g_wi_h);
    cudaGetSymbolAddress((void**)&wi_l, g_wi_l);
    cudaGetSymbolAddress((void**)&a0,   g_a0);
    cudaGetSymbolAddress((void**)&a1,   g_a1);
    cudaGetSymbolAddress((void**)&s1h,  g_s1h);
    cudaGetSymbolAddress((void**)&s1l,  g_s1l);
    cudaGetSymbolAddress((void**)&s2h,  g_s2h);
    cudaGetSymbolAddress((void**)&s2l,  g_s2l);
    cudaGetSymbolAddress((void**)&t2,   g_t2);
    cudaGetSymbolAddress((void**)&bc1,  g_bc1);
    cudaGetSymbolAddress((void**)&bc2,  g_bc2);
    cudaGetSymbolAddress((void**)&bcp,  g_bcp);
    cudaGetSymbolAddress((void**)&zero, g_zero);

    cudaFuncSetAttribute(gemm_pre<false, true>, cudaFuncAttributeMaxDynamicSharedMemorySize, GPDSM);
    cudaFuncSetAttribute(gemm_pre<true, false>, cudaFuncAttributeMaxDynamicSharedMemorySize, GPDSM);
    cudaFuncSetAttribute(gemm2<false, true>,    cudaFuncAttributeMaxDynamicSharedMemorySize, G2DSM);
    cudaFuncSetAttribute(gemm2<true, true>,     cudaFuncAttributeMaxDynamicSharedMemorySize, G2DSM);
    cudaFuncSetAttribute(fused2,                cudaFuncAttributeMaxDynamicSharedMemorySize, F2DSM);

    // --- One-time conversions (launches 0-2) ---
    convT_all<<<dim3(32, 32, 17), 256>>>(Wv, Wo, fbW, wv_h, wv_l, wo_h, wo_l, fb_h, fb_l);
    convgT_all<<<dim3(16, 64, 12), 256>>>(We, Wi, we_h, we_l, wi_h, wi_l);
    convact_all<<<(int)(6 * M1 / 4 / 256 + BD / 4 / 256), 256>>>(Wlat, x, s1h, s1l, a1);

    // --- Combo weight precompute (launches 3-4, full 3-pass precision) ---
    dim3 gridC(8, 8, 6);
    gemm_pre<false, true><<<gridC, 128, GPDSM>>>(s1h, s1l, wv_h, wv_l,
        zero, nullptr, s2h, s2l, M1, M1, 0, M1);
    gemm_pre<true, false><<<gridC, 128, GPDSM>>>(s2h, s2l, wo_h, wo_l,
        zero, t2, nullptr, nullptr, M1, M1, 0, M1);

    const size_t WL_STRIDE = (size_t)NMC * Hh * Hh;
    dim3 gridG(Dd / 128, Bsz / 128);   // 8 x 128
    dim3 gridF(Dd / 64,  Bsz / 128);   // 16 x 128

    // Launch 5 = fused2 l0 (ncu -s 5 target)
    fused2<<<gridF, 128, F2DSM>>>(a1, we_h, we_l, wi_h,
                                  be, bi, Wl, bl, a0);

    conv_T<<<dim3(32, 32, 6), 256>>>(t2, wc_h, wc_l);
    bias_part<<<dim3(4, 8, 6), 256>>>(blat, Wv, bcp);
    bias_reduce<<<dim3(4, 6), 256>>>(bcp, bv, bc1);
    bias_part<<<dim3(4, 8, 6), 256>>>(bc1, Wo, bcp);
    bias_reduce<<<dim3(4, 6), 256>>>(bcp, bo, bc2);

    for (int l = 0; l < Lc; l++) {
        if (l > 0) {
            fused2<<<gridF, 128, F2DSM>>>(a1,
                we_h + (size_t)l * M1, we_l + (size_t)l * M1,
                wi_h + (size_t)l * M1,
                be + l * Dd, bi + l * Dd, Wl + l * WL_STRIDE, bl + l * Dd,
                a0);
        }
        gemm2<false, true><<<gridG, 128, G2DSM>>>(a0,
            wc_h + (size_t)l * M1, wc_l + (size_t)l * M1,
            bc2 + (size_t)l * Dd, out + (size_t)l * BD, a1);
    }

    int p = 1;
    for (int i = 0; i < Lc - 1; i++) {
        int idx = Lc - 2 - i;
        hlf* src = p ? a1 : a0;
        hlf* dst = p ? a0 : a1;
        gemm2<true, true><<<gridG, 128, G2DSM>>>(src,
            fb_h + (size_t)i * M1, fb_l + (size_t)i * M1,
            fbb + i * Dd, out + (size_t)idx * BD, dst);
        p ^= 1;
    }
}

// round 14
// speedup vs baseline: 2.2275x; 1.1993x over previous
#include <cuda_runtime.h>
#include <cuda_fp16.h>
#include <mma.h>
#include <cstdint>

using namespace nvcuda;
typedef __half hlf;

// Problem constants
#define Bsz 16384
#define Dd  1024
#define Lc  6
#define NMC 64
#define Hh  16
#define M1  (1024 * 1024)
#define BD  ((size_t)Bsz * Dd)

// Tiling: block 128x128 (generic) / 128x64 (fused), 4 warps, occ 2, 2-stage
#define BK   32
#define LDK  40
#define NKT  (Dd / BK)
#define GPSTGB (4 * 128 * LDK * 2)        // pre (3-pass): A hi/lo + B hi/lo = 40960
#define GPDSM  (2 * GPSTGB)
#define G1STGB (2 * 128 * LDK * 2)        // 1-pass: A + B = 20480
#define G1DSM  (2 * G1STGB)
#define F2STGB ((128 + 3 * 64) * LDK * 2) // fused: A + Eh + El + Ih = 25600
#define F2DSM  (2 * F2STGB)

// ---------------------------------------------------------------------------
// Persistent buffers (weights fp16; activations single fp16)
// ---------------------------------------------------------------------------
__device__ hlf g_wc_h [6 * M1], g_wc_l [6 * M1];   // combo weights [n][k] (lo unused at runtime)
__device__ hlf g_wv_h [6 * M1], g_wv_l [6 * M1];
__device__ hlf g_wo_h [6 * M1], g_wo_l [6 * M1];
__device__ hlf g_fb_h [5 * M1], g_fb_l [5 * M1];   // lo unused at runtime
__device__ hlf g_we_h [6 * M1], g_we_l [6 * M1];   // gathered [n=m*16+h][k=d]
__device__ hlf g_wi_h [6 * M1], g_wi_l [6 * M1];   // lo unused at runtime
__device__ hlf g_s1h[6 * M1], g_s1l[6 * M1];
__device__ hlf g_s2h[6 * M1], g_s2l[6 * M1];
__device__ float g_t2[6 * M1];
__device__ float g_bc1[6 * Dd], g_bc2[6 * Dd];
__device__ float g_bcp[6 * 8 * Dd];
__device__ float g_zero[Dd];
__device__ hlf g_a0[BD], g_a1[BD];                 // single fp16 activations

__device__ __forceinline__ void split1(float v, hlf* h, hlf* l) {
    hlf hh = __float2half_rn(v);
    *h = hh;
    *l = __float2half_rn(v - __half2float(hh));
}

__device__ __forceinline__ void cp16(void* smem, const void* g) {
    uint32_t s = (uint32_t)__cvta_generic_to_shared(smem);
    asm volatile("cp.async.cg.shared.global [%0], [%1], 16;" :: "r"(s), "l"(g));
}
__device__ __forceinline__ void cp_commit() { asm volatile("cp.async.commit_group;"); }
template <int N>
__device__ __forceinline__ void cp_wait() {
    asm volatile("cp.async.wait_group %0;" :: "n"(N));
}

// ---------------------------------------------------------------------------
// Conversion kernels
// ---------------------------------------------------------------------------
__device__ __forceinline__ void convT_body(const float* S, hlf* H, hlf* L,
                                           int k0, int n0, int tid) {
    __shared__ float t[32][33];
    const int r = tid >> 5, c = tid & 31;
    #pragma unroll
    for (int i = 0; i < 4; i++)
        t[r + i * 8][c] = S[(size_t)(k0 + r + i * 8) * Dd + n0 + c];
    __syncthreads();
    #pragma unroll
    for (int i = 0; i < 4; i++) {
        hlf hb, lb; split1(t[c][r + i * 8], &hb, &lb);
        size_t o = (size_t)(n0 + r + i * 8) * Dd + k0 + c;
        H[o] = hb; L[o] = lb;
    }
}

__global__ void convT_all(const float* __restrict__ Wv, const float* __restrict__ Wo,
                          const float* __restrict__ fbW,
                          hlf* __restrict__ wvh, hlf* __restrict__ wvl,
                          hlf* __restrict__ woh, hlf* __restrict__ wol,
                          hlf* __restrict__ fbh, hlf* __restrict__ fbl) {
    const int z = blockIdx.z;
    const float* S; hlf *H, *L;
    if (z < 6)       { S = Wv  + (size_t)z * M1;        H = wvh + (size_t)z * M1;        L = wvl + (size_t)z * M1; }
    else if (z < 12) { S = Wo  + (size_t)(z - 6) * M1;  H = woh + (size_t)(z - 6) * M1;  L = wol + (size_t)(z - 6) * M1; }
    else             { S = fbW + (size_t)(z - 12) * M1; H = fbh + (size_t)(z - 12) * M1; L = fbl + (size_t)(z - 12) * M1; }
    convT_body(S, H, L, blockIdx.y * 32, blockIdx.x * 32, threadIdx.x);
}

__global__ void conv_T(const float* __restrict__ src, hlf* __restrict__ hi,
                       hlf* __restrict__ lo) {
    const int l = blockIdx.z;
    convT_body(src + (size_t)l * M1, hi + (size_t)l * M1, lo + (size_t)l * M1,
               blockIdx.y * 32, blockIdx.x * 32, threadIdx.x);
}

__global__ void convgT_all(const float* __restrict__ We, const float* __restrict__ Wi,
                           hlf* __restrict__ weh, hlf* __restrict__ wel,
                           hlf* __restrict__ wih, hlf* __restrict__ wil) {
    __shared__ float t[64][17];
    const int z = blockIdx.z;
    const int l = (z < 6) ? z : z - 6;
    const float* src = (z < 6) ? We : Wi;
    hlf* hi = (z < 6) ? weh : wih;
    hlf* lo = (z < 6) ? wel : wil;
    const int d0 = blockIdx.x * 64, m = blockIdx.y;
    const int tid = threadIdx.x;
    {
        int dd = tid >> 2, h4 = (tid & 3) * 4;
        float4 v = *reinterpret_cast<const float4*>(
            &src[((size_t)(l * NMC + m) * Dd + d0 + dd) * Hh + h4]);
        t[dd][h4] = v.x; t[dd][h4 + 1] = v.y; t[dd][h4 + 2] = v.z; t[dd][h4 + 3] = v.w;
    }
    __syncthreads();
    int h = tid >> 4, cq = tid & 15;
    size_t rowo = (size_t)l * M1 + (size_t)(m * 16 + h) * Dd + d0 + cq * 4;
    #pragma unroll
    for (int j = 0; j < 4; j++) {
        hlf hb, lb; split1(t[cq * 4 + j][h], &hb, &lb);
        hi[rowo + j] = hb; lo[rowo + j] = lb;
    }
}

// Wlat (split, for precompute) + x (single fp16 activation) in one launch
__global__ void convact_all(const float* __restrict__ Wlat, const float* __restrict__ x,
                            hlf* __restrict__ s1h, hlf* __restrict__ s1l,
                            hlf* __restrict__ a1) {
    size_t idx = (size_t)blockIdx.x * blockDim.x + threadIdx.x;   // float4 index
    const size_t n1 = (size_t)6 * M1 / 4;
    if (idx < n1) {
        size_t i = idx * 4;
        float4 v = *reinterpret_cast<const float4*>(Wlat + i);
        hlf hs[4], ls[4];
        split1(v.x, &hs[0], &ls[0]); split1(v.y, &hs[1], &ls[1]);
        split1(v.z, &hs[2], &ls[2]); split1(v.w, &hs[3], &ls[3]);
        *reinterpret_cast<float2*>(s1h + i) = *reinterpret_cast<float2*>(hs);
        *reinterpret_cast<float2*>(s1l + i) = *reinterpret_cast<float2*>(ls);
    } else {
        size_t i = (idx - n1) * 4;
        float4 v = *reinterpret_cast<const float4*>(x + i);
        hlf hs[4];
        hs[0] = __float2half_rn(v.x); hs[1] = __float2half_rn(v.y);
        hs[2] = __float2half_rn(v.z); hs[3] = __float2half_rn(v.w);
        *reinterpret_cast<float2*>(a1 + i) = *reinterpret_cast<float2*>(hs);
    }
}

// Bias combo, deterministic 2-phase
__global__ void bias_part(const float* __restrict__ bin, const float* __restrict__ W,
                          float* __restrict__ bcp) {
    const int l = blockIdx.z;
    const int i0 = blockIdx.y * 128;
    const int j = blockIdx.x * 256 + threadIdx.x;
    const float* Wl = W + (size_t)l * M1;
    const float* bi = bin + (size_t)l * Dd;
    float s = 0.0f;
    #pragma unroll 4
    for (int i = i0; i < i0 + 128; i++) s += bi[i] * Wl[(size_t)i * Dd + j];
    bcp[((size_t)l * 8 + blockIdx.y) * Dd + j] = s;
}
__global__ void bias_reduce(const float* __restrict__ bcp, const float* __restrict__ badd,
                            float* __restrict__ bc) {
    const int l = blockIdx.y;
    const int j = blockIdx.x * 256 + threadIdx.x;
    float s = badd[(size_t)l * Dd + j];
    #pragma unroll
    for (int c = 0; c < 8; c++) s += bcp[((size_t)l * 8 + c) * Dd + j];
    bc[(size_t)l * Dd + j] = s;
}

// ---------------------------------------------------------------------------
// gemm_pre: full 3-pass split GEMM (combo precompute only, 1/16 scale).
// ---------------------------------------------------------------------------
template <bool WF32, bool WSPLIT>
__global__ __launch_bounds__(128, 2)
void gemm_pre(const hlf* __restrict__ Ahi_, const hlf* __restrict__ Alo_,
              const hlf* __restrict__ Whi_, const hlf* __restrict__ Wlo_,
              const float* __restrict__ bias_, float* __restrict__ Cf_,
              hlf* __restrict__ Chi_, hlf* __restrict__ Clo_,
              size_t sA, size_t sW, size_t sB, size_t sC) {
    extern __shared__ char smraw[];
    const int z = blockIdx.z;
    const hlf* Ahi = Ahi_ + (size_t)z * sA;
    const hlf* Alo = Alo_ + (size_t)z * sA;
    const hlf* Whi = Whi_ + (size_t)z * sW;
    const hlf* Wlo = Wlo_ + (size_t)z * sW;
    const float* bias = bias_ + (size_t)z * sB;
    float* Cf = WF32 ? Cf_ + (size_t)z * sC : nullptr;
    hlf* Chi = WSPLIT ? Chi_ + (size_t)z * sC : nullptr;
    hlf* Clo = WSPLIT ? Clo_ + (size_t)z * sC : nullptr;

    const int tid = threadIdx.x, wid = tid >> 5, lane = tid & 31;
    const int wm = wid >> 1, wn = wid & 1;
    const int m0 = blockIdx.y * 128, n0 = blockIdx.x * 128;

    wmma::fragment<wmma::accumulator, 16, 16, 16, float> acc[4][4];
    #pragma unroll
    for (int i = 0; i < 4; i++)
        #pragma unroll
        for (int j = 0; j < 4; j++)
            wmma::fill_fragment(acc[i][j], 0.0f);

    auto load_stage = [&](int st, int kt) {
        hlf* Ah = reinterpret_cast<hlf*>(smraw + st * GPSTGB);
        hlf* Al = Ah + 128 * LDK;
        hlf* Bh = Al + 128 * LDK;
        hlf* Bl = Bh + 128 * LDK;
        const int k0 = kt * BK;
        #pragma unroll
        for (int t = 0; t < 4; t++) {
            int item = tid + t * 128;
            int r = item >> 2, c = (item & 3) * 8;
            size_t ga = (size_t)(m0 + r) * Dd + k0 + c;
            size_t gb = (size_t)(n0 + r) * Dd + k0 + c;
            cp16(Ah + r * LDK + c, Ahi + ga);
            cp16(Al + r * LDK + c, Alo + ga);
            cp16(Bh + r * LDK + c, Whi + gb);
            cp16(Bl + r * LDK + c, Wlo + gb);
        }
        cp_commit();
    };

    load_stage(0, 0);
    for (int kt = 0; kt < NKT; kt++) {
        int st = kt & 1;
        if (kt + 1 < NKT) { load_stage(st ^ 1, kt + 1); cp_wait<1>(); }
        else              { cp_wait<0>(); }
        __syncthreads();

        hlf* Ah = reinterpret_cast<hlf*>(smraw + st * GPSTGB);
        hlf* Al = Ah + 128 * LDK;
        hlf* Bh = Al + 128 * LDK;
        hlf* Bl = Bh + 128 * LDK;
        #pragma unroll
        for (int ks = 0; ks < BK; ks += 16) {
            #pragma unroll
            for (int jh = 0; jh < 2; jh++) {
                wmma::fragment<wmma::matrix_b, 16, 16, 16, hlf, wmma::col_major> bh[2], bl[2];
                #pragma unroll
                for (int j = 0; j < 2; j++) {
                    int nb = (wn * 64 + (jh * 2 + j) * 16) * LDK + ks;
                    wmma::load_matrix_sync(bh[j], &Bh[nb], LDK);
                    wmma::load_matrix_sync(bl[j], &Bl[nb], LDK);
                }
                #pragma unroll
                for (int i = 0; i < 4; i++) {
                    wmma::fragment<wmma::matrix_a, 16, 16, 16, hlf, wmma::row_major> ah, al;
                    wmma::load_matrix_sync(ah, &Ah[(wm * 64 + i * 16) * LDK + ks], LDK);
                    wmma::load_matrix_sync(al, &Al[(wm * 64 + i * 16) * LDK + ks], LDK);
                    #pragma unroll
                    for (int j = 0; j < 2; j++)
                        wmma::mma_sync(acc[i][jh * 2 + j], ah, bh[j], acc[i][jh * 2 + j]);
                    #pragma unroll
                    for (int j = 0; j < 2; j++)
                        wmma::mma_sync(acc[i][jh * 2 + j], ah, bl[j], acc[i][jh * 2 + j]);
                    #pragma unroll
                    for (int j = 0; j < 2; j++)
                        wmma::mma_sync(acc[i][jh * 2 + j], al, bh[j], acc[i][jh * 2 + j]);
                }
            }
        }
        __syncthreads();
    }

    __syncthreads();
    float* patch = reinterpret_cast<float*>(smraw) + wid * 16 * 20;
    const int er = lane >> 1, eh = (lane & 1) * 8;
    #pragma unroll
    for (int i = 0; i < 4; i++) {
        #pragma unroll
        for (int j = 0; j < 4; j++) {
            wmma::store_matrix_sync(patch, acc[i][j], 20, wmma::mem_row_major);
            __syncwarp();
            int gr = m0 + wm * 64 + i * 16 + er;
            int gc = n0 + wn * 64 + j * 16 + eh;
            size_t go = (size_t)gr * Dd + gc;
            float4 b0 = *reinterpret_cast<const float4*>(&bias[gc]);
            float4 b1 = *reinterpret_cast<const float4*>(&bias[gc + 4]);
            float v[8];
            #pragma unroll
            for (int e = 0; e < 8; e++) v[e] = patch[er * 20 + eh + e];
            v[0] += b0.x; v[1] += b0.y; v[2] += b0.z; v[3] += b0.w;
            v[4] += b1.x; v[5] += b1.y; v[6] += b1.z; v[7] += b1.w;
            if (WF32) {
                *reinterpret_cast<float4*>(&Cf[go])     = *reinterpret_cast<float4*>(&v[0]);
                *reinterpret_cast<float4*>(&Cf[go + 4]) = *reinterpret_cast<float4*>(&v[4]);
            }
            if (WSPLIT) {
                hlf hs[8], ls[8];
                #pragma unroll
                for (int e = 0; e < 8; e++) split1(v[e], &hs[e], &ls[e]);
                *reinterpret_cast<float4*>(&Chi[go]) = *reinterpret_cast<float4*>(hs);
                *reinterpret_cast<float4*>(&Clo[go]) = *reinterpret_cast<float4*>(ls);
            }
            __syncwarp();
        }
    }
}

// ---------------------------------------------------------------------------
// gemm1: single-pass fp16 GEMM. C = (ACC ? Cf : 0) + A @ W + bias.
// A fp16 [Bsz,Dd] rm; W fp16 [n][k] km. Writes fp16 Ch + fp32 Cf.
// ---------------------------------------------------------------------------
template <bool ACC>
__global__ __launch_bounds__(128, 2)
void gemm1(const hlf* __restrict__ A, const hlf* __restrict__ W,
           const float* __restrict__ bias, float* __restrict__ Cf,
           hlf* __restrict__ Ch) {
    extern __shared__ char smraw[];
    const int tid = threadIdx.x, wid = tid >> 5, lane = tid & 31;
    const int wm = wid >> 1, wn = wid & 1;
    const int m0 = blockIdx.y * 128, n0 = blockIdx.x * 128;

    wmma::fragment<wmma::accumulator, 16, 16, 16, float> acc[4][4];
    #pragma unroll
    for (int i = 0; i < 4; i++)
        #pragma unroll
        for (int j = 0; j < 4; j++)
            wmma::fill_fragment(acc[i][j], 0.0f);

    auto load_stage = [&](int st, int kt) {
        hlf* Ad = reinterpret_cast<hlf*>(smraw + st * G1STGB);
        hlf* Bd = Ad + 128 * LDK;
        const int k0 = kt * BK;
        #pragma unroll
        for (int t = 0; t < 4; t++) {
            int item = tid + t * 128;
            int r = item >> 2, c = (item & 3) * 8;
            cp16(Ad + r * LDK + c, A + (size_t)(m0 + r) * Dd + k0 + c);
            cp16(Bd + r * LDK + c, W + (size_t)(n0 + r) * Dd + k0 + c);
        }
        cp_commit();
    };

    load_stage(0, 0);
    for (int kt = 0; kt < NKT; kt++) {
        int st = kt & 1;
        if (kt + 1 < NKT) { load_stage(st ^ 1, kt + 1); cp_wait<1>(); }
        else              { cp_wait<0>(); }
        __syncthreads();

        hlf* Ad = reinterpret_cast<hlf*>(smraw + st * G1STGB);
        hlf* Bd = Ad + 128 * LDK;
        #pragma unroll
        for (int ks = 0; ks < BK; ks += 16) {
            wmma::fragment<wmma::matrix_b, 16, 16, 16, hlf, wmma::col_major> bf[4];
            #pragma unroll
            for (int j = 0; j < 4; j++)
                wmma::load_matrix_sync(bf[j], &Bd[(wn * 64 + j * 16) * LDK + ks], LDK);
            #pragma unroll
            for (int i = 0; i < 4; i++) {
                wmma::fragment<wmma::matrix_a, 16, 16, 16, hlf, wmma::row_major> ah;
                wmma::load_matrix_sync(ah, &Ad[(wm * 64 + i * 16) * LDK + ks], LDK);
                #pragma unroll
                for (int j = 0; j < 4; j++)
                    wmma::mma_sync(acc[i][j], ah, bf[j], acc[i][j]);
            }
        }
        __syncthreads();
    }

    __syncthreads();
    float* patch = reinterpret_cast<float*>(smraw) + wid * 16 * 20;
    const int er = lane >> 1, eh = (lane & 1) * 8;
    #pragma unroll
    for (int i = 0; i < 4; i++) {
        #pragma unroll
        for (int j = 0; j < 4; j++) {
            wmma::store_matrix_sync(patch, acc[i][j], 20, wmma::mem_row_major);
            __syncwarp();
            int gr = m0 + wm * 64 + i * 16 + er;
            int gc = n0 + wn * 64 + j * 16 + eh;
            size_t go = (size_t)gr * Dd + gc;
            float4 b0 = *reinterpret_cast<const float4*>(&bias[gc]);
            float4 b1 = *reinterpret_cast<const float4*>(&bias[gc + 4]);
            float v[8];
            #pragma unroll
            for (int e = 0; e < 8; e++) v[e] = patch[er * 20 + eh + e];
            v[0] += b0.x; v[1] += b0.y; v[2] += b0.z; v[3] += b0.w;
            v[4] += b1.x; v[5] += b1.y; v[6] += b1.z; v[7] += b1.w;
            if (ACC) {
                float4 o0 = *reinterpret_cast<const float4*>(&Cf[go]);
                float4 o1 = *reinterpret_cast<const float4*>(&Cf[go + 4]);
                v[0] += o0.x; v[1] += o0.y; v[2] += o0.z; v[3] += o0.w;
                v[4] += o1.x; v[5] += o1.y; v[6] += o1.z; v[7] += o1.w;
            }
            *reinterpret_cast<float4*>(&Cf[go])     = *reinterpret_cast<float4*>(&v[0]);
            *reinterpret_cast<float4*>(&Cf[go + 4]) = *reinterpret_cast<float4*>(&v[4]);
            hlf hs[8];
            #pragma unroll
            for (int e = 0; e < 8; e++) hs[e] = __float2half_rn(v[e]);
            *reinterpret_cast<float4*>(&Ch[go]) = *reinterpret_cast<float4*>(hs);
            __syncwarp();
        }
    }
}

// ---------------------------------------------------------------------------
// fused2: block 128x64, 4 warps, warp 64x32. A single fp16.
// exc: 2-pass (We hi+lo); inh: 1-pass (Wi hi). Output single fp16 mc.
// ---------------------------------------------------------------------------
__global__ __launch_bounds__(128, 2)
void fused2(const hlf* __restrict__ A,
            const hlf* __restrict__ Weh, const hlf* __restrict__ Wel,
            const hlf* __restrict__ Wih,
            const float* __restrict__ be_l, const float* __restrict__ bi_l,
            const float* __restrict__ Wl_l, const float* __restrict__ bl_l,
            hlf* __restrict__ Mc) {
    extern __shared__ char smraw[];
    __shared__ float swl[1024];
    __shared__ float sbe[64], sbi[64], sbl[64];

    const int tid = threadIdx.x, wid = tid >> 5, lane = tid & 31;
    const int wm = wid >> 1, wn = wid & 1;
    const int m0 = blockIdx.y * 128, n0 = blockIdx.x * 64;

    for (int i = tid; i < 256; i += 128)
        *reinterpret_cast<float4*>(&swl[i * 4]) =
            *reinterpret_cast<const float4*>(&Wl_l[(size_t)n0 * Hh + i * 4]);
    if (tid < 64) {
        sbe[tid] = be_l[n0 + tid];
        sbi[tid] = bi_l[n0 + tid];
        sbl[tid] = bl_l[n0 + tid];
    }

    wmma::fragment<wmma::accumulator, 16, 16, 16, float> ae[4][2], ai[4][2];
    #pragma unroll
    for (int i = 0; i < 4; i++)
        #pragma unroll
        for (int j = 0; j < 2; j++) {
            wmma::fill_fragment(ae[i][j], 0.0f);
            wmma::fill_fragment(ai[i][j], 0.0f);
        }

    auto load_stage = [&](int st, int kt) {
        hlf* Ad = reinterpret_cast<hlf*>(smraw + st * F2STGB);
        hlf* Eh = Ad + 128 * LDK;
        hlf* El = Eh + 64 * LDK;
        hlf* Ih = El + 64 * LDK;
        const int k0 = kt * BK;
        #pragma unroll
        for (int t = 0; t < 4; t++) {
            int item = tid + t * 128;
            int r = item >> 2, c = (item & 3) * 8;
            cp16(Ad + r * LDK + c, A + (size_t)(m0 + r) * Dd + k0 + c);
        }
        #pragma unroll
        for (int t = 0; t < 2; t++) {
            int item = tid + t * 128;
            int r = item >> 2, c = (item & 3) * 8;
            size_t gb = (size_t)(n0 + r) * Dd + k0 + c;
            cp16(Eh + r * LDK + c, Weh + gb);
            cp16(El + r * LDK + c, Wel + gb);
            cp16(Ih + r * LDK + c, Wih + gb);
        }
        cp_commit();
    };

    load_stage(0, 0);
    for (int kt = 0; kt < NKT; kt++) {
        int st = kt & 1;
        if (kt + 1 < NKT) { load_stage(st ^ 1, kt + 1); cp_wait<1>(); }
        else              { cp_wait<0>(); }
        __syncthreads();

        hlf* Ad = reinterpret_cast<hlf*>(smraw + st * F2STGB);
        hlf* Eh = Ad + 128 * LDK;
        hlf* El = Eh + 64 * LDK;
        hlf* Ih = El + 64 * LDK;
        #pragma unroll
        for (int ks = 0; ks < BK; ks += 16) {
            wmma::fragment<wmma::matrix_b, 16, 16, 16, hlf, wmma::col_major>
                eh[2], el[2], ih[2];
            #pragma unroll
            for (int j = 0; j < 2; j++) {
                int nb = (wn * 32 + j * 16) * LDK + ks;
                wmma::load_matrix_sync(eh[j], &Eh[nb], LDK);
                wmma::load_matrix_sync(el[j], &El[nb], LDK);
                wmma::load_matrix_sync(ih[j], &Ih[nb], LDK);
            }
            #pragma unroll
            for (int i = 0; i < 4; i++) {
                wmma::fragment<wmma::matrix_a, 16, 16, 16, hlf, wmma::row_major> ah;
                wmma::load_matrix_sync(ah, &Ad[(wm * 64 + i * 16) * LDK + ks], LDK);
                #pragma unroll
                for (int j = 0; j < 2; j++) wmma::mma_sync(ae[i][j], ah, eh[j], ae[i][j]);
                #pragma unroll
                for (int j = 0; j < 2; j++) wmma::mma_sync(ai[i][j], ah, ih[j], ai[i][j]);
                #pragma unroll
                for (int j = 0; j < 2; j++) wmma::mma_sync(ae[i][j], ah, el[j], ae[i][j]);
            }
        }
        __syncthreads();
    }

    __syncthreads();
    float* pe = reinterpret_cast<float*>(smraw) + wid * 2 * 16 * 20;
    float* pi = pe + 16 * 20;
    const int er = lane >> 1, eh8 = (lane & 1) * 8;
    #pragma unroll
    for (int i = 0; i < 4; i++) {
        #pragma unroll
        for (int j = 0; j < 2; j++) {
            wmma::store_matrix_sync(pe, ae[i][j], 20, wmma::mem_row_major);
            wmma::store_matrix_sync(pi, ai[i][j], 20, wmma::mem_row_major);
            __syncwarp();
            int ml = wn * 2 + j;
            int gr = m0 + wm * 64 + i * 16 + er;
            float ihv[16];
            #pragma unroll
            for (int h = 0; h < 16; h++)
                ihv[h] = fmaxf(pi[er * 20 + h] + sbi[ml * 16 + h], 0.0f);
            hlf hs[8];
            #pragma unroll
            for (int e = 0; e < 8; e++) {
                int k = eh8 + e;
                float lat = sbl[ml * 16 + k];
                #pragma unroll
                for (int h = 0; h < 16; h++)
                    lat += ihv[h] * swl[ml * 256 + h * 16 + k];
                float ex = fmaxf(pe[er * 20 + k] + sbe[ml * 16 + k], 0.0f);
                hs[e] = __float2half_rn(fmaxf(ex - lat, 0.0f));
            }
            *reinterpret_cast<float4*>(&Mc[(size_t)gr * Dd + n0 + ml * 16 + eh8]) =
                *reinterpret_cast<float4*>(hs);
            __syncwarp();
        }
    }
}

// ---------------------------------------------------------------------------
// Host orchestration
// ---------------------------------------------------------------------------
extern "C" void kernel_launch(void* const* d_in, const int* in_sizes, int n_in,
                              void* d_out, int out_size) {
    const float* x    = (const float*)d_in[0];
    const float* We   = (const float*)d_in[1];
    const float* be   = (const float*)d_in[2];
    const float* Wi   = (const float*)d_in[3];
    const float* bi   = (const float*)d_in[4];
    const float* Wl   = (const float*)d_in[5];
    const float* bl   = (const float*)d_in[6];
    const float* Wlat = (const float*)d_in[7];
    const float* blat = (const float*)d_in[8];
    const float* Wv   = (const float*)d_in[9];
    const float* bv   = (const float*)d_in[10];
    const float* Wo   = (const float*)d_in[11];
    const float* bo   = (const float*)d_in[12];
    const float* fbW  = (const float*)d_in[13];
    const float* fbb  = (const float*)d_in[14];
    float* out = (float*)d_out;

    hlf *wc_h, *wc_l, *wv_h, *wv_l, *wo_h, *wo_l, *fb_h, *fb_l;
    hlf *we_h, *we_l, *wi_h, *wi_l, *a0, *a1;
    hlf *s1h, *s1l, *s2h, *s2l;
    float *t2, *bc1, *bc2, *bcp, *zero;
    cudaGetSymbolAddress((void**)&wc_h, g_wc_h);
    cudaGetSymbolAddress((void**)&wc_l, g_wc_l);
    cudaGetSymbolAddress((void**)&wv_h, g_wv_h);
    cudaGetSymbolAddress((void**)&wv_l, g_wv_l);
    cudaGetSymbolAddress((void**)&wo_h, g_wo_h);
    cudaGetSymbolAddress((void**)&wo_l, g_wo_l);
    cudaGetSymbolAddress((void**)&fb_h, g_fb_h);
    cudaGetSymbolAddress((void**)&fb_l, g_fb_l);
    cudaGetSymbolAddress((void**)&we_h, g_we_h);
    cudaGetSymbolAddress((void**)&we_l, g_we_l);
    cudaGetSymbolAddress((void**)&wi_h, g_wi_h);
    cudaGetSymbolAddress((void**)&wi_l, g_wi_l);
    cudaGetSymbolAddress((void**)&a0,   g_a0);
    cudaGetSymbolAddress((void**)&a1,   g_a1);
    cudaGetSymbolAddress((void**)&s1h,  g_s1h);
    cudaGetSymbolAddress((void**)&s1l,  g_s1l);
    cudaGetSymbolAddress((void**)&s2h,  g_s2h);
    cudaGetSymbolAddress((void**)&s2l,  g_s2l);
    cudaGetSymbolAddress((void**)&t2,   g_t2);
    cudaGetSymbolAddress((void**)&bc1,  g_bc1);
    cudaGetSymbolAddress((void**)&bc2,  g_bc2);
    cudaGetSymbolAddress((void**)&bcp,  g_bcp);
    cudaGetSymbolAddress((void**)&zero, g_zero);

    cudaFuncSetAttribute(gemm_pre<false, true>, cudaFuncAttributeMaxDynamicSharedMemorySize, GPDSM);
    cudaFuncSetAttribute(gemm_pre<true, false>, cudaFuncAttributeMaxDynamicSharedMemorySize, GPDSM);
    cudaFuncSetAttribute(gemm1<false>,          cudaFuncAttributeMaxDynamicSharedMemorySize, G1DSM);
    cudaFuncSetAttribute(gemm1<true>,           cudaFuncAttributeMaxDynamicSharedMemorySize, G1DSM);
    cudaFuncSetAttribute(fused2,                cudaFuncAttributeMaxDynamicSharedMemorySize, F2DSM);

    // --- One-time conversions (launches 0-2) ---
    convT_all<<<dim3(32, 32, 17), 256>>>(Wv, Wo, fbW, wv_h, wv_l, wo_h, wo_l, fb_h, fb_l);
    convgT_all<<<dim3(16, 64, 12), 256>>>(We, Wi, we_h, we_l, wi_h, wi_l);
    convact_all<<<(int)(6 * M1 / 4 / 256 + BD / 4 / 256), 256>>>(Wlat, x, s1h, s1l, a1);

    // --- Combo weight precompute (launches 3-4, full 3-pass precision) ---
    dim3 gridC(8, 8, 6);
    gemm_pre<false, true><<<gridC, 128, GPDSM>>>(s1h, s1l, wv_h, wv_l,
        zero, nullptr, s2h, s2l, M1, M1, 0, M1);
    gemm_pre<true, false><<<gridC, 128, GPDSM>>>(s2h, s2l, wo_h, wo_l,
        zero, t2, nullptr, nullptr, M1, M1, 0, M1);

    const size_t WL_STRIDE = (size_t)NMC * Hh * Hh;
    dim3 gridG(Dd / 128, Bsz / 128);   // 8 x 128
    dim3 gridF(Dd / 64,  Bsz / 128);   // 16 x 128

    // Launch 5 = fused2 l0 (ncu -s 5 target)
    fused2<<<gridF, 128, F2DSM>>>(a1, we_h, we_l, wi_h,
                                  be, bi, Wl, bl, a0);

    conv_T<<<dim3(32, 32, 6), 256>>>(t2, wc_h, wc_l);
    bias_part<<<dim3(4, 8, 6), 256>>>(blat, Wv, bcp);
    bias_reduce<<<dim3(4, 6), 256>>>(bcp, bv, bc1);
    bias_part<<<dim3(4, 8, 6), 256>>>(bc1, Wo, bcp);
    bias_reduce<<<dim3(4, 6), 256>>>(bcp, bo, bc2);

    for (int l = 0; l < Lc; l++) {
        if (l > 0) {
            fused2<<<gridF, 128, F2DSM>>>(a1,
                we_h + (size_t)l * M1, we_l + (size_t)l * M1,
                wi_h + (size_t)l * M1,
                be + l * Dd, bi + l * Dd, Wl + l * WL_STRIDE, bl + l * Dd,
                a0);
        }
        // Combo-apply: single-pass fp16 weights
        gemm1<false><<<gridG, 128, G1DSM>>>(a0,
            wc_h + (size_t)l * M1,
            bc2 + (size_t)l * Dd, out + (size_t)l * BD, a1);
    }

    int p = 1;
    for (int i = 0; i < Lc - 1; i++) {
        int idx = Lc - 2 - i;
        hlf* src = p ? a1 : a0;
        hlf* dst = p ? a0 : a1;
        // Feedback: single-pass fp16 weights
        gemm1<true><<<gridG, 128, G1DSM>>>(src,
            fb_h + (size_t)i * M1,
            fbb + i * Dd, out + (size_t)idx * BD, dst);
        p ^= 1;
    }
}

// round 15
// speedup vs baseline: 2.5130x; 1.1282x over previous
#include <cuda_runtime.h>
#include <cuda_fp16.h>
#include <mma.h>
#include <cstdint>

using namespace nvcuda;
typedef __half hlf;

// Problem constants
#define Bsz 16384
#define Dd  1024
#define Lc  6
#define NMC 64
#define Hh  16
#define M1  (1024 * 1024)
#define BD  ((size_t)Bsz * Dd)

// Tiling: block 128x128 (generic) / 128x64 (fused), 4 warps, occ 2, 2-stage
#define BK   32
#define LDK  40
#define NKT  (Dd / BK)
#define GPSTGB (4 * 128 * LDK * 2)        // pre (3-pass): A hi/lo + B hi/lo = 40960
#define GPDSM  (2 * GPSTGB)
#define G1STGB (2 * 128 * LDK * 2)        // 1-pass: A + B = 20480
#define G1DSM  (2 * G1STGB)
#define F1STGB ((128 + 2 * 64) * LDK * 2) // fused: A + Eh + Ih = 20480
#define F1DSM  (2 * F1STGB)

// ---------------------------------------------------------------------------
// Persistent buffers (weights fp16; activations single fp16)
// ---------------------------------------------------------------------------
__device__ hlf g_wc_h [6 * M1], g_wc_l [6 * M1];   // combo weights [n][k]
__device__ hlf g_wv_h [6 * M1], g_wv_l [6 * M1];
__device__ hlf g_wo_h [6 * M1], g_wo_l [6 * M1];
__device__ hlf g_fb_h [5 * M1], g_fb_l [5 * M1];
__device__ hlf g_we_h [6 * M1], g_we_l [6 * M1];   // gathered [n=m*16+h][k=d]
__device__ hlf g_wi_h [6 * M1], g_wi_l [6 * M1];
__device__ hlf g_s1h[6 * M1], g_s1l[6 * M1];
__device__ hlf g_s2h[6 * M1], g_s2l[6 * M1];
__device__ float g_t2[6 * M1];
__device__ float g_bc1[6 * Dd], g_bc2[6 * Dd];
__device__ float g_bcp[6 * 8 * Dd];
__device__ float g_zero[Dd];
__device__ hlf g_a0[BD], g_a1[BD];                 // single fp16 activations

__device__ __forceinline__ void split1(float v, hlf* h, hlf* l) {
    hlf hh = __float2half_rn(v);
    *h = hh;
    *l = __float2half_rn(v - __half2float(hh));
}

__device__ __forceinline__ void cp16(void* smem, const void* g) {
    uint32_t s = (uint32_t)__cvta_generic_to_shared(smem);
    asm volatile("cp.async.cg.shared.global [%0], [%1], 16;" :: "r"(s), "l"(g));
}
__device__ __forceinline__ void cp_commit() { asm volatile("cp.async.commit_group;"); }
template <int N>
__device__ __forceinline__ void cp_wait() {
    asm volatile("cp.async.wait_group %0;" :: "n"(N));
}

// ---------------------------------------------------------------------------
// Conversion kernels
// ---------------------------------------------------------------------------
__device__ __forceinline__ void convT_body(const float* S, hlf* H, hlf* L,
                                           int k0, int n0, int tid) {
    __shared__ float t[32][33];
    const int r = tid >> 5, c = tid & 31;
    #pragma unroll
    for (int i = 0; i < 4; i++)
        t[r + i * 8][c] = S[(size_t)(k0 + r + i * 8) * Dd + n0 + c];
    __syncthreads();
    #pragma unroll
    for (int i = 0; i < 4; i++) {
        hlf hb, lb; split1(t[c][r + i * 8], &hb, &lb);
        size_t o = (size_t)(n0 + r + i * 8) * Dd + k0 + c;
        H[o] = hb; L[o] = lb;
    }
}

__global__ void convT_all(const float* __restrict__ Wv, const float* __restrict__ Wo,
                          const float* __restrict__ fbW,
                          hlf* __restrict__ wvh, hlf* __restrict__ wvl,
                          hlf* __restrict__ woh, hlf* __restrict__ wol,
                          hlf* __restrict__ fbh, hlf* __restrict__ fbl) {
    const int z = blockIdx.z;
    const float* S; hlf *H, *L;
    if (z < 6)       { S = Wv  + (size_t)z * M1;        H = wvh + (size_t)z * M1;        L = wvl + (size_t)z * M1; }
    else if (z < 12) { S = Wo  + (size_t)(z - 6) * M1;  H = woh + (size_t)(z - 6) * M1;  L = wol + (size_t)(z - 6) * M1; }
    else             { S = fbW + (size_t)(z - 12) * M1; H = fbh + (size_t)(z - 12) * M1; L = fbl + (size_t)(z - 12) * M1; }
    convT_body(S, H, L, blockIdx.y * 32, blockIdx.x * 32, threadIdx.x);
}

__global__ void conv_T(const float* __restrict__ src, hlf* __restrict__ hi,
                       hlf* __restrict__ lo) {
    const int l = blockIdx.z;
    convT_body(src + (size_t)l * M1, hi + (size_t)l * M1, lo + (size_t)l * M1,
               blockIdx.y * 32, blockIdx.x * 32, threadIdx.x);
}

__global__ void convgT_all(const float* __restrict__ We, const float* __restrict__ Wi,
                           hlf* __restrict__ weh, hlf* __restrict__ wel,
                           hlf* __restrict__ wih, hlf* __restrict__ wil) {
    __shared__ float t[64][17];
    const int z = blockIdx.z;
    const int l = (z < 6) ? z : z - 6;
    const float* src = (z < 6) ? We : Wi;
    hlf* hi = (z < 6) ? weh : wih;
    hlf* lo = (z < 6) ? wel : wil;
    const int d0 = blockIdx.x * 64, m = blockIdx.y;
    const int tid = threadIdx.x;
    {
        int dd = tid >> 2, h4 = (tid & 3) * 4;
        float4 v = *reinterpret_cast<const float4*>(
            &src[((size_t)(l * NMC + m) * Dd + d0 + dd) * Hh + h4]);
        t[dd][h4] = v.x; t[dd][h4 + 1] = v.y; t[dd][h4 + 2] = v.z; t[dd][h4 + 3] = v.w;
    }
    __syncthreads();
    int h = tid >> 4, cq = tid & 15;
    size_t rowo = (size_t)l * M1 + (size_t)(m * 16 + h) * Dd + d0 + cq * 4;
    #pragma unroll
    for (int j = 0; j < 4; j++) {
        hlf hb, lb; split1(t[cq * 4 + j][h], &hb, &lb);
        hi[rowo + j] = hb; lo[rowo + j] = lb;
    }
}

// Wlat (split, for precompute) + x (single fp16 activation) in one launch
__global__ void convact_all(const float* __restrict__ Wlat, const float* __restrict__ x,
                            hlf* __restrict__ s1h, hlf* __restrict__ s1l,
                            hlf* __restrict__ a1) {
    size_t idx = (size_t)blockIdx.x * blockDim.x + threadIdx.x;   // float4 index
    const size_t n1 = (size_t)6 * M1 / 4;
    if (idx < n1) {
        size_t i = idx * 4;
        float4 v = *reinterpret_cast<const float4*>(Wlat + i);
        hlf hs[4], ls[4];
        split1(v.x, &hs[0], &ls[0]); split1(v.y, &hs[1], &ls[1]);
        split1(v.z, &hs[2], &ls[2]); split1(v.w, &hs[3], &ls[3]);
        *reinterpret_cast<float2*>(s1h + i) = *reinterpret_cast<float2*>(hs);
        *reinterpret_cast<float2*>(s1l + i) = *reinterpret_cast<float2*>(ls);
    } else {
        size_t i = (idx - n1) * 4;
        float4 v = *reinterpret_cast<const float4*>(x + i);
        hlf hs[4];
        hs[0] = __float2half_rn(v.x); hs[1] = __float2half_rn(v.y);
        hs[2] = __float2half_rn(v.z); hs[3] = __float2half_rn(v.w);
        *reinterpret_cast<float2*>(a1 + i) = *reinterpret_cast<float2*>(hs);
    }
}

// Bias combo, deterministic 2-phase
__global__ void bias_part(const float* __restrict__ bin, const float* __restrict__ W,
                          float* __restrict__ bcp) {
    const int l = blockIdx.z;
    const int i0 = blockIdx.y * 128;
    const int j = blockIdx.x * 256 + threadIdx.x;
    const float* Wl = W + (size_t)l * M1;
    const float* bi = bin + (size_t)l * Dd;
    float s = 0.0f;
    #pragma unroll 4
    for (int i = i0; i < i0 + 128; i++) s += bi[i] * Wl[(size_t)i * Dd + j];
    bcp[((size_t)l * 8 + blockIdx.y) * Dd + j] = s;
}
__global__ void bias_reduce(const float* __restrict__ bcp, const float* __restrict__ badd,
                            float* __restrict__ bc) {
    const int l = blockIdx.y;
    const int j = blockIdx.x * 256 + threadIdx.x;
    float s = badd[(size_t)l * Dd + j];
    #pragma unroll
    for (int c = 0; c < 8; c++) s += bcp[((size_t)l * 8 + c) * Dd + j];
    bc[(size_t)l * Dd + j] = s;
}

// ---------------------------------------------------------------------------
// gemm_pre: full 3-pass split GEMM (combo precompute only, 1/16 scale).
// ---------------------------------------------------------------------------
template <bool WF32, bool WSPLIT>
__global__ __launch_bounds__(128, 2)
void gemm_pre(const hlf* __restrict__ Ahi_, const hlf* __restrict__ Alo_,
              const hlf* __restrict__ Whi_, const hlf* __restrict__ Wlo_,
              const float* __restrict__ bias_, float* __restrict__ Cf_,
              hlf* __restrict__ Chi_, hlf* __restrict__ Clo_,
              size_t sA, size_t sW, size_t sB, size_t sC) {
    extern __shared__ char smraw[];
    const int z = blockIdx.z;
    const hlf* Ahi = Ahi_ + (size_t)z * sA;
    const hlf* Alo = Alo_ + (size_t)z * sA;
    const hlf* Whi = Whi_ + (size_t)z * sW;
    const hlf* Wlo = Wlo_ + (size_t)z * sW;
    const float* bias = bias_ + (size_t)z * sB;
    float* Cf = WF32 ? Cf_ + (size_t)z * sC : nullptr;
    hlf* Chi = WSPLIT ? Chi_ + (size_t)z * sC : nullptr;
    hlf* Clo = WSPLIT ? Clo_ + (size_t)z * sC : nullptr;

    const int tid = threadIdx.x, wid = tid >> 5, lane = tid & 31;
    const int wm = wid >> 1, wn = wid & 1;
    const int m0 = blockIdx.y * 128, n0 = blockIdx.x * 128;

    wmma::fragment<wmma::accumulator, 16, 16, 16, float> acc[4][4];
    #pragma unroll
    for (int i = 0; i < 4; i++)
        #pragma unroll
        for (int j = 0; j < 4; j++)
            wmma::fill_fragment(acc[i][j], 0.0f);

    auto load_stage = [&](int st, int kt) {
        hlf* Ah = reinterpret_cast<hlf*>(smraw + st * GPSTGB);
        hlf* Al = Ah + 128 * LDK;
        hlf* Bh = Al + 128 * LDK;
        hlf* Bl = Bh + 128 * LDK;
        const int k0 = kt * BK;
        #pragma unroll
        for (int t = 0; t < 4; t++) {
            int item = tid + t * 128;
            int r = item >> 2, c = (item & 3) * 8;
            size_t ga = (size_t)(m0 + r) * Dd + k0 + c;
            size_t gb = (size_t)(n0 + r) * Dd + k0 + c;
            cp16(Ah + r * LDK + c, Ahi + ga);
            cp16(Al + r * LDK + c, Alo + ga);
            cp16(Bh + r * LDK + c, Whi + gb);
            cp16(Bl + r * LDK + c, Wlo + gb);
        }
        cp_commit();
    };

    load_stage(0, 0);
    for (int kt = 0; kt < NKT; kt++) {
        int st = kt & 1;
        if (kt + 1 < NKT) { load_stage(st ^ 1, kt + 1); cp_wait<1>(); }
        else              { cp_wait<0>(); }
        __syncthreads();

        hlf* Ah = reinterpret_cast<hlf*>(smraw + st * GPSTGB);
        hlf* Al = Ah + 128 * LDK;
        hlf* Bh = Al + 128 * LDK;
        hlf* Bl = Bh + 128 * LDK;
        #pragma unroll
        for (int ks = 0; ks < BK; ks += 16) {
            #pragma unroll
            for (int jh = 0; jh < 2; jh++) {
                wmma::fragment<wmma::matrix_b, 16, 16, 16, hlf, wmma::col_major> bh[2], bl[2];
                #pragma unroll
                for (int j = 0; j < 2; j++) {
                    int nb = (wn * 64 + (jh * 2 + j) * 16) * LDK + ks;
                    wmma::load_matrix_sync(bh[j], &Bh[nb], LDK);
                    wmma::load_matrix_sync(bl[j], &Bl[nb], LDK);
                }
                #pragma unroll
                for (int i = 0; i < 4; i++) {
                    wmma::fragment<wmma::matrix_a, 16, 16, 16, hlf, wmma::row_major> ah, al;
                    wmma::load_matrix_sync(ah, &Ah[(wm * 64 + i * 16) * LDK + ks], LDK);
                    wmma::load_matrix_sync(al, &Al[(wm * 64 + i * 16) * LDK + ks], LDK);
                    #pragma unroll
                    for (int j = 0; j < 2; j++)
                        wmma::mma_sync(acc[i][jh * 2 + j], ah, bh[j], acc[i][jh * 2 + j]);
                    #pragma unroll
                    for (int j = 0; j < 2; j++)
                        wmma::mma_sync(acc[i][jh * 2 + j], ah, bl[j], acc[i][jh * 2 + j]);
                    #pragma unroll
                    for (int j = 0; j < 2; j++)
                        wmma::mma_sync(acc[i][jh * 2 + j], al, bh[j], acc[i][jh * 2 + j]);
                }
            }
        }
        __syncthreads();
    }

    __syncthreads();
    float* patch = reinterpret_cast<float*>(smraw) + wid * 16 * 20;
    const int er = lane >> 1, eh = (lane & 1) * 8;
    #pragma unroll
    for (int i = 0; i < 4; i++) {
        #pragma unroll
        for (int j = 0; j < 4; j++) {
            wmma::store_matrix_sync(patch, acc[i][j], 20, wmma::mem_row_major);
            __syncwarp();
            int gr = m0 + wm * 64 + i * 16 + er;
            int gc = n0 + wn * 64 + j * 16 + eh;
            size_t go = (size_t)gr * Dd + gc;
            float4 b0 = *reinterpret_cast<const float4*>(&bias[gc]);
            float4 b1 = *reinterpret_cast<const float4*>(&bias[gc + 4]);
            float v[8];
            #pragma unroll
            for (int e = 0; e < 8; e++) v[e] = patch[er * 20 + eh + e];
            v[0] += b0.x; v[1] += b0.y; v[2] += b0.z; v[3] += b0.w;
            v[4] += b1.x; v[5] += b1.y; v[6] += b1.z; v[7] += b1.w;
            if (WF32) {
                *reinterpret_cast<float4*>(&Cf[go])     = *reinterpret_cast<float4*>(&v[0]);
                *reinterpret_cast<float4*>(&Cf[go + 4]) = *reinterpret_cast<float4*>(&v[4]);
            }
            if (WSPLIT) {
                hlf hs[8], ls[8];
                #pragma unroll
                for (int e = 0; e < 8; e++) split1(v[e], &hs[e], &ls[e]);
                *reinterpret_cast<float4*>(&Chi[go]) = *reinterpret_cast<float4*>(hs);
                *reinterpret_cast<float4*>(&Clo[go]) = *reinterpret_cast<float4*>(ls);
            }
            __syncwarp();
        }
    }
}

// ---------------------------------------------------------------------------
// gemm1: single-pass fp16 GEMM. C = (ACC ? Cf : 0) + A @ W + bias.
// ---------------------------------------------------------------------------
template <bool ACC>
__global__ __launch_bounds__(128, 2)
void gemm1(const hlf* __restrict__ A, const hlf* __restrict__ W,
           const float* __restrict__ bias, float* __restrict__ Cf,
           hlf* __restrict__ Ch) {
    extern __shared__ char smraw[];
    const int tid = threadIdx.x, wid = tid >> 5, lane = tid & 31;
    const int wm = wid >> 1, wn = wid & 1;
    const int m0 = blockIdx.y * 128, n0 = blockIdx.x * 128;

    wmma::fragment<wmma::accumulator, 16, 16, 16, float> acc[4][4];
    #pragma unroll
    for (int i = 0; i < 4; i++)
        #pragma unroll
        for (int j = 0; j < 4; j++)
            wmma::fill_fragment(acc[i][j], 0.0f);

    auto load_stage = [&](int st, int kt) {
        hlf* Ad = reinterpret_cast<hlf*>(smraw + st * G1STGB);
        hlf* Bd = Ad + 128 * LDK;
        const int k0 = kt * BK;
        #pragma unroll
        for (int t = 0; t < 4; t++) {
            int item = tid + t * 128;
            int r = item >> 2, c = (item & 3) * 8;
            cp16(Ad + r * LDK + c, A + (size_t)(m0 + r) * Dd + k0 + c);
            cp16(Bd + r * LDK + c, W + (size_t)(n0 + r) * Dd + k0 + c);
        }
        cp_commit();
    };

    load_stage(0, 0);
    for (int kt = 0; kt < NKT; kt++) {
        int st = kt & 1;
        if (kt + 1 < NKT) { load_stage(st ^ 1, kt + 1); cp_wait<1>(); }
        else              { cp_wait<0>(); }
        __syncthreads();

        hlf* Ad = reinterpret_cast<hlf*>(smraw + st * G1STGB);
        hlf* Bd = Ad + 128 * LDK;
        #pragma unroll
        for (int ks = 0; ks < BK; ks += 16) {
            wmma::fragment<wmma::matrix_b, 16, 16, 16, hlf, wmma::col_major> bf[4];
            #pragma unroll
            for (int j = 0; j < 4; j++)
                wmma::load_matrix_sync(bf[j], &Bd[(wn * 64 + j * 16) * LDK + ks], LDK);
            #pragma unroll
            for (int i = 0; i < 4; i++) {
                wmma::fragment<wmma::matrix_a, 16, 16, 16, hlf, wmma::row_major> ah;
                wmma::load_matrix_sync(ah, &Ad[(wm * 64 + i * 16) * LDK + ks], LDK);
                #pragma unroll
                for (int j = 0; j < 4; j++)
                    wmma::mma_sync(acc[i][j], ah, bf[j], acc[i][j]);
            }
        }
        __syncthreads();
    }

    __syncthreads();
    float* patch = reinterpret_cast<float*>(smraw) + wid * 16 * 20;
    const int er = lane >> 1, eh = (lane & 1) * 8;
    #pragma unroll
    for (int i = 0; i < 4; i++) {
        #pragma unroll
        for (int j = 0; j < 4; j++) {
            wmma::store_matrix_sync(patch, acc[i][j], 20, wmma::mem_row_major);
            __syncwarp();
            int gr = m0 + wm * 64 + i * 16 + er;
            int gc = n0 + wn * 64 + j * 16 + eh;
            size_t go = (size_t)gr * Dd + gc;
            float4 b0 = *reinterpret_cast<const float4*>(&bias[gc]);
            float4 b1 = *reinterpret_cast<const float4*>(&bias[gc + 4]);
            float v[8];
            #pragma unroll
            for (int e = 0; e < 8; e++) v[e] = patch[er * 20 + eh + e];
            v[0] += b0.x; v[1] += b0.y; v[2] += b0.z; v[3] += b0.w;
            v[4] += b1.x; v[5] += b1.y; v[6] += b1.z; v[7] += b1.w;
            if (ACC) {
                float4 o0 = *reinterpret_cast<const float4*>(&Cf[go]);
                float4 o1 = *reinterpret_cast<const float4*>(&Cf[go + 4]);
                v[0] += o0.x; v[1] += o0.y; v[2] += o0.z; v[3] += o0.w;
                v[4] += o1.x; v[5] += o1.y; v[6] += o1.z; v[7] += o1.w;
            }
            *reinterpret_cast<float4*>(&Cf[go])     = *reinterpret_cast<float4*>(&v[0]);
            *reinterpret_cast<float4*>(&Cf[go + 4]) = *reinterpret_cast<float4*>(&v[4]);
            hlf hs[8];
            #pragma unroll
            for (int e = 0; e < 8; e++) hs[e] = __float2half_rn(v[e]);
            *reinterpret_cast<float4*>(&Ch[go]) = *reinterpret_cast<float4*>(hs);
            __syncwarp();
        }
    }
}

// ---------------------------------------------------------------------------
// fused1: block 128x64, 4 warps, warp 64x32. A single fp16.
// exc: 1-pass (We hi); inh: 1-pass (Wi hi). Output single fp16 mc.
// ---------------------------------------------------------------------------
__global__ __launch_bounds__(128, 2)
void fused1(const hlf* __restrict__ A,
            const hlf* __restrict__ Weh, const hlf* __restrict__ Wih,
            const float* __restrict__ be_l, const float* __restrict__ bi_l,
            const float* __restrict__ Wl_l, const float* __restrict__ bl_l,
            hlf* __restrict__ Mc) {
    extern __shared__ char smraw[];
    __shared__ float swl[1024];
    __shared__ float sbe[64], sbi[64], sbl[64];

    const int tid = threadIdx.x, wid = tid >> 5, lane = tid & 31;
    const int wm = wid >> 1, wn = wid & 1;
    const int m0 = blockIdx.y * 128, n0 = blockIdx.x * 64;

    for (int i = tid; i < 256; i += 128)
        *reinterpret_cast<float4*>(&swl[i * 4]) =
            *reinterpret_cast<const float4*>(&Wl_l[(size_t)n0 * Hh + i * 4]);
    if (tid < 64) {
        sbe[tid] = be_l[n0 + tid];
        sbi[tid] = bi_l[n0 + tid];
        sbl[tid] = bl_l[n0 + tid];
    }

    wmma::fragment<wmma::accumulator, 16, 16, 16, float> ae[4][2], ai[4][2];
    #pragma unroll
    for (int i = 0; i < 4; i++)
        #pragma unroll
        for (int j = 0; j < 2; j++) {
            wmma::fill_fragment(ae[i][j], 0.0f);
            wmma::fill_fragment(ai[i][j], 0.0f);
        }

    auto load_stage = [&](int st, int kt) {
        hlf* Ad = reinterpret_cast<hlf*>(smraw + st * F1STGB);
        hlf* Eh = Ad + 128 * LDK;
        hlf* Ih = Eh + 64 * LDK;
        const int k0 = kt * BK;
        #pragma unroll
        for (int t = 0; t < 4; t++) {
            int item = tid + t * 128;
            int r = item >> 2, c = (item & 3) * 8;
            cp16(Ad + r * LDK + c, A + (size_t)(m0 + r) * Dd + k0 + c);
        }
        #pragma unroll
        for (int t = 0; t < 2; t++) {
            int item = tid + t * 128;
            int r = item >> 2, c = (item & 3) * 8;
            size_t gb = (size_t)(n0 + r) * Dd + k0 + c;
            cp16(Eh + r * LDK + c, Weh + gb);
            cp16(Ih + r * LDK + c, Wih + gb);
        }
        cp_commit();
    };

    load_stage(0, 0);
    for (int kt = 0; kt < NKT; kt++) {
        int st = kt & 1;
        if (kt + 1 < NKT) { load_stage(st ^ 1, kt + 1); cp_wait<1>(); }
        else              { cp_wait<0>(); }
        __syncthreads();

        hlf* Ad = reinterpret_cast<hlf*>(smraw + st * F1STGB);
        hlf* Eh = Ad + 128 * LDK;
        hlf* Ih = Eh + 64 * LDK;
        #pragma unroll
        for (int ks = 0; ks < BK; ks += 16) {
            wmma::fragment<wmma::matrix_b, 16, 16, 16, hlf, wmma::col_major> eh[2], ih[2];
            #pragma unroll
            for (int j = 0; j < 2; j++) {
                int nb = (wn * 32 + j * 16) * LDK + ks;
                wmma::load_matrix_sync(eh[j], &Eh[nb], LDK);
                wmma::load_matrix_sync(ih[j], &Ih[nb], LDK);
            }
            #pragma unroll
            for (int i = 0; i < 4; i++) {
                wmma::fragment<wmma::matrix_a, 16, 16, 16, hlf, wmma::row_major> ah;
                wmma::load_matrix_sync(ah, &Ad[(wm * 64 + i * 16) * LDK + ks], LDK);
                #pragma unroll
                for (int j = 0; j < 2; j++) wmma::mma_sync(ae[i][j], ah, eh[j], ae[i][j]);
                #pragma unroll
                for (int j = 0; j < 2; j++) wmma::mma_sync(ai[i][j], ah, ih[j], ai[i][j]);
            }
        }
        __syncthreads();
    }

    __syncthreads();
    float* pe = reinterpret_cast<float*>(smraw) + wid * 2 * 16 * 20;
    float* pi = pe + 16 * 20;
    const int er = lane >> 1, eh8 = (lane & 1) * 8;
    #pragma unroll
    for (int i = 0; i < 4; i++) {
        #pragma unroll
        for (int j = 0; j < 2; j++) {
            wmma::store_matrix_sync(pe, ae[i][j], 20, wmma::mem_row_major);
            wmma::store_matrix_sync(pi, ai[i][j], 20, wmma::mem_row_major);
            __syncwarp();
            int ml = wn * 2 + j;
            int gr = m0 + wm * 64 + i * 16 + er;
            float ihv[16];
            #pragma unroll
            for (int h = 0; h < 16; h++)
                ihv[h] = fmaxf(pi[er * 20 + h] + sbi[ml * 16 + h], 0.0f);
            hlf hs[8];
            #pragma unroll
            for (int e = 0; e < 8; e++) {
                int k = eh8 + e;
                float lat = sbl[ml * 16 + k];
                #pragma unroll
                for (int h = 0; h < 16; h++)
                    lat += ihv[h] * swl[ml * 256 + h * 16 + k];
                float ex = fmaxf(pe[er * 20 + k] + sbe[ml * 16 + k], 0.0f);
                hs[e] = __float2half_rn(fmaxf(ex - lat, 0.0f));
            }
            *reinterpret_cast<float4*>(&Mc[(size_t)gr * Dd + n0 + ml * 16 + eh8]) =
                *reinterpret_cast<float4*>(hs);
            __syncwarp();
        }
    }
}

// ---------------------------------------------------------------------------
// Host orchestration
// ---------------------------------------------------------------------------
extern "C" void kernel_launch(void* const* d_in, const int* in_sizes, int n_in,
                              void* d_out, int out_size) {
    const float* x    = (const float*)d_in[0];
    const float* We   = (const float*)d_in[1];
    const float* be   = (const float*)d_in[2];
    const float* Wi   = (const float*)d_in[3];
    const float* bi   = (const float*)d_in[4];
    const float* Wl   = (const float*)d_in[5];
    const float* bl   = (const float*)d_in[6];
    const float* Wlat = (const float*)d_in[7];
    const float* blat = (const float*)d_in[8];
    const float* Wv   = (const float*)d_in[9];
    const float* bv   = (const float*)d_in[10];
    const float* Wo   = (const float*)d_in[11];
    const float* bo   = (const float*)d_in[12];
    const float* fbW  = (const float*)d_in[13];
    const float* fbb  = (const float*)d_in[14];
    float* out = (float*)d_out;

    hlf *wc_h, *wc_l, *wv_h, *wv_l, *wo_h, *wo_l, *fb_h, *fb_l;
    hlf *we_h, *we_l, *wi_h, *wi_l, *a0, *a1;
    hlf *s1h, *s1l, *s2h, *s2l;
    float *t2, *bc1, *bc2, *bcp, *zero;
    cudaGetSymbolAddress((void**)&wc_h, g_wc_h);
    cudaGetSymbolAddress((void**)&wc_l, g_wc_l);
    cudaGetSymbolAddress((void**)&wv_h, g_wv_h);
    cudaGetSymbolAddress((void**)&wv_l, g_wv_l);
    cudaGetSymbolAddress((void**)&wo_h, g_wo_h);
    cudaGetSymbolAddress((void**)&wo_l, g_wo_l);
    cudaGetSymbolAddress((void**)&fb_h, g_fb_h);
    cudaGetSymbolAddress((void**)&fb_l, g_fb_l);
    cudaGetSymbolAddress((void**)&we_h, g_we_h);
    cudaGetSymbolAddress((void**)&we_l, g_we_l);
    cudaGetSymbolAddress((void**)&wi_h, g_wi_h);
    cudaGetSymbolAddress((void**)&wi_l, g_wi_l);
    cudaGetSymbolAddress((void**)&a0,   g_a0);
    cudaGetSymbolAddress((void**)&a1,   g_a1);
    cudaGetSymbolAddress((void**)&s1h,  g_s1h);
    cudaGetSymbolAddress((void**)&s1l,  g_s1l);
    cudaGetSymbolAddress((void**)&s2h,  g_s2h);
    cudaGetSymbolAddress((void**)&s2l,  g_s2l);
    cudaGetSymbolAddress((void**)&t2,   g_t2);
    cudaGetSymbolAddress((void**)&bc1,  g_bc1);
    cudaGetSymbolAddress((void**)&bc2,  g_bc2);
    cudaGetSymbolAddress((void**)&bcp,  g_bcp);
    cudaGetSymbolAddress((void**)&zero, g_zero);

    cudaFuncSetAttribute(gemm_pre<false, true>, cudaFuncAttributeMaxDynamicSharedMemorySize, GPDSM);
    cudaFuncSetAttribute(gemm_pre<true, false>, cudaFuncAttributeMaxDynamicSharedMemorySize, GPDSM);
    cudaFuncSetAttribute(gemm1<false>,          cudaFuncAttributeMaxDynamicSharedMemorySize, G1DSM);
    cudaFuncSetAttribute(gemm1<true>,           cudaFuncAttributeMaxDynamicSharedMemorySize, G1DSM);
    cudaFuncSetAttribute(fused1,                cudaFuncAttributeMaxDynamicSharedMemorySize, F1DSM);

    // --- One-time conversions (launches 0-2) ---
    convT_all<<<dim3(32, 32, 17), 256>>>(Wv, Wo, fbW, wv_h, wv_l, wo_h, wo_l, fb_h, fb_l);
    convgT_all<<<dim3(16, 64, 12), 256>>>(We, Wi, we_h, we_l, wi_h, wi_l);
    convact_all<<<(int)(6 * M1 / 4 / 256 + BD / 4 / 256), 256>>>(Wlat, x, s1h, s1l, a1);

    // --- Combo weight precompute (launches 3-4, full 3-pass precision) ---
    dim3 gridC(8, 8, 6);
    gemm_pre<false, true><<<gridC, 128, GPDSM>>>(s1h, s1l, wv_h, wv_l,
        zero, nullptr, s2h, s2l, M1, M1, 0, M1);
    gemm_pre<true, false><<<gridC, 128, GPDSM>>>(s2h, s2l, wo_h, wo_l,
        zero, t2, nullptr, nullptr, M1, M1, 0, M1);

    const size_t WL_STRIDE = (size_t)NMC * Hh * Hh;
    dim3 gridG(Dd / 128, Bsz / 128);   // 8 x 128
    dim3 gridF(Dd / 64,  Bsz / 128);   // 16 x 128

    // Launch 5 = fused1 l0 (ncu -s 5 target)
    fused1<<<gridF, 128, F1DSM>>>(a1, we_h, wi_h,
                                  be, bi, Wl, bl, a0);

    conv_T<<<dim3(32, 32, 6), 256>>>(t2, wc_h, wc_l);
    bias_part<<<dim3(4, 8, 6), 256>>>(blat, Wv, bcp);
    bias_reduce<<<dim3(4, 6), 256>>>(bcp, bv, bc1);
    bias_part<<<dim3(4, 8, 6), 256>>>(bc1, Wo, bcp);
    bias_reduce<<<dim3(4, 6), 256>>>(bcp, bo, bc2);

    for (int l = 0; l < Lc; l++) {
        if (l > 0) {
            fused1<<<gridF, 128, F1DSM>>>(a1,
                we_h + (size_t)l * M1, wi_h + (size_t)l * M1,
                be + l * Dd, bi + l * Dd, Wl + l * WL_STRIDE, bl + l * Dd,
                a0);
        }
        gemm1<false><<<gridG, 128, G1DSM>>>(a0,
            wc_h + (size_t)l * M1,
            bc2 + (size_t)l * Dd, out + (size_t)l * BD, a1);
    }

    int p = 1;
    for (int i = 0; i < Lc - 1; i++) {
        int idx = Lc - 2 - i;
        hlf* src = p ? a1 : a0;
        hlf* dst = p ? a0 : a1;
        gemm1<true><<<gridG, 128, G1DSM>>>(src,
            fb_h + (size_t)i * M1,
            fbb + i * Dd, out + (size_t)idx * BD, dst);
        p ^= 1;
    }
}

// round 16
// speedup vs baseline: 2.5436x; 1.0122x over previous
#include <cuda_runtime.h>
#include <cuda_fp16.h>
#include <mma.h>
#include <cstdint>

using namespace nvcuda;
typedef __half hlf;

// Problem constants
#define Bsz 16384
#define Dd  1024
#define Lc  6
#define NMC 64
#define Hh  16
#define M1  (1024 * 1024)
#define BD  ((size_t)Bsz * Dd)

// Tiling: block 128x128 (generic) / 128x64 (fused), 4 warps, occ 2, 2-stage
#define BK   32
#define LDK  40
#define NKT  (Dd / BK)
#define G1STGB (2 * 128 * LDK * 2)        // 1-pass: A + B = 20480
#define G1DSM  (2 * G1STGB)
#define F1STGB ((128 + 2 * 64) * LDK * 2) // fused: A + Eh + Ih = 20480
#define F1DSM  (2 * F1STGB)

// ---------------------------------------------------------------------------
// Persistent buffers (all runtime weights single fp16)
// ---------------------------------------------------------------------------
__device__ hlf g_wc_h[6 * M1];                 // combo weights [n][k]
__device__ hlf g_wv_h[6 * M1], g_wo_h[6 * M1]; // [n][k]
__device__ hlf g_fb_h[5 * M1];                 // [n][k]
__device__ hlf g_we_h[6 * M1], g_wi_h[6 * M1]; // gathered [n=m*16+h][k=d]
__device__ hlf g_s1h[6 * M1];                  // Wlat fp16 row-major
__device__ hlf g_s2h[6 * M1];                  // t1 fp16 row-major
__device__ float g_t2[6 * M1];                 // t2 fp32 row-major
__device__ float g_bc1[6 * Dd], g_bc2[6 * Dd];
__device__ float g_bcp[6 * 8 * Dd];
__device__ float g_zero[Dd];
__device__ hlf g_a0[BD], g_a1[BD];             // fp16 activations

__device__ __forceinline__ void cp16(void* smem, const void* g) {
    uint32_t s = (uint32_t)__cvta_generic_to_shared(smem);
    asm volatile("cp.async.cg.shared.global [%0], [%1], 16;" :: "r"(s), "l"(g));
}
__device__ __forceinline__ void cp_commit() { asm volatile("cp.async.commit_group;"); }
template <int N>
__device__ __forceinline__ void cp_wait() {
    asm volatile("cp.async.wait_group %0;" :: "n"(N));
}

// ---------------------------------------------------------------------------
// Conversion kernels (fp16 hi-only)
// ---------------------------------------------------------------------------
__device__ __forceinline__ void convT_body(const float* S, hlf* H,
                                           int k0, int n0, int tid) {
    __shared__ float t[32][33];
    const int r = tid >> 5, c = tid & 31;
    #pragma unroll
    for (int i = 0; i < 4; i++)
        t[r + i * 8][c] = S[(size_t)(k0 + r + i * 8) * Dd + n0 + c];
    __syncthreads();
    #pragma unroll
    for (int i = 0; i < 4; i++)
        H[(size_t)(n0 + r + i * 8) * Dd + k0 + c] = __float2half_rn(t[c][r + i * 8]);
}

// z: 0-5 Wv, 6-11 Wo, 12-16 fbW
__global__ void convT_all(const float* __restrict__ Wv, const float* __restrict__ Wo,
                          const float* __restrict__ fbW,
                          hlf* __restrict__ wvh, hlf* __restrict__ woh,
                          hlf* __restrict__ fbh) {
    const int z = blockIdx.z;
    const float* S; hlf* H;
    if (z < 6)       { S = Wv  + (size_t)z * M1;        H = wvh + (size_t)z * M1; }
    else if (z < 12) { S = Wo  + (size_t)(z - 6) * M1;  H = woh + (size_t)(z - 6) * M1; }
    else             { S = fbW + (size_t)(z - 12) * M1; H = fbh + (size_t)(z - 12) * M1; }
    convT_body(S, H, blockIdx.y * 32, blockIdx.x * 32, threadIdx.x);
}

__global__ void conv_T(const float* __restrict__ src, hlf* __restrict__ hi) {
    const int l = blockIdx.z;
    convT_body(src + (size_t)l * M1, hi + (size_t)l * M1,
               blockIdx.y * 32, blockIdx.x * 32, threadIdx.x);
}

// Gather We/Wi: out[l][m*16+h][d] = src[l][m][d][h]. z: 0-5 We, 6-11 Wi.
__global__ void convgT_all(const float* __restrict__ We, const float* __restrict__ Wi,
                           hlf* __restrict__ weh, hlf* __restrict__ wih) {
    __shared__ float t[64][17];
    const int z = blockIdx.z;
    const int l = (z < 6) ? z : z - 6;
    const float* src = (z < 6) ? We : Wi;
    hlf* hi = (z < 6) ? weh : wih;
    const int d0 = blockIdx.x * 64, m = blockIdx.y;
    const int tid = threadIdx.x;
    {
        int dd = tid >> 2, h4 = (tid & 3) * 4;
        float4 v = *reinterpret_cast<const float4*>(
            &src[((size_t)(l * NMC + m) * Dd + d0 + dd) * Hh + h4]);
        t[dd][h4] = v.x; t[dd][h4 + 1] = v.y; t[dd][h4 + 2] = v.z; t[dd][h4 + 3] = v.w;
    }
    __syncthreads();
    int h = tid >> 4, cq = tid & 15;
    size_t rowo = (size_t)l * M1 + (size_t)(m * 16 + h) * Dd + d0 + cq * 4;
    #pragma unroll
    for (int j = 0; j < 4; j++)
        hi[rowo + j] = __float2half_rn(t[cq * 4 + j][h]);
}

// Wlat (row-major fp16) + x (fp16 activation) in one launch
__global__ void convact_all(const float* __restrict__ Wlat, const float* __restrict__ x,
                            hlf* __restrict__ s1h, hlf* __restrict__ a1) {
    size_t idx = (size_t)blockIdx.x * blockDim.x + threadIdx.x;   // float4 index
    const size_t n1 = (size_t)6 * M1 / 4;
    const float* src; hlf* dst; size_t i;
    if (idx < n1) { src = Wlat; dst = s1h; i = idx * 4; }
    else          { src = x;    dst = a1;  i = (idx - n1) * 4; }
    float4 v = *reinterpret_cast<const float4*>(src + i);
    hlf hs[4];
    hs[0] = __float2half_rn(v.x); hs[1] = __float2half_rn(v.y);
    hs[2] = __float2half_rn(v.z); hs[3] = __float2half_rn(v.w);
    *reinterpret_cast<float2*>(dst + i) = *reinterpret_cast<float2*>(hs);
}

// Bias combo, deterministic 2-phase
__global__ void bias_part(const float* __restrict__ bin, const float* __restrict__ W,
                          float* __restrict__ bcp) {
    const int l = blockIdx.z;
    const int i0 = blockIdx.y * 128;
    const int j = blockIdx.x * 256 + threadIdx.x;
    const float* Wl = W + (size_t)l * M1;
    const float* bi = bin + (size_t)l * Dd;
    float s = 0.0f;
    #pragma unroll 4
    for (int i = i0; i < i0 + 128; i++) s += bi[i] * Wl[(size_t)i * Dd + j];
    bcp[((size_t)l * 8 + blockIdx.y) * Dd + j] = s;
}
__global__ void bias_reduce(const float* __restrict__ bcp, const float* __restrict__ badd,
                            float* __restrict__ bc) {
    const int l = blockIdx.y;
    const int j = blockIdx.x * 256 + threadIdx.x;
    float s = badd[(size_t)l * Dd + j];
    #pragma unroll
    for (int c = 0; c < 8; c++) s += bcp[((size_t)l * 8 + c) * Dd + j];
    bc[(size_t)l * Dd + j] = s;
}

// ---------------------------------------------------------------------------
// gemm1: single-pass fp16 GEMM. C = (ACC ? Cf : 0) + A @ W + bias.
// A fp16 [M,Dd] rm; W fp16 [n][k] km. Writes fp16 Ch + fp32 Cf. z-batched.
// ---------------------------------------------------------------------------
template <bool ACC>
__global__ __launch_bounds__(128, 2)
void gemm1(const hlf* __restrict__ A_, const hlf* __restrict__ W_,
           const float* __restrict__ bias_, float* __restrict__ Cf_,
           hlf* __restrict__ Ch_,
           size_t sA, size_t sW, size_t sB, size_t sC) {
    extern __shared__ char smraw[];
    const int z = blockIdx.z;
    const hlf* A = A_ + (size_t)z * sA;
    const hlf* W = W_ + (size_t)z * sW;
    const float* bias = bias_ + (size_t)z * sB;
    float* Cf = Cf_ + (size_t)z * sC;
    hlf* Ch = Ch_ + (size_t)z * sC;

    const int tid = threadIdx.x, wid = tid >> 5, lane = tid & 31;
    const int wm = wid >> 1, wn = wid & 1;
    const int m0 = blockIdx.y * 128, n0 = blockIdx.x * 128;

    wmma::fragment<wmma::accumulator, 16, 16, 16, float> acc[4][4];
    #pragma unroll
    for (int i = 0; i < 4; i++)
        #pragma unroll
        for (int j = 0; j < 4; j++)
            wmma::fill_fragment(acc[i][j], 0.0f);

    auto load_stage = [&](int st, int kt) {
        hlf* Ad = reinterpret_cast<hlf*>(smraw + st * G1STGB);
        hlf* Bd = Ad + 128 * LDK;
        const int k0 = kt * BK;
        #pragma unroll
        for (int t = 0; t < 4; t++) {
            int item = tid + t * 128;
            int r = item >> 2, c = (item & 3) * 8;
            cp16(Ad + r * LDK + c, A + (size_t)(m0 + r) * Dd + k0 + c);
            cp16(Bd + r * LDK + c, W + (size_t)(n0 + r) * Dd + k0 + c);
        }
        cp_commit();
    };

    load_stage(0, 0);
    for (int kt = 0; kt < NKT; kt++) {
        int st = kt & 1;
        if (kt + 1 < NKT) { load_stage(st ^ 1, kt + 1); cp_wait<1>(); }
        else              { cp_wait<0>(); }
        __syncthreads();

        hlf* Ad = reinterpret_cast<hlf*>(smraw + st * G1STGB);
        hlf* Bd = Ad + 128 * LDK;
        #pragma unroll
        for (int ks = 0; ks < BK; ks += 16) {
            wmma::fragment<wmma::matrix_b, 16, 16, 16, hlf, wmma::col_major> bf[4];
            #pragma unroll
            for (int j = 0; j < 4; j++)
                wmma::load_matrix_sync(bf[j], &Bd[(wn * 64 + j * 16) * LDK + ks], LDK);
            #pragma unroll
            for (int i = 0; i < 4; i++) {
                wmma::fragment<wmma::matrix_a, 16, 16, 16, hlf, wmma::row_major> ah;
                wmma::load_matrix_sync(ah, &Ad[(wm * 64 + i * 16) * LDK + ks], LDK);
                #pragma unroll
                for (int j = 0; j < 4; j++)
                    wmma::mma_sync(acc[i][j], ah, bf[j], acc[i][j]);
            }
        }
        __syncthreads();
    }

    __syncthreads();
    float* patch = reinterpret_cast<float*>(smraw) + wid * 16 * 20;
    const int er = lane >> 1, eh = (lane & 1) * 8;
    #pragma unroll
    for (int i = 0; i < 4; i++) {
        #pragma unroll
        for (int j = 0; j < 4; j++) {
            wmma::store_matrix_sync(patch, acc[i][j], 20, wmma::mem_row_major);
            __syncwarp();
            int gr = m0 + wm * 64 + i * 16 + er;
            int gc = n0 + wn * 64 + j * 16 + eh;
            size_t go = (size_t)gr * Dd + gc;
            float4 b0 = *reinterpret_cast<const float4*>(&bias[gc]);
            float4 b1 = *reinterpret_cast<const float4*>(&bias[gc + 4]);
            float v[8];
            #pragma unroll
            for (int e = 0; e < 8; e++) v[e] = patch[er * 20 + eh + e];
            v[0] += b0.x; v[1] += b0.y; v[2] += b0.z; v[3] += b0.w;
            v[4] += b1.x; v[5] += b1.y; v[6] += b1.z; v[7] += b1.w;
            if (ACC) {
                float4 o0 = *reinterpret_cast<const float4*>(&Cf[go]);
                float4 o1 = *reinterpret_cast<const float4*>(&Cf[go + 4]);
                v[0] += o0.x; v[1] += o0.y; v[2] += o0.z; v[3] += o0.w;
                v[4] += o1.x; v[5] += o1.y; v[6] += o1.z; v[7] += o1.w;
            }
            *reinterpret_cast<float4*>(&Cf[go])     = *reinterpret_cast<float4*>(&v[0]);
            *reinterpret_cast<float4*>(&Cf[go + 4]) = *reinterpret_cast<float4*>(&v[4]);
            hlf hs[8];
            #pragma unroll
            for (int e = 0; e < 8; e++) hs[e] = __float2half_rn(v[e]);
            *reinterpret_cast<float4*>(&Ch[go]) = *reinterpret_cast<float4*>(hs);
            __syncwarp();
        }
    }
}

// ---------------------------------------------------------------------------
// fused1: block 128x64, 4 warps, warp 64x32. A fp16; exc/inh single-pass.
// ---------------------------------------------------------------------------
__global__ __launch_bounds__(128, 2)
void fused1(const hlf* __restrict__ A,
            const hlf* __restrict__ Weh, const hlf* __restrict__ Wih,
            const float* __restrict__ be_l, const float* __restrict__ bi_l,
            const float* __restrict__ Wl_l, const float* __restrict__ bl_l,
            hlf* __restrict__ Mc) {
    extern __shared__ char smraw[];
    __shared__ float swl[1024];
    __shared__ float sbe[64], sbi[64], sbl[64];

    const int tid = threadIdx.x, wid = tid >> 5, lane = tid & 31;
    const int wm = wid >> 1, wn = wid & 1;
    const int m0 = blockIdx.y * 128, n0 = blockIdx.x * 64;

    for (int i = tid; i < 256; i += 128)
        *reinterpret_cast<float4*>(&swl[i * 4]) =
            *reinterpret_cast<const float4*>(&Wl_l[(size_t)n0 * Hh + i * 4]);
    if (tid < 64) {
        sbe[tid] = be_l[n0 + tid];
        sbi[tid] = bi_l[n0 + tid];
        sbl[tid] = bl_l[n0 + tid];
    }

    wmma::fragment<wmma::accumulator, 16, 16, 16, float> ae[4][2], ai[4][2];
    #pragma unroll
    for (int i = 0; i < 4; i++)
        #pragma unroll
        for (int j = 0; j < 2; j++) {
            wmma::fill_fragment(ae[i][j], 0.0f);
            wmma::fill_fragment(ai[i][j], 0.0f);
        }

    auto load_stage = [&](int st, int kt) {
        hlf* Ad = reinterpret_cast<hlf*>(smraw + st * F1STGB);
        hlf* Eh = Ad + 128 * LDK;
        hlf* Ih = Eh + 64 * LDK;
        const int k0 = kt * BK;
        #pragma unroll
        for (int t = 0; t < 4; t++) {
            int item = tid + t * 128;
            int r = item >> 2, c = (item & 3) * 8;
            cp16(Ad + r * LDK + c, A + (size_t)(m0 + r) * Dd + k0 + c);
        }
        #pragma unroll
        for (int t = 0; t < 2; t++) {
            int item = tid + t * 128;
            int r = item >> 2, c = (item & 3) * 8;
            size_t gb = (size_t)(n0 + r) * Dd + k0 + c;
            cp16(Eh + r * LDK + c, Weh + gb);
            cp16(Ih + r * LDK + c, Wih + gb);
        }
        cp_commit();
    };

    load_stage(0, 0);
    for (int kt = 0; kt < NKT; kt++) {
        int st = kt & 1;
        if (kt + 1 < NKT) { load_stage(st ^ 1, kt + 1); cp_wait<1>(); }
        else              { cp_wait<0>(); }
        __syncthreads();

        hlf* Ad = reinterpret_cast<hlf*>(smraw + st * F1STGB);
        hlf* Eh = Ad + 128 * LDK;
        hlf* Ih = Eh + 64 * LDK;
        #pragma unroll
        for (int ks = 0; ks < BK; ks += 16) {
            wmma::fragment<wmma::matrix_b, 16, 16, 16, hlf, wmma::col_major> eh[2], ih[2];
            #pragma unroll
            for (int j = 0; j < 2; j++) {
                int nb = (wn * 32 + j * 16) * LDK + ks;
                wmma::load_matrix_sync(eh[j], &Eh[nb], LDK);
                wmma::load_matrix_sync(ih[j], &Ih[nb], LDK);
            }
            #pragma unroll
            for (int i = 0; i < 4; i++) {
                wmma::fragment<wmma::matrix_a, 16, 16, 16, hlf, wmma::row_major> ah;
                wmma::load_matrix_sync(ah, &Ad[(wm * 64 + i * 16) * LDK + ks], LDK);
                #pragma unroll
                for (int j = 0; j < 2; j++) wmma::mma_sync(ae[i][j], ah, eh[j], ae[i][j]);
                #pragma unroll
                for (int j = 0; j < 2; j++) wmma::mma_sync(ai[i][j], ah, ih[j], ai[i][j]);
            }
        }
        __syncthreads();
    }

    __syncthreads();
    float* pe = reinterpret_cast<float*>(smraw) + wid * 2 * 16 * 20;
    float* pi = pe + 16 * 20;
    const int er = lane >> 1, eh8 = (lane & 1) * 8;
    #pragma unroll
    for (int i = 0; i < 4; i++) {
        #pragma unroll
        for (int j = 0; j < 2; j++) {
            wmma::store_matrix_sync(pe, ae[i][j], 20, wmma::mem_row_major);
            wmma::store_matrix_sync(pi, ai[i][j], 20, wmma::mem_row_major);
            __syncwarp();
            int ml = wn * 2 + j;
            int gr = m0 + wm * 64 + i * 16 + er;
            float ihv[16];
            #pragma unroll
            for (int h = 0; h < 16; h++)
                ihv[h] = fmaxf(pi[er * 20 + h] + sbi[ml * 16 + h], 0.0f);
            hlf hs[8];
            #pragma unroll
            for (int e = 0; e < 8; e++) {
                int k = eh8 + e;
                float lat = sbl[ml * 16 + k];
                #pragma unroll
                for (int h = 0; h < 16; h++)
                    lat += ihv[h] * swl[ml * 256 + h * 16 + k];
                float ex = fmaxf(pe[er * 20 + k] + sbe[ml * 16 + k], 0.0f);
                hs[e] = __float2half_rn(fmaxf(ex - lat, 0.0f));
            }
            *reinterpret_cast<float4*>(&Mc[(size_t)gr * Dd + n0 + ml * 16 + eh8]) =
                *reinterpret_cast<float4*>(hs);
            __syncwarp();
        }
    }
}

// ---------------------------------------------------------------------------
// Host orchestration
// ---------------------------------------------------------------------------
extern "C" void kernel_launch(void* const* d_in, const int* in_sizes, int n_in,
                              void* d_out, int out_size) {
    const float* x    = (const float*)d_in[0];
    const float* We   = (const float*)d_in[1];
    const float* be   = (const float*)d_in[2];
    const float* Wi   = (const float*)d_in[3];
    const float* bi   = (const float*)d_in[4];
    const float* Wl   = (const float*)d_in[5];
    const float* bl   = (const float*)d_in[6];
    const float* Wlat = (const float*)d_in[7];
    const float* blat = (const float*)d_in[8];
    const float* Wv   = (const float*)d_in[9];
    const float* bv   = (const float*)d_in[10];
    const float* Wo   = (const float*)d_in[11];
    const float* bo   = (const float*)d_in[12];
    const float* fbW  = (const float*)d_in[13];
    const float* fbb  = (const float*)d_in[14];
    float* out = (float*)d_out;

    hlf *wc_h, *wv_h, *wo_h, *fb_h, *we_h, *wi_h, *a0, *a1, *s1h, *s2h;
    float *t2, *bc1, *bc2, *bcp, *zero;
    cudaGetSymbolAddress((void**)&wc_h, g_wc_h);
    cudaGetSymbolAddress((void**)&wv_h, g_wv_h);
    cudaGetSymbolAddress((void**)&wo_h, g_wo_h);
    cudaGetSymbolAddress((void**)&fb_h, g_fb_h);
    cudaGetSymbolAddress((void**)&we_h, g_we_h);
    cudaGetSymbolAddress((void**)&wi_h, g_wi_h);
    cudaGetSymbolAddress((void**)&a0,   g_a0);
    cudaGetSymbolAddress((void**)&a1,   g_a1);
    cudaGetSymbolAddress((void**)&s1h,  g_s1h);
    cudaGetSymbolAddress((void**)&s2h,  g_s2h);
    cudaGetSymbolAddress((void**)&t2,   g_t2);
    cudaGetSymbolAddress((void**)&bc1,  g_bc1);
    cudaGetSymbolAddress((void**)&bc2,  g_bc2);
    cudaGetSymbolAddress((void**)&bcp,  g_bcp);
    cudaGetSymbolAddress((void**)&zero, g_zero);

    cudaFuncSetAttribute(gemm1<false>, cudaFuncAttributeMaxDynamicSharedMemorySize, G1DSM);
    cudaFuncSetAttribute(gemm1<true>,  cudaFuncAttributeMaxDynamicSharedMemorySize, G1DSM);
    cudaFuncSetAttribute(fused1,       cudaFuncAttributeMaxDynamicSharedMemorySize, F1DSM);

    // --- One-time conversions (launches 0-2, fp16 hi-only) ---
    convT_all<<<dim3(32, 32, 17), 256>>>(Wv, Wo, fbW, wv_h, wo_h, fb_h);
    convgT_all<<<dim3(16, 64, 12), 256>>>(We, Wi, we_h, wi_h);
    convact_all<<<(int)(6 * M1 / 4 / 256 + BD / 4 / 256), 256>>>(Wlat, x, s1h, a1);

    // --- Combo weight precompute, single-pass (launches 3-4) ---
    // t1 = Wlat @ Wv  (fp16 -> s2h);  t2 = t1 @ Wo (fp32 -> t2)
    dim3 gridC(8, 8, 6);
    gemm1<false><<<gridC, 128, G1DSM>>>(s1h, wv_h, zero, t2, s2h, M1, M1, 0, M1);
    gemm1<false><<<gridC, 128, G1DSM>>>(s2h, wo_h, zero, t2, s1h, M1, M1, 0, M1);

    const size_t WL_STRIDE = (size_t)NMC * Hh * Hh;
    dim3 gridG(Dd / 128, Bsz / 128);   // 8 x 128
    dim3 gridF(Dd / 64,  Bsz / 128);   // 16 x 128

    // Launch 5 = fused1 l0 (ncu -s 5 target)
    fused1<<<gridF, 128, F1DSM>>>(a1, we_h, wi_h,
                                  be, bi, Wl, bl, a0);

    conv_T<<<dim3(32, 32, 6), 256>>>(t2, wc_h);
    bias_part<<<dim3(4, 8, 6), 256>>>(blat, Wv, bcp);
    bias_reduce<<<dim3(4, 6), 256>>>(bcp, bv, bc1);
    bias_part<<<dim3(4, 8, 6), 256>>>(bc1, Wo, bcp);
    bias_reduce<<<dim3(4, 6), 256>>>(bcp, bo, bc2);

    for (int l = 0; l < Lc; l++) {
        if (l > 0) {
            fused1<<<gridF, 128, F1DSM>>>(a1,
                we_h + (size_t)l * M1, wi_h + (size_t)l * M1,
                be + l * Dd, bi + l * Dd, Wl + l * WL_STRIDE, bl + l * Dd,
                a0);
        }
        gemm1<false><<<gridG, 128, G1DSM>>>(a0,
            wc_h + (size_t)l * M1,
            bc2 + (size_t)l * Dd, out + (size_t)l * BD, a1,
            0, 0, 0, 0);
    }

    int p = 1;
    for (int i = 0; i < Lc - 1; i++) {
        int idx = Lc - 2 - i;
        hlf* src = p ? a1 : a0;
        hlf* dst = p ? a0 : a1;
        gemm1<true><<<gridG, 128, G1DSM>>>(src,
            fb_h + (size_t)i * M1,
            fbb + i * Dd, out + (size_t)idx * BD, dst,
            0, 0, 0, 0);
        p ^= 1;
    }
}